// round 2
// baseline (speedup 1.0000x reference)
#include <cuda_runtime.h>
#include <math.h>

// ---------------- problem constants ----------------
constexpr int cB   = 2;
constexpr int cN   = 1024;
constexpr int cD   = 1024;
constexpr int cL   = 6;
constexpr int cH   = 16;
constexpr int cDh  = 64;
constexpr int cDff = 2730;
constexpr int cDc  = 4096;     // cond dim = 4*DIM
constexpr int cRows = cB * cN; // 2048

// ---------------- device scratch (static, allocation-free) ----------------
__device__ float g_cond[cB * cDc];
__device__ float g_attn_film[cL * cB * 2 * cD];
__device__ float g_ff_film[cL * cB * 2 * cD];
__device__ float g_attn_adaz[cL * cB * cD];   // sigmoid applied
__device__ float g_ff_adaz[cL * cB * cD];     // sigmoid applied
__device__ float g_x[cRows * cD];
__device__ float g_xc[cRows * cD];
__device__ float g_qkv[cRows * 3 * cD];
__device__ float g_vr[cRows * cD];            // layer-0 original v
__device__ float g_o[cRows * cD];             // gated attention output
__device__ float g_tmp[cRows * 2 * cDff];     // ff hidden / proj results
__device__ float g_ffa[cRows * cDff];         // gelu(gate)*a
__device__ float g_skip[3][cRows * cD];
__device__ float g_xcat[cRows * 2 * cD];
__device__ float g_gates[cRows * cH];

// ---------------- utility ----------------
__global__ void k_copy(float* __restrict__ dst, const float* __restrict__ src, int n) {
  int i = blockIdx.x * 256 + threadIdx.x;
  if (i < n) dst[i] = src[i];
}

// ---------------- cond = silu(fourier @ tcond_w + b) ----------------
__global__ void k_cond(const float* __restrict__ times, const float* __restrict__ fw,
                       const float* __restrict__ tw, const float* __restrict__ tb) {
  __shared__ float fs[1025];
  int b = blockIdx.y;
  float t = times[b];
  for (int i = threadIdx.x; i < 1025; i += 256) {
    if (i == 0)        fs[0] = t;
    else if (i <= 512) fs[i] = sinf(6.283185307179586f * t * fw[i - 1]);
    else               fs[i] = cosf(6.283185307179586f * t * fw[i - 513]);
  }
  __syncthreads();
  int j = blockIdx.x * 256 + threadIdx.x;
  float acc = tb[j];
  for (int k = 0; k < 1025; k++) acc += fs[k] * tw[k * cDc + j];
  g_cond[b * cDc + j] = acc / (1.f + expf(-acc));   // silu
}

// ---------------- all cond projections (film g/b, adaz sigmoids) ----------------
__global__ void k_proj(const float* __restrict__ afw, const float* __restrict__ afb,
                       const float* __restrict__ ffw, const float* __restrict__ ffb,
                       const float* __restrict__ aaw, const float* __restrict__ aab,
                       const float* __restrict__ faw, const float* __restrict__ fab) {
  __shared__ float cs[cDc];
  int l = blockIdx.y, b = blockIdx.z;
  for (int i = threadIdx.x; i < cDc; i += 256) cs[i] = g_cond[b * cDc + i];
  __syncthreads();
  int o = blockIdx.x * 256 + threadIdx.x;  // 0..6143 per (l,b)
  const float* W; const float* bias; float* out; int cols; int c; bool sig = false;
  if (o < 2048)      { c = o;        cols = 2048; W = afw + (size_t)l*cDc*2048; bias = afb + l*2048; out = g_attn_film + (l*cB + b)*2048; }
  else if (o < 4096) { c = o - 2048; cols = 2048; W = ffw + (size_t)l*cDc*2048; bias = ffb + l*2048; out = g_ff_film   + (l*cB + b)*2048; }
  else if (o < 5120) { c = o - 4096; cols = 1024; W = aaw + (size_t)l*cDc*1024; bias = aab + l*1024; out = g_attn_adaz + (l*cB + b)*1024; sig = true; }
  else               { c = o - 5120; cols = 1024; W = faw + (size_t)l*cDc*1024; bias = fab + l*1024; out = g_ff_adaz   + (l*cB + b)*1024; sig = true; }
  float acc = bias[c];
  for (int k = 0; k < cDc; k++) acc += cs[k] * W[(size_t)k * cols + c];
  if (sig) acc = 1.f / (1.f + expf(-acc));
  out[c] = acc;
}

// ---------------- LN + FiLM: g_xc = ln(g_x)*(g+1)+b ----------------
__global__ void k_lnfilm(const float* __restrict__ film) {
  int row = blockIdx.x;
  int b = row >> 10;
  int tid = threadIdx.x;
  float4 v = ((const float4*)(g_x + (size_t)row * cD))[tid];
  float s  = v.x + v.y + v.z + v.w;
  float s2 = v.x*v.x + v.y*v.y + v.z*v.z + v.w*v.w;
  #pragma unroll
  for (int off = 16; off > 0; off >>= 1) {
    s  += __shfl_xor_sync(0xffffffffu, s,  off);
    s2 += __shfl_xor_sync(0xffffffffu, s2, off);
  }
  __shared__ float ws[8], ws2[8];
  __shared__ float smu, srstd;
  if ((tid & 31) == 0) { ws[tid >> 5] = s; ws2[tid >> 5] = s2; }
  __syncthreads();
  if (tid == 0) {
    float t1 = 0.f, t2 = 0.f;
    for (int w = 0; w < 8; w++) { t1 += ws[w]; t2 += ws2[w]; }
    float mu = t1 * (1.f / cD);
    float var = t2 * (1.f / cD) - mu * mu;
    smu = mu; srstd = rsqrtf(var + 1e-5f);
  }
  __syncthreads();
  float mu = smu, rs = srstd;
  const float* fg = film + b * 2 * cD;
  int d = tid * 4;
  float4 o;
  o.x = (v.x - mu) * rs * (fg[d+0] + 1.f) + fg[cD + d + 0];
  o.y = (v.y - mu) * rs * (fg[d+1] + 1.f) + fg[cD + d + 1];
  o.z = (v.z - mu) * rs * (fg[d+2] + 1.f) + fg[cD + d + 2];
  o.w = (v.w - mu) * rs * (fg[d+3] + 1.f) + fg[cD + d + 3];
  ((float4*)(g_xc + (size_t)row * cD))[tid] = o;
}

// ---------------- SGEMM: C[M,Nc] = A[M,K] @ W[K,Nc] (+bias) ----------------
// 64x64 block tile, BK=8, 16x16 threads, 4x4 microtile. M must be multiple of 64.
__global__ void k_sgemm(const float* __restrict__ A, const float* __restrict__ W,
                        const float* __restrict__ bias, float* __restrict__ C,
                        int M, int Nc, int K) {
  __shared__ float sA[8 * 64];
  __shared__ float sB[8 * 64];
  int tid = threadIdx.x;
  int tx = tid & 15, ty = tid >> 4;
  int rb = blockIdx.y * 64, cb = blockIdx.x * 64;
  float acc[4][4] = {};
  for (int k0 = 0; k0 < K; k0 += 8) {
    #pragma unroll
    for (int s = 0; s < 2; s++) {
      int e = tid + s * 256;
      int m = e >> 3, kk = e & 7;
      int gk = k0 + kk;
      sA[kk * 64 + m] = (gk < K) ? A[(size_t)(rb + m) * K + gk] : 0.f;
      int kk2 = e >> 6, n = e & 63;
      int gk2 = k0 + kk2, gn = cb + n;
      sB[kk2 * 64 + n] = (gk2 < K && gn < Nc) ? W[(size_t)gk2 * Nc + gn] : 0.f;
    }
    __syncthreads();
    #pragma unroll
    for (int kk = 0; kk < 8; kk++) {
      float4 av = *(const float4*)&sA[kk * 64 + ty * 4];
      float4 bv = *(const float4*)&sB[kk * 64 + tx * 4];
      float a[4] = {av.x, av.y, av.z, av.w};
      float bb[4] = {bv.x, bv.y, bv.z, bv.w};
      #pragma unroll
      for (int i = 0; i < 4; i++)
        #pragma unroll
        for (int j = 0; j < 4; j++)
          acc[i][j] += a[i] * bb[j];
    }
    __syncthreads();
  }
  #pragma unroll
  for (int i = 0; i < 4; i++) {
    int gm = rb + ty * 4 + i;
    #pragma unroll
    for (int j = 0; j < 4; j++) {
      int gn = cb + tx * 4 + j;
      if (gn < Nc) C[(size_t)gm * Nc + gn] = acc[i][j] + (bias ? bias[gn] : 0.f);
    }
  }
}

// ---------------- rope on q,k in g_qkv ----------------
__global__ void k_rope(const float* __restrict__ rf) {
  int i = blockIdx.x * 256 + threadIdx.x;  // over cRows*cH*32
  if (i >= cRows * cH * 32) return;
  int p = i & 31;
  int h = (i >> 5) & 15;
  int row = i >> 9;          // 0..2047
  int n = row & 1023;
  float f = rf[n * 64 + 2 * p];
  float csv = cosf(f), snv = sinf(f);
  size_t base = (size_t)row * 3072 + h * 64 + 2 * p;
  #pragma unroll
  for (int s = 0; s < 2; s++) {
    float x0 = g_qkv[base + s * 1024];
    float x1 = g_qkv[base + s * 1024 + 1];
    g_qkv[base + s * 1024]     = x0 * csv - x1 * snv;
    g_qkv[base + s * 1024 + 1] = x1 * csv + x0 * snv;
  }
}

__global__ void k_savevr() {
  int i = blockIdx.x * 256 + threadIdx.x;
  if (i >= cRows * cD) return;
  int row = i >> 10, c = i & 1023;
  g_vr[i] = g_qkv[(size_t)row * 3072 + 2048 + c];
}

// ---------------- gates = sigmoid(xc @ gates_w) ----------------
__global__ void k_gates(const float* __restrict__ gw) {
  int i = blockIdx.x * 256 + threadIdx.x;
  if (i >= cRows * cH) return;
  int row = i >> 4, h = i & 15;
  const float* xr = g_xc + (size_t)row * cD;
  float acc = 0.f;
  for (int k = 0; k < cD; k++) acc += xr[k] * gw[k * cH + h];
  g_gates[i] = 1.f / (1.f + expf(-acc));
}

// ---------------- fused causal attention with softcap + online softmax ----------------
// grid: (qtile 0..31, bh 0..31). 32-row Q tile, 64-row K/V tiles. P reuses K smem.
__global__ void k_attn(int mix) {
  __shared__ float Qs[32 * 65];
  __shared__ float KP[64 * 65];
  __shared__ float Vs[64 * 64];
  int qt = blockIdx.x, bh = blockIdx.y;
  int b = bh >> 4, h = bh & 15;
  int q0 = qt * 32;
  int tid = threadIdx.x;
  int tx = tid & 15, ty = tid >> 4;

  for (int idx = tid; idx < 32 * 64; idx += 256) {
    int r = idx >> 6, d = idx & 63;
    Qs[r * 65 + d] = g_qkv[(size_t)(b * cN + q0 + r) * 3072 + h * 64 + d];
  }

  float o[2][4] = {};
  float mrun[2] = {-1e30f, -1e30f};
  float lrun[2] = {0.f, 0.f};
  int ktmax = (q0 + 31) >> 6;

  for (int kt = 0; kt <= ktmax; kt++) {
    int k0 = kt * 64;
    __syncthreads();  // protect KP/Vs (also orders Qs writes before first compute)
    for (int idx = tid; idx < 64 * 64; idx += 256) {
      int r = idx >> 6, d = idx & 63;
      size_t base = (size_t)(b * cN + k0 + r) * 3072 + h * 64 + d;
      KP[r * 65 + d] = g_qkv[base + 1024];
      float vv = g_qkv[base + 2048];
      if (mix) vv = 0.5f * (vv + g_vr[(size_t)(b * cN + k0 + r) * 1024 + h * 64 + d]);
      Vs[r * 64 + d] = vv;
    }
    __syncthreads();

    float s[2][4] = {};
    #pragma unroll 8
    for (int d = 0; d < 64; d++) {
      float a0 = Qs[(ty * 2) * 65 + d];
      float a1 = Qs[(ty * 2 + 1) * 65 + d];
      #pragma unroll
      for (int j = 0; j < 4; j++) {
        float kv = KP[(tx * 4 + j) * 65 + d];
        s[0][j] += a0 * kv;
        s[1][j] += a1 * kv;
      }
    }

    float p[2][4];
    #pragma unroll
    for (int ri = 0; ri < 2; ri++) {
      int ig = q0 + ty * 2 + ri;
      float rmax = -1e30f;
      #pragma unroll
      for (int j = 0; j < 4; j++) {
        int jg = k0 + tx * 4 + j;
        float v = s[ri][j] * 0.125f;          // *= DIM_HEAD^-0.5
        v = 50.f * tanhf(v * 0.02f);          // softcap 50
        if (jg > ig) v = -1e30f;              // causal mask
        s[ri][j] = v;
        rmax = fmaxf(rmax, v);
      }
      #pragma unroll
      for (int off = 1; off < 16; off <<= 1)
        rmax = fmaxf(rmax, __shfl_xor_sync(0xffffffffu, rmax, off));
      float mnew  = fmaxf(mrun[ri], rmax);
      float alpha = __expf(mrun[ri] - mnew);
      float rsum = 0.f;
      #pragma unroll
      for (int j = 0; j < 4; j++) {
        float pv = __expf(s[ri][j] - mnew);
        p[ri][j] = pv;
        rsum += pv;
      }
      #pragma unroll
      for (int off = 1; off < 16; off <<= 1)
        rsum += __shfl_xor_sync(0xffffffffu, rsum, off);
      lrun[ri] = lrun[ri] * alpha + rsum;
      mrun[ri] = mnew;
      #pragma unroll
      for (int j = 0; j < 4; j++) o[ri][j] *= alpha;
    }

    __syncthreads();  // all threads done reading KP as K
    #pragma unroll
    for (int ri = 0; ri < 2; ri++)
      #pragma unroll
      for (int j = 0; j < 4; j++)
        KP[(ty * 2 + ri) * 65 + tx * 4 + j] = p[ri][j];
    __syncthreads();

    #pragma unroll 4
    for (int j = 0; j < 64; j++) {
      float p0 = KP[(ty * 2) * 65 + j];
      float p1 = KP[(ty * 2 + 1) * 65 + j];
      float4 v4 = *(const float4*)&Vs[j * 64 + tx * 4];
      o[0][0] += p0 * v4.x; o[0][1] += p0 * v4.y; o[0][2] += p0 * v4.z; o[0][3] += p0 * v4.w;
      o[1][0] += p1 * v4.x; o[1][1] += p1 * v4.y; o[1][2] += p1 * v4.z; o[1][3] += p1 * v4.w;
    }
  }

  #pragma unroll
  for (int ri = 0; ri < 2; ri++) {
    int nIdx = q0 + ty * 2 + ri;
    float gate = g_gates[(b * cN + nIdx) * cH + h];
    float inv = gate / lrun[ri];
    #pragma unroll
    for (int j = 0; j < 4; j++)
      g_o[(size_t)(b * cN + nIdx) * cD + h * 64 + tx * 4 + j] = o[ri][j] * inv;
  }
}

// ---------------- glu: ffa = gelu_exact(gate) * a ----------------
__global__ void k_glu() {
  int i = blockIdx.x * 256 + threadIdx.x;
  if (i >= cRows * cDff) return;
  int row = i / cDff, c = i - row * cDff;
  float a = g_tmp[(size_t)row * 2 * cDff + c];
  float g = g_tmp[(size_t)row * 2 * cDff + cDff + c];
  float ge = 0.5f * g * (1.f + erff(g * 0.7071067811865476f));
  g_ffa[i] = ge * a;
}

// ---------------- x += tmp * adaz ----------------
__global__ void k_addscaled(const float* __restrict__ adaz) {
  int i = blockIdx.x * 256 + threadIdx.x;
  if (i >= cRows * cD) return;
  int row = i >> 10, d = i & 1023;
  int b = row >> 10;
  g_x[i] += g_tmp[i] * adaz[b * cD + d];
}

// ---------------- xcat = [x, skip] ----------------
__global__ void k_concat(const float* __restrict__ skip) {
  int i = blockIdx.x * 256 + threadIdx.x;
  if (i >= cRows * 2 * cD) return;
  int row = i >> 11, c = i & 2047;
  g_xcat[i] = (c < 1024) ? g_x[(size_t)row * cD + c] : skip[(size_t)row * cD + c - 1024];
}

// ---------------- final norm ----------------
__global__ void k_final(const float* __restrict__ gamma, float* __restrict__ out) {
  int row = blockIdx.x;
  int tid = threadIdx.x;
  float4 v = ((const float4*)(g_x + (size_t)row * cD))[tid];
  float s2 = v.x*v.x + v.y*v.y + v.z*v.z + v.w*v.w;
  #pragma unroll
  for (int off = 16; off > 0; off >>= 1)
    s2 += __shfl_xor_sync(0xffffffffu, s2, off);
  __shared__ float ws2[8];
  __shared__ float sscale;
  if ((tid & 31) == 0) ws2[tid >> 5] = s2;
  __syncthreads();
  if (tid == 0) {
    float t2 = 0.f;
    for (int w = 0; w < 8; w++) t2 += ws2[w];
    sscale = 32.f / fmaxf(sqrtf(t2), 1e-12f);
  }
  __syncthreads();
  float sc = sscale;
  int d = tid * 4;
  float4 o;
  o.x = v.x * sc * (gamma[d + 0] + 1.f);
  o.y = v.y * sc * (gamma[d + 1] + 1.f);
  o.z = v.z * sc * (gamma[d + 2] + 1.f);
  o.w = v.w * sc * (gamma[d + 3] + 1.f);
  ((float4*)(out + (size_t)row * cD))[tid] = o;
}

// ---------------- host launcher ----------------
extern "C" void kernel_launch(void* const* d_in, const int* in_sizes, int n_in,
                              void* d_out, int out_size) {
  const float* in_x  = (const float*)d_in[0];
  const float* times = (const float*)d_in[1];
  const float* rf    = (const float*)d_in[2];
  const float* fw    = (const float*)d_in[3];
  const float* tw    = (const float*)d_in[4];
  const float* tb    = (const float*)d_in[5];
  const float* skw   = (const float*)d_in[6];
  const float* afw   = (const float*)d_in[7];
  const float* afb   = (const float*)d_in[8];
  const float* aaw   = (const float*)d_in[9];
  const float* aab   = (const float*)d_in[10];
  const float* qkvw  = (const float*)d_in[11];
  const float* gw    = (const float*)d_in[12];
  const float* ow    = (const float*)d_in[13];
  const float* ffw   = (const float*)d_in[14];
  const float* ffb   = (const float*)d_in[15];
  const float* faw   = (const float*)d_in[16];
  const float* fab   = (const float*)d_in[17];
  const float* w1    = (const float*)d_in[18];
  const float* b1    = (const float*)d_in[19];
  const float* w2    = (const float*)d_in[20];
  const float* b2    = (const float*)d_in[21];
  const float* gamma = (const float*)d_in[22];
  float* out = (float*)d_out;

  float *px, *pxc, *pqkv, *po, *ptmp, *pffa, *pxcat, *pskip, *paf, *pff, *paa, *pfa;
  cudaGetSymbolAddress((void**)&px,    g_x);
  cudaGetSymbolAddress((void**)&pxc,   g_xc);
  cudaGetSymbolAddress((void**)&pqkv,  g_qkv);
  cudaGetSymbolAddress((void**)&po,    g_o);
  cudaGetSymbolAddress((void**)&ptmp,  g_tmp);
  cudaGetSymbolAddress((void**)&pffa,  g_ffa);
  cudaGetSymbolAddress((void**)&pxcat, g_xcat);
  cudaGetSymbolAddress((void**)&pskip, g_skip);
  cudaGetSymbolAddress((void**)&paf,   g_attn_film);
  cudaGetSymbolAddress((void**)&pff,   g_ff_film);
  cudaGetSymbolAddress((void**)&paa,   g_attn_adaz);
  cudaGetSymbolAddress((void**)&pfa,   g_ff_adaz);

  // x <- input
  k_copy<<<(cRows * cD) / 256, 256>>>(px, in_x, cRows * cD);
  // conditioning
  k_cond<<<dim3(cDc / 256, cB), 256>>>(times, fw, tw, tb);
  k_proj<<<dim3(24, cL, cB), 256>>>(afw, afb, ffw, ffb, aaw, aab, faw, fab);

  for (int l = 0; l < cL; l++) {
    if (l < 3) {
      k_copy<<<(cRows * cD) / 256, 256>>>(pskip + (size_t)l * cRows * cD, px, cRows * cD);
    } else {
      k_concat<<<(cRows * 2 * cD) / 256, 256>>>(pskip + (size_t)(5 - l) * cRows * cD);
      k_sgemm<<<dim3(16, 32), 256>>>(pxcat, skw + (size_t)(l - 3) * 2048 * 1024, nullptr, px,
                                     cRows, 1024, 2048);
    }
    // attention block
    k_lnfilm<<<cRows, 256>>>(paf + (size_t)l * cB * 2 * cD);
    k_sgemm<<<dim3(48, 32), 256>>>(pxc, qkvw + (size_t)l * 1024 * 3072, nullptr, pqkv,
                                   cRows, 3072, 1024);
    if (l == 0) k_savevr<<<(cRows * cD) / 256, 256>>>();
    k_rope<<<(cRows * cH * 32) / 256, 256>>>(rf);
    k_gates<<<(cRows * cH) / 256, 256>>>(gw + (size_t)l * 1024 * 16);
    k_attn<<<dim3(32, 32), 256>>>(l > 0 ? 1 : 0);
    k_sgemm<<<dim3(16, 32), 256>>>(po, ow + (size_t)l * 1024 * 1024, nullptr, ptmp,
                                   cRows, 1024, 1024);
    k_addscaled<<<(cRows * cD) / 256, 256>>>(paa + (size_t)l * cB * cD);
    // feed-forward block
    k_lnfilm<<<cRows, 256>>>(pff + (size_t)l * cB * 2 * cD);
    k_sgemm<<<dim3(86, 32), 256>>>(pxc, w1 + (size_t)l * 1024 * (2 * cDff),
                                   b1 + (size_t)l * (2 * cDff), ptmp,
                                   cRows, 2 * cDff, 1024);
    k_glu<<<(cRows * cDff + 255) / 256, 256>>>();
    k_sgemm<<<dim3(16, 32), 256>>>(pffa, w2 + (size_t)l * cDff * 1024,
                                   b2 + (size_t)l * 1024, ptmp,
                                   cRows, 1024, cDff);
    k_addscaled<<<(cRows * cD) / 256, 256>>>(pfa + (size_t)l * cB * cD);
  }
  k_final<<<cRows, 256>>>(gamma, out);
}

// round 4
// speedup vs baseline: 1.6129x; 1.6129x over previous
#include <cuda_runtime.h>
#include <math.h>

// ---------------- problem constants ----------------
constexpr int cB   = 2;
constexpr int cN   = 1024;
constexpr int cD   = 1024;
constexpr int cL   = 6;
constexpr int cH   = 16;
constexpr int cDff = 2730;
constexpr int cDffP = 2732;    // padded (multiple of 4 -> 16B-aligned rows)
constexpr int cDc  = 4096;     // cond dim = 4*DIM
constexpr int cRows = cB * cN; // 2048

// ---------------- device scratch (static, allocation-free, zero-initialized) ----------------
__device__ float g_cond[cB * cDc];
__device__ float g_attn_film[cL * cB * 2 * cD];
__device__ float g_ff_film[cL * cB * 2 * cD];
__device__ float g_attn_adaz[cL * cB * cD];   // sigmoid applied
__device__ float g_ff_adaz[cL * cB * cD];     // sigmoid applied
__device__ float g_x[cRows * cD];
__device__ float g_xc[cRows * cD];
__device__ float g_qkv[cRows * 3 * cD];
__device__ float g_vr[cRows * cD];            // layer-0 original v
__device__ float g_o[cRows * cD];             // gated attention output
__device__ float g_tmp[cRows * 2 * cDff];     // ff hidden / proj results
__device__ float g_ffa[cRows * cDffP];        // gelu(gate)*a, padded stride (pads stay 0)
__device__ float g_skip[3][cRows * cD];
__device__ float g_xcat[cRows * 2 * cD];
__device__ float g_gates[cRows * cH];

// ---------------- utility ----------------
__global__ void k_copy(float* __restrict__ dst, const float* __restrict__ src, int n) {
  int i = blockIdx.x * 256 + threadIdx.x;
  if (i < n) dst[i] = src[i];
}

// ---------------- cond = silu(fourier @ tcond_w + b) ----------------
__global__ void k_cond(const float* __restrict__ times, const float* __restrict__ fw,
                       const float* __restrict__ tw, const float* __restrict__ tb) {
  __shared__ float fs[1025];
  int b = blockIdx.y;
  float t = times[b];
  for (int i = threadIdx.x; i < 1025; i += 256) {
    if (i == 0)        fs[0] = t;
    else if (i <= 512) fs[i] = sinf(6.283185307179586f * t * fw[i - 1]);
    else               fs[i] = cosf(6.283185307179586f * t * fw[i - 513]);
  }
  __syncthreads();
  int j = blockIdx.x * 256 + threadIdx.x;
  float acc = tb[j];
  for (int k = 0; k < 1025; k++) acc += fs[k] * tw[k * cDc + j];
  g_cond[b * cDc + j] = acc / (1.f + expf(-acc));   // silu
}

// ---------------- all cond projections; both batch rows share one weight read ----------------
__global__ void k_proj(const float* __restrict__ afw, const float* __restrict__ afb,
                       const float* __restrict__ ffw, const float* __restrict__ ffb,
                       const float* __restrict__ aaw, const float* __restrict__ aab,
                       const float* __restrict__ faw, const float* __restrict__ fab) {
  __shared__ float cs0[cDc], cs1[cDc];
  int l = blockIdx.y;
  for (int i = threadIdx.x; i < cDc; i += 256) {
    cs0[i] = g_cond[i];
    cs1[i] = g_cond[cDc + i];
  }
  __syncthreads();
  int o = blockIdx.x * 256 + threadIdx.x;  // 0..6143 per l
  const float* W; const float* bias; float* out; int cols; int c; bool sig = false;
  if (o < 2048)      { c = o;        cols = 2048; W = afw + (size_t)l*cDc*2048; bias = afb + l*2048; out = g_attn_film + (size_t)l*cB*2048; }
  else if (o < 4096) { c = o - 2048; cols = 2048; W = ffw + (size_t)l*cDc*2048; bias = ffb + l*2048; out = g_ff_film   + (size_t)l*cB*2048; }
  else if (o < 5120) { c = o - 4096; cols = 1024; W = aaw + (size_t)l*cDc*1024; bias = aab + l*1024; out = g_attn_adaz + (size_t)l*cB*1024; sig = true; }
  else               { c = o - 5120; cols = 1024; W = faw + (size_t)l*cDc*1024; bias = fab + l*1024; out = g_ff_adaz   + (size_t)l*cB*1024; sig = true; }
  float acc0 = bias[c], acc1 = bias[c];
  #pragma unroll 4
  for (int k = 0; k < cDc; k++) {
    float w = W[(size_t)k * cols + c];
    acc0 += cs0[k] * w;
    acc1 += cs1[k] * w;
  }
  if (sig) { acc0 = 1.f / (1.f + expf(-acc0)); acc1 = 1.f / (1.f + expf(-acc1)); }
  out[c] = acc0;
  out[cols + c] = acc1;
}

// ---------------- LN + FiLM: g_xc = ln(g_x)*(g+1)+b ----------------
__global__ void k_lnfilm(const float* __restrict__ film) {
  int row = blockIdx.x;
  int b = row >> 10;
  int tid = threadIdx.x;
  float4 v = ((const float4*)(g_x + (size_t)row * cD))[tid];
  float s  = v.x + v.y + v.z + v.w;
  float s2 = v.x*v.x + v.y*v.y + v.z*v.z + v.w*v.w;
  #pragma unroll
  for (int off = 16; off > 0; off >>= 1) {
    s  += __shfl_xor_sync(0xffffffffu, s,  off);
    s2 += __shfl_xor_sync(0xffffffffu, s2, off);
  }
  __shared__ float ws[8], ws2[8];
  __shared__ float smu, srstd;
  if ((tid & 31) == 0) { ws[tid >> 5] = s; ws2[tid >> 5] = s2; }
  __syncthreads();
  if (tid == 0) {
    float t1 = 0.f, t2 = 0.f;
    for (int w = 0; w < 8; w++) { t1 += ws[w]; t2 += ws2[w]; }
    float mu = t1 * (1.f / cD);
    float var = t2 * (1.f / cD) - mu * mu;
    smu = mu; srstd = rsqrtf(var + 1e-5f);
  }
  __syncthreads();
  float mu = smu, rs = srstd;
  const float* fg = film + b * 2 * cD;
  int d = tid * 4;
  float4 o;
  o.x = (v.x - mu) * rs * (fg[d+0] + 1.f) + fg[cD + d + 0];
  o.y = (v.y - mu) * rs * (fg[d+1] + 1.f) + fg[cD + d + 1];
  o.z = (v.z - mu) * rs * (fg[d+2] + 1.f) + fg[cD + d + 2];
  o.w = (v.w - mu) * rs * (fg[d+3] + 1.f) + fg[cD + d + 3];
  ((float4*)(g_xc + (size_t)row * cD))[tid] = o;
}

// ---------------- tf32 tensor-core GEMM ----------------
// C[M,N] = A[M,K] @ W[K,N] (+bias). A has row stride lda (lda % 4 == 0).
// 128x128x32 block tile, 8 warps (2x4), warp tile 64x32, mma.m16n8k8.tf32.
__device__ __forceinline__ unsigned f2tf(float x) {
  unsigned u;
  asm("cvt.rna.tf32.f32 %0, %1;" : "=r"(u) : "f"(x));
  return u;
}
__device__ __forceinline__ void mma_tf32(float (&c)[4], const unsigned (&a)[4],
                                         const unsigned (&b)[2]) {
  asm volatile(
      "mma.sync.aligned.m16n8k8.row.col.f32.tf32.tf32.f32 "
      "{%0,%1,%2,%3}, {%4,%5,%6,%7}, {%8,%9}, {%0,%1,%2,%3};\n"
      : "+f"(c[0]), "+f"(c[1]), "+f"(c[2]), "+f"(c[3])
      : "r"(a[0]), "r"(a[1]), "r"(a[2]), "r"(a[3]), "r"(b[0]), "r"(b[1]));
}

__global__ __launch_bounds__(256) void k_gemm_tf32(
    const float* __restrict__ A, const float* __restrict__ W,
    const float* __restrict__ bias, float* __restrict__ C,
    int M, int N, int K, int lda) {
  __shared__ unsigned sA[128][36];
  __shared__ unsigned sB[32][136];
  int tid = threadIdx.x;
  int warp = tid >> 5, lane = tid & 31;
  int wm = warp >> 2, wn = warp & 3;     // 2 x 4 warp grid
  int g = lane >> 2, t = lane & 3;
  int rb = blockIdx.y * 128, cb = blockIdx.x * 128;
  float acc[4][4][4] = {};

  for (int k0 = 0; k0 < K; k0 += 32) {
    __syncthreads();
    // load A tile: thread idx -> (m = idx>>3, kgroup = idx&7), float4 along k
    #pragma unroll
    for (int it = 0; it < 4; it++) {
      int idx = tid + it * 256;
      int m = idx >> 3, kg = idx & 7;
      int gk = k0 + kg * 4;
      const float* src = A + (size_t)(rb + m) * lda + gk;
      float4 v;
      if (gk + 3 < K) {
        v = *(const float4*)src;   // lda%4==0 and gk%4==0 -> 16B aligned
      } else {
        v.x = (gk + 0 < K) ? src[0] : 0.f;
        v.y = (gk + 1 < K) ? src[1] : 0.f;
        v.z = (gk + 2 < K) ? src[2] : 0.f;
        v.w = (gk + 3 < K) ? src[3] : 0.f;
      }
      uint4 u = {f2tf(v.x), f2tf(v.y), f2tf(v.z), f2tf(v.w)};
      *(uint4*)&sA[m][kg * 4] = u;
    }
    // load B tile: thread idx -> (kk = idx>>5, n4 = idx&31), float4 along n
    #pragma unroll
    for (int it = 0; it < 4; it++) {
      int idx = tid + it * 256;
      int kk = idx >> 5, n4 = idx & 31;
      int gk = k0 + kk, gn = cb + n4 * 4;
      float4 v = {0.f, 0.f, 0.f, 0.f};
      if (gk < K) {
        const float* src = W + (size_t)gk * N + gn;
        if (gn + 3 < N) {
          v = *(const float4*)src;
        } else {
          if (gn + 0 < N) v.x = src[0];
          if (gn + 1 < N) v.y = src[1];
          if (gn + 2 < N) v.z = src[2];
          if (gn + 3 < N) v.w = src[3];
        }
      }
      uint4 u = {f2tf(v.x), f2tf(v.y), f2tf(v.z), f2tf(v.w)};
      *(uint4*)&sB[kk][n4 * 4] = u;
    }
    __syncthreads();

    #pragma unroll
    for (int ks = 0; ks < 4; ks++) {
      int kb = ks * 8;
      unsigned a[4][4], b[4][2];
      #pragma unroll
      for (int i = 0; i < 4; i++) {
        int mr = wm * 64 + i * 16;
        a[i][0] = sA[mr + g][kb + t];
        a[i][1] = sA[mr + 8 + g][kb + t];
        a[i][2] = sA[mr + g][kb + 4 + t];
        a[i][3] = sA[mr + 8 + g][kb + 4 + t];
      }
      #pragma unroll
      for (int j = 0; j < 4; j++) {
        int nc = wn * 32 + j * 8;
        b[j][0] = sB[kb + t][nc + g];
        b[j][1] = sB[kb + 4 + t][nc + g];
      }
      #pragma unroll
      for (int i = 0; i < 4; i++)
        #pragma unroll
        for (int j = 0; j < 4; j++)
          mma_tf32(acc[i][j], a[i], b[j]);
    }
  }

  // epilogue: float2 stores (c0,c1 / c2,c3 are adjacent columns)
  #pragma unroll
  for (int i = 0; i < 4; i++) {
    int r0 = rb + wm * 64 + i * 16 + g;
    #pragma unroll
    for (int j = 0; j < 4; j++) {
      int c0 = cb + wn * 32 + j * 8 + 2 * t;
      if (c0 < N) {  // N even, c0 even -> c0+1 < N too
        float b0 = bias ? bias[c0] : 0.f;
        float b1 = bias ? bias[c0 + 1] : 0.f;
        float2 v0 = {acc[i][j][0] + b0, acc[i][j][1] + b1};
        float2 v1 = {acc[i][j][2] + b0, acc[i][j][3] + b1};
        *(float2*)&C[(size_t)r0 * N + c0] = v0;
        *(float2*)&C[(size_t)(r0 + 8) * N + c0] = v1;
      }
    }
  }
}

// ---------------- rope on q,k in g_qkv ----------------
__global__ void k_rope(const float* __restrict__ rf) {
  int i = blockIdx.x * 256 + threadIdx.x;  // over cRows*cH*32
  if (i >= cRows * cH * 32) return;
  int p = i & 31;
  int h = (i >> 5) & 15;
  int row = i >> 9;          // 0..2047
  int n = row & 1023;
  float f = rf[n * 64 + 2 * p];
  float csv = cosf(f), snv = sinf(f);
  size_t base = (size_t)row * 3072 + h * 64 + 2 * p;
  #pragma unroll
  for (int s = 0; s < 2; s++) {
    float x0 = g_qkv[base + s * 1024];
    float x1 = g_qkv[base + s * 1024 + 1];
    g_qkv[base + s * 1024]     = x0 * csv - x1 * snv;
    g_qkv[base + s * 1024 + 1] = x1 * csv + x0 * snv;
  }
}

__global__ void k_savevr() {
  int i = blockIdx.x * 256 + threadIdx.x;
  if (i >= cRows * cD) return;
  int row = i >> 10, c = i & 1023;
  g_vr[i] = g_qkv[(size_t)row * 3072 + 2048 + c];
}

// ---------------- gates = sigmoid(xc @ gates_w) ----------------
__global__ void k_gates(const float* __restrict__ gw) {
  int i = blockIdx.x * 256 + threadIdx.x;
  if (i >= cRows * cH) return;
  int row = i >> 4, h = i & 15;
  const float* xr = g_xc + (size_t)row * cD;
  float acc = 0.f;
  #pragma unroll 4
  for (int k = 0; k < cD; k++) acc += xr[k] * gw[k * cH + h];
  g_gates[i] = 1.f / (1.f + expf(-acc));
}

// ---------------- fused causal attention with softcap + online softmax ----------------
__global__ void k_attn(int mix) {
  __shared__ float Qs[32 * 65];
  __shared__ float KP[64 * 65];
  __shared__ float Vs[64 * 64];
  int qt = blockIdx.x, bh = blockIdx.y;
  int b = bh >> 4, h = bh & 15;
  int q0 = qt * 32;
  int tid = threadIdx.x;
  int tx = tid & 15, ty = tid >> 4;

  for (int idx = tid; idx < 32 * 64; idx += 256) {
    int r = idx >> 6, d = idx & 63;
    Qs[r * 65 + d] = g_qkv[(size_t)(b * cN + q0 + r) * 3072 + h * 64 + d];
  }

  float o[2][4] = {};
  float mrun[2] = {-1e30f, -1e30f};
  float lrun[2] = {0.f, 0.f};
  int ktmax = (q0 + 31) >> 6;

  for (int kt = 0; kt <= ktmax; kt++) {
    int k0 = kt * 64;
    __syncthreads();
    for (int idx = tid; idx < 64 * 64; idx += 256) {
      int r = idx >> 6, d = idx & 63;
      size_t base = (size_t)(b * cN + k0 + r) * 3072 + h * 64 + d;
      KP[r * 65 + d] = g_qkv[base + 1024];
      float vv = g_qkv[base + 2048];
      if (mix) vv = 0.5f * (vv + g_vr[(size_t)(b * cN + k0 + r) * 1024 + h * 64 + d]);
      Vs[r * 64 + d] = vv;
    }
    __syncthreads();

    float s[2][4] = {};
    #pragma unroll 8
    for (int d = 0; d < 64; d++) {
      float a0 = Qs[(ty * 2) * 65 + d];
      float a1 = Qs[(ty * 2 + 1) * 65 + d];
      #pragma unroll
      for (int j = 0; j < 4; j++) {
        float kv = KP[(tx * 4 + j) * 65 + d];
        s[0][j] += a0 * kv;
        s[1][j] += a1 * kv;
      }
    }

    float p[2][4];
    #pragma unroll
    for (int ri = 0; ri < 2; ri++) {
      int ig = q0 + ty * 2 + ri;
      float rmax = -1e30f;
      #pragma unroll
      for (int j = 0; j < 4; j++) {
        int jg = k0 + tx * 4 + j;
        float v = s[ri][j] * 0.125f;
        v = 50.f * tanhf(v * 0.02f);
        if (jg > ig) v = -1e30f;
        s[ri][j] = v;
        rmax = fmaxf(rmax, v);
      }
      #pragma unroll
      for (int off = 1; off < 16; off <<= 1)
        rmax = fmaxf(rmax, __shfl_xor_sync(0xffffffffu, rmax, off));
      float mnew  = fmaxf(mrun[ri], rmax);
      float alpha = __expf(mrun[ri] - mnew);
      float rsum = 0.f;
      #pragma unroll
      for (int j = 0; j < 4; j++) {
        float pv = __expf(s[ri][j] - mnew);
        p[ri][j] = pv;
        rsum += pv;
      }
      #pragma unroll
      for (int off = 1; off < 16; off <<= 1)
        rsum += __shfl_xor_sync(0xffffffffu, rsum, off);
      lrun[ri] = lrun[ri] * alpha + rsum;
      mrun[ri] = mnew;
      #pragma unroll
      for (int j = 0; j < 4; j++) o[ri][j] *= alpha;
    }

    __syncthreads();
    #pragma unroll
    for (int ri = 0; ri < 2; ri++)
      #pragma unroll
      for (int j = 0; j < 4; j++)
        KP[(ty * 2 + ri) * 65 + tx * 4 + j] = p[ri][j];
    __syncthreads();

    #pragma unroll 4
    for (int j = 0; j < 64; j++) {
      float p0 = KP[(ty * 2) * 65 + j];
      float p1 = KP[(ty * 2 + 1) * 65 + j];
      float4 v4 = *(const float4*)&Vs[j * 64 + tx * 4];
      o[0][0] += p0 * v4.x; o[0][1] += p0 * v4.y; o[0][2] += p0 * v4.z; o[0][3] += p0 * v4.w;
      o[1][0] += p1 * v4.x; o[1][1] += p1 * v4.y; o[1][2] += p1 * v4.z; o[1][3] += p1 * v4.w;
    }
  }

  #pragma unroll
  for (int ri = 0; ri < 2; ri++) {
    int nIdx = q0 + ty * 2 + ri;
    float gate = g_gates[(b * cN + nIdx) * cH + h];
    float inv = gate / lrun[ri];
    #pragma unroll
    for (int j = 0; j < 4; j++)
      g_o[(size_t)(b * cN + nIdx) * cD + h * 64 + tx * 4 + j] = o[ri][j] * inv;
  }
}

// ---------------- glu: ffa = gelu_exact(gate) * a (padded output stride) ----------------
__global__ void k_glu() {
  int i = blockIdx.x * 256 + threadIdx.x;
  if (i >= cRows * cDff) return;
  int row = i / cDff, c = i - row * cDff;
  float a = g_tmp[(size_t)row * 2 * cDff + c];
  float g = g_tmp[(size_t)row * 2 * cDff + cDff + c];
  float ge = 0.5f * g * (1.f + erff(g * 0.7071067811865476f));
  g_ffa[(size_t)row * cDffP + c] = ge * a;
}

// ---------------- x += tmp * adaz ----------------
__global__ void k_addscaled(const float* __restrict__ adaz) {
  int i = blockIdx.x * 256 + threadIdx.x;
  if (i >= cRows * cD) return;
  int row = i >> 10, d = i & 1023;
  int b = row >> 10;
  g_x[i] += g_tmp[i] * adaz[b * cD + d];
}

// ---------------- xcat = [x, skip] ----------------
__global__ void k_concat(const float* __restrict__ skip) {
  int i = blockIdx.x * 256 + threadIdx.x;
  if (i >= cRows * 2 * cD) return;
  int row = i >> 11, c = i & 2047;
  g_xcat[i] = (c < 1024) ? g_x[(size_t)row * cD + c] : skip[(size_t)row * cD + c - 1024];
}

// ---------------- final norm ----------------
__global__ void k_final(const float* __restrict__ gamma, float* __restrict__ out) {
  int row = blockIdx.x;
  int tid = threadIdx.x;
  float4 v = ((const float4*)(g_x + (size_t)row * cD))[tid];
  float s2 = v.x*v.x + v.y*v.y + v.z*v.z + v.w*v.w;
  #pragma unroll
  for (int off = 16; off > 0; off >>= 1)
    s2 += __shfl_xor_sync(0xffffffffu, s2, off);
  __shared__ float ws2[8];
  __shared__ float sscale;
  if ((tid & 31) == 0) ws2[tid >> 5] = s2;
  __syncthreads();
  if (tid == 0) {
    float t2 = 0.f;
    for (int w = 0; w < 8; w++) t2 += ws2[w];
    sscale = 32.f / fmaxf(sqrtf(t2), 1e-12f);
  }
  __syncthreads();
  float sc = sscale;
  int d = tid * 4;
  float4 o;
  o.x = v.x * sc * (gamma[d + 0] + 1.f);
  o.y = v.y * sc * (gamma[d + 1] + 1.f);
  o.z = v.z * sc * (gamma[d + 2] + 1.f);
  o.w = v.w * sc * (gamma[d + 3] + 1.f);
  ((float4*)(out + (size_t)row * cD))[tid] = o;
}

// ---------------- host launcher ----------------
extern "C" void kernel_launch(void* const* d_in, const int* in_sizes, int n_in,
                              void* d_out, int out_size) {
  const float* in_x  = (const float*)d_in[0];
  const float* times = (const float*)d_in[1];
  const float* rf    = (const float*)d_in[2];
  const float* fw    = (const float*)d_in[3];
  const float* tw    = (const float*)d_in[4];
  const float* tb    = (const float*)d_in[5];
  const float* skw   = (const float*)d_in[6];
  const float* afw   = (const float*)d_in[7];
  const float* afb   = (const float*)d_in[8];
  const float* aaw   = (const float*)d_in[9];
  const float* aab   = (const float*)d_in[10];
  const float* qkvw  = (const float*)d_in[11];
  const float* gw    = (const float*)d_in[12];
  const float* ow    = (const float*)d_in[13];
  const float* ffw   = (const float*)d_in[14];
  const float* ffb   = (const float*)d_in[15];
  const float* faw   = (const float*)d_in[16];
  const float* fab   = (const float*)d_in[17];
  const float* w1    = (const float*)d_in[18];
  const float* b1    = (const float*)d_in[19];
  const float* w2    = (const float*)d_in[20];
  const float* b2    = (const float*)d_in[21];
  const float* gamma = (const float*)d_in[22];
  float* out = (float*)d_out;

  float *px, *pxc, *pqkv, *po, *ptmp, *pffa, *pxcat, *pskip, *paf, *pff, *paa, *pfa;
  cudaGetSymbolAddress((void**)&px,    g_x);
  cudaGetSymbolAddress((void**)&pxc,   g_xc);
  cudaGetSymbolAddress((void**)&pqkv,  g_qkv);
  cudaGetSymbolAddress((void**)&po,    g_o);
  cudaGetSymbolAddress((void**)&ptmp,  g_tmp);
  cudaGetSymbolAddress((void**)&pffa,  g_ffa);
  cudaGetSymbolAddress((void**)&pxcat, g_xcat);
  cudaGetSymbolAddress((void**)&pskip, g_skip);
  cudaGetSymbolAddress((void**)&paf,   g_attn_film);
  cudaGetSymbolAddress((void**)&pff,   g_ff_film);
  cudaGetSymbolAddress((void**)&paa,   g_attn_adaz);
  cudaGetSymbolAddress((void**)&pfa,   g_ff_adaz);

  // x <- input
  k_copy<<<(cRows * cD) / 256, 256>>>(px, in_x, cRows * cD);
  // conditioning
  k_cond<<<dim3(cDc / 256, cB), 256>>>(times, fw, tw, tb);
  k_proj<<<dim3(24, cL), 256>>>(afw, afb, ffw, ffb, aaw, aab, faw, fab);

  for (int l = 0; l < cL; l++) {
    if (l < 3) {
      k_copy<<<(cRows * cD) / 256, 256>>>(pskip + (size_t)l * cRows * cD, px, cRows * cD);
    } else {
      k_concat<<<(cRows * 2 * cD) / 256, 256>>>(pskip + (size_t)(5 - l) * cRows * cD);
      k_gemm_tf32<<<dim3(8, 16), 256>>>(pxcat, skw + (size_t)(l - 3) * 2048 * 1024, nullptr, px,
                                        cRows, 1024, 2048, 2048);
    }
    // attention block
    k_lnfilm<<<cRows, 256>>>(paf + (size_t)l * cB * 2 * cD);
    k_gemm_tf32<<<dim3(24, 16), 256>>>(pxc, qkvw + (size_t)l * 1024 * 3072, nullptr, pqkv,
                                       cRows, 3072, 1024, 1024);
    if (l == 0) k_savevr<<<(cRows * cD) / 256, 256>>>();
    k_rope<<<(cRows * cH * 32) / 256, 256>>>(rf);
    k_gates<<<(cRows * cH) / 256, 256>>>(gw + (size_t)l * 1024 * 16);
    k_attn<<<dim3(32, 32), 256>>>(l > 0 ? 1 : 0);
    k_gemm_tf32<<<dim3(8, 16), 256>>>(po, ow + (size_t)l * 1024 * 1024, nullptr, ptmp,
                                      cRows, 1024, 1024, 1024);
    k_addscaled<<<(cRows * cD) / 256, 256>>>(paa + (size_t)l * cB * cD);
    // feed-forward block
    k_lnfilm<<<cRows, 256>>>(pff + (size_t)l * cB * 2 * cD);
    k_gemm_tf32<<<dim3(43, 16), 256>>>(pxc, w1 + (size_t)l * 1024 * (2 * cDff),
                                       b1 + (size_t)l * (2 * cDff), ptmp,
                                       cRows, 2 * cDff, 1024, 1024);
    k_glu<<<(cRows * cDff + 255) / 256, 256>>>();
    k_gemm_tf32<<<dim3(8, 16), 256>>>(pffa, w2 + (size_t)l * cDff * 1024,
                                      b2 + (size_t)l * 1024, ptmp,
                                      cRows, 1024, cDff, cDffP);
    k_addscaled<<<(cRows * cD) / 256, 256>>>(pfa + (size_t)l * cB * cD);
  }
  k_final<<<cRows, 256>>>(gamma, out);
}

// round 5
// speedup vs baseline: 2.6943x; 1.6705x over previous
#include <cuda_runtime.h>
#include <math.h>

// ---------------- problem constants ----------------
constexpr int cB   = 2;
constexpr int cN   = 1024;
constexpr int cD   = 1024;
constexpr int cL   = 6;
constexpr int cH   = 16;
constexpr int cDff = 2730;
constexpr int cDffP = 2732;    // padded (multiple of 4 -> 16B-aligned rows)
constexpr int cDc  = 4096;     // cond dim = 4*DIM
constexpr int cRows = cB * cN; // 2048

// ---------------- device scratch (static, allocation-free, zero-initialized) ----------------
__device__ float g_cond[cB * cDc];
__device__ float g_attn_film[cL * cB * 2 * cD];
__device__ float g_ff_film[cL * cB * 2 * cD];
__device__ float g_attn_adaz[cL * cB * cD];
__device__ float g_ff_adaz[cL * cB * cD];
__device__ __align__(16) float g_x[cRows * cD];
__device__ __align__(16) float g_xc[cRows * cD];
__device__ __align__(16) float g_qkv[cRows * 3 * cD];
__device__ __align__(16) float g_vr[cRows * cD];
__device__ __align__(16) float g_o[cRows * cD];
__device__ __align__(16) float g_tmp[cRows * 2 * cDff];
__device__ __align__(16) float g_ffa[cRows * cDffP + 64];  // +tail pad for overread
__device__ __align__(16) float g_skip[3][cRows * cD];
__device__ __align__(16) float g_xcat[cRows * 2 * cD];
__device__ float g_gates[cRows * cH];

// pre-rounded (tf32) weights
__device__ __align__(16) float g_wq[cL * cD * 3 * cD];         // 18.9M
__device__ __align__(16) float g_wo[cL * cD * cD];             // 6.3M
__device__ __align__(16) float g_w1[cL * cD * 2 * cDff];       // 33.5M
__device__ __align__(16) float g_w2[cL * cDff * cD];           // 16.8M
__device__ __align__(16) float g_ws[3 * 2 * cD * cD];          // 6.3M

__device__ __forceinline__ float f2tf_f(float x) {
  unsigned u;
  asm("cvt.rna.tf32.f32 %0, %1;" : "=r"(u) : "f"(x));
  return __uint_as_float(u);
}

// ---------------- utility ----------------
__global__ void k_copy(float* __restrict__ dst, const float* __restrict__ src, int n) {
  int i = blockIdx.x * 256 + threadIdx.x;
  if (i < n) dst[i] = src[i];
}

// round a weight array to tf32 (n % 4 == 0)
__global__ void k_round(float* __restrict__ dst, const float* __restrict__ src, int n) {
  int i = (blockIdx.x * 256 + threadIdx.x) * 4;
  if (i < n) {
    float4 v = *(const float4*)(src + i);
    float4 o = {f2tf_f(v.x), f2tf_f(v.y), f2tf_f(v.z), f2tf_f(v.w)};
    *(float4*)(dst + i) = o;
  }
}

// ---------------- cond = silu(fourier @ tcond_w + b) ----------------
__global__ void k_cond(const float* __restrict__ times, const float* __restrict__ fw,
                       const float* __restrict__ tw, const float* __restrict__ tb) {
  __shared__ float fs[1025];
  int b = blockIdx.y;
  float t = times[b];
  for (int i = threadIdx.x; i < 1025; i += 256) {
    if (i == 0)        fs[0] = t;
    else if (i <= 512) fs[i] = sinf(6.283185307179586f * t * fw[i - 1]);
    else               fs[i] = cosf(6.283185307179586f * t * fw[i - 513]);
  }
  __syncthreads();
  int j = blockIdx.x * 256 + threadIdx.x;
  float acc = tb[j];
  for (int k = 0; k < 1025; k++) acc += fs[k] * tw[k * cDc + j];
  g_cond[b * cDc + j] = acc / (1.f + expf(-acc));
}

// ---------------- all cond projections; both batch rows share one weight read ----------------
__global__ void k_proj(const float* __restrict__ afw, const float* __restrict__ afb,
                       const float* __restrict__ ffw, const float* __restrict__ ffb,
                       const float* __restrict__ aaw, const float* __restrict__ aab,
                       const float* __restrict__ faw, const float* __restrict__ fab) {
  __shared__ float cs0[cDc], cs1[cDc];
  int l = blockIdx.y;
  for (int i = threadIdx.x; i < cDc; i += 256) {
    cs0[i] = g_cond[i];
    cs1[i] = g_cond[cDc + i];
  }
  __syncthreads();
  int o = blockIdx.x * 256 + threadIdx.x;
  const float* W; const float* bias; float* out; int cols; int c; bool sig = false;
  if (o < 2048)      { c = o;        cols = 2048; W = afw + (size_t)l*cDc*2048; bias = afb + l*2048; out = g_attn_film + (size_t)l*cB*2048; }
  else if (o < 4096) { c = o - 2048; cols = 2048; W = ffw + (size_t)l*cDc*2048; bias = ffb + l*2048; out = g_ff_film   + (size_t)l*cB*2048; }
  else if (o < 5120) { c = o - 4096; cols = 1024; W = aaw + (size_t)l*cDc*1024; bias = aab + l*1024; out = g_attn_adaz + (size_t)l*cB*1024; sig = true; }
  else               { c = o - 5120; cols = 1024; W = faw + (size_t)l*cDc*1024; bias = fab + l*1024; out = g_ff_adaz   + (size_t)l*cB*1024; sig = true; }
  float acc0 = bias[c], acc1 = bias[c];
  #pragma unroll 8
  for (int k = 0; k < cDc; k++) {
    float w = W[(size_t)k * cols + c];
    acc0 += cs0[k] * w;
    acc1 += cs1[k] * w;
  }
  if (sig) { acc0 = 1.f / (1.f + expf(-acc0)); acc1 = 1.f / (1.f + expf(-acc1)); }
  out[c] = acc0;
  out[cols + c] = acc1;
}

// ---------------- LN + FiLM (emits tf32-rounded xc) ----------------
__global__ void k_lnfilm(const float* __restrict__ film) {
  int row = blockIdx.x;
  int b = row >> 10;
  int tid = threadIdx.x;
  float4 v = ((const float4*)(g_x + (size_t)row * cD))[tid];
  float s  = v.x + v.y + v.z + v.w;
  float s2 = v.x*v.x + v.y*v.y + v.z*v.z + v.w*v.w;
  #pragma unroll
  for (int off = 16; off > 0; off >>= 1) {
    s  += __shfl_xor_sync(0xffffffffu, s,  off);
    s2 += __shfl_xor_sync(0xffffffffu, s2, off);
  }
  __shared__ float ws[8], ws2[8];
  __shared__ float smu, srstd;
  if ((tid & 31) == 0) { ws[tid >> 5] = s; ws2[tid >> 5] = s2; }
  __syncthreads();
  if (tid == 0) {
    float t1 = 0.f, t2 = 0.f;
    for (int w = 0; w < 8; w++) { t1 += ws[w]; t2 += ws2[w]; }
    float mu = t1 * (1.f / cD);
    float var = t2 * (1.f / cD) - mu * mu;
    smu = mu; srstd = rsqrtf(var + 1e-5f);
  }
  __syncthreads();
  float mu = smu, rs = srstd;
  const float* fg = film + b * 2 * cD;
  int d = tid * 4;
  float4 o;
  o.x = f2tf_f((v.x - mu) * rs * (fg[d+0] + 1.f) + fg[cD + d + 0]);
  o.y = f2tf_f((v.y - mu) * rs * (fg[d+1] + 1.f) + fg[cD + d + 1]);
  o.z = f2tf_f((v.z - mu) * rs * (fg[d+2] + 1.f) + fg[cD + d + 2]);
  o.w = f2tf_f((v.w - mu) * rs * (fg[d+3] + 1.f) + fg[cD + d + 3]);
  ((float4*)(g_xc + (size_t)row * cD))[tid] = o;
}

// ---------------- tf32 tensor-core GEMM, cp.async 2-stage pipeline ----------------
// C[M,N] = A[M,K] @ W[K,N]; inputs already tf32-rounded bit patterns.
// Optional: +bias, then if adaz: C = resid + C*adaz[b*N+c].
// 128x128 block tile, BK=16, 8 warps (2x4), warp 64x32, mma.m16n8k8.tf32.
__device__ __forceinline__ void mma_tf32(float (&c)[4], const unsigned (&a)[4],
                                         const unsigned (&b)[2]) {
  asm volatile(
      "mma.sync.aligned.m16n8k8.row.col.f32.tf32.tf32.f32 "
      "{%0,%1,%2,%3}, {%4,%5,%6,%7}, {%8,%9}, {%0,%1,%2,%3};\n"
      : "+f"(c[0]), "+f"(c[1]), "+f"(c[2]), "+f"(c[3])
      : "r"(a[0]), "r"(a[1]), "r"(a[2]), "r"(a[3]), "r"(b[0]), "r"(b[1]));
}
__device__ __forceinline__ void cpa16(void* smem, const void* gmem, bool valid) {
  unsigned sa = (unsigned)__cvta_generic_to_shared(smem);
  int sz = valid ? 16 : 0;
  asm volatile("cp.async.cg.shared.global [%0], [%1], 16, %2;\n"
               :: "r"(sa), "l"(gmem), "r"(sz) : "memory");
}

__global__ __launch_bounds__(256, 2) void k_gemm(
    const float* __restrict__ A, const float* __restrict__ W,
    const float* __restrict__ bias, float* __restrict__ C,
    const float* __restrict__ resid, const float* __restrict__ adaz,
    int M, int N, int K, int lda) {
  __shared__ unsigned sA[2][128][20];   // [m][k], pad 4
  __shared__ unsigned sB[2][16][136];   // [k][n], pad 8
  int tid = threadIdx.x;
  int warp = tid >> 5, lane = tid & 31;
  int wm = warp >> 2, wn = warp & 3;
  int g = lane >> 2, t = lane & 3;
  int rb = blockIdx.y * 128, cb = blockIdx.x * 128;
  float acc[4][4][4] = {};
  int nk = (K + 15) / 16;

  // stage loader: A always full 16B (row-padded / tail-padded buffers make it safe;
  // garbage k>=K contributes 0 because B is zero-filled there). B guarded.
  auto load_stage = [&](int buf, int k0) {
    #pragma unroll
    for (int it = 0; it < 2; it++) {
      int idx = tid + it * 256;              // 0..511
      int m = idx >> 2, kg = idx & 3;
      int gk = k0 + kg * 4;
      cpa16(&sA[buf][m][kg * 4], A + (size_t)(rb + m) * lda + gk, true);
    }
    #pragma unroll
    for (int it = 0; it < 2; it++) {
      int idx = tid + it * 256;
      int kk = idx >> 5, n4 = idx & 31;
      int gk = k0 + kk, gn = cb + n4 * 4;
      bool ok = (gk < K) && (gn < N);
      cpa16(&sB[buf][kk][n4 * 4], W + (size_t)gk * N + gn, ok);
    }
    asm volatile("cp.async.commit_group;\n" ::: "memory");
  };

  load_stage(0, 0);
  for (int it = 0; it < nk; it++) {
    asm volatile("cp.async.wait_group 0;\n" ::: "memory");
    __syncthreads();
    if (it + 1 < nk) load_stage((it + 1) & 1, (it + 1) * 16);
    int buf = it & 1;
    #pragma unroll
    for (int ks = 0; ks < 2; ks++) {
      int kb = ks * 8;
      unsigned a[4][4], b[4][2];
      #pragma unroll
      for (int i = 0; i < 4; i++) {
        int mr = wm * 64 + i * 16;
        a[i][0] = sA[buf][mr + g][kb + t];
        a[i][1] = sA[buf][mr + 8 + g][kb + t];
        a[i][2] = sA[buf][mr + g][kb + 4 + t];
        a[i][3] = sA[buf][mr + 8 + g][kb + 4 + t];
      }
      #pragma unroll
      for (int j = 0; j < 4; j++) {
        int nc = wn * 32 + j * 8;
        b[j][0] = sB[buf][kb + t][nc + g];
        b[j][1] = sB[buf][kb + 4 + t][nc + g];
      }
      #pragma unroll
      for (int i = 0; i < 4; i++)
        #pragma unroll
        for (int j = 0; j < 4; j++)
          mma_tf32(acc[i][j], a[i], b[j]);
    }
  }

  #pragma unroll
  for (int i = 0; i < 4; i++) {
    int r0 = rb + wm * 64 + i * 16 + g;
    int bidx = r0 >> 10;   // batch (rows/batch = 1024, tile-aligned)
    #pragma unroll
    for (int j = 0; j < 4; j++) {
      int c0 = cb + wn * 32 + j * 8 + 2 * t;
      if (c0 < N) {
        float b0 = bias ? bias[c0] : 0.f;
        float b1 = bias ? bias[c0 + 1] : 0.f;
        float v00 = acc[i][j][0] + b0, v01 = acc[i][j][1] + b1;
        float v10 = acc[i][j][2] + b0, v11 = acc[i][j][3] + b1;
        if (adaz) {
          const float* az = adaz + bidx * N;
          float a0 = az[c0], a1 = az[c0 + 1];
          v00 = resid[(size_t)r0 * N + c0]       + v00 * a0;
          v01 = resid[(size_t)r0 * N + c0 + 1]   + v01 * a1;
          v10 = resid[(size_t)(r0+8) * N + c0]   + v10 * a0;
          v11 = resid[(size_t)(r0+8) * N + c0+1] + v11 * a1;
        }
        float2 w0 = {v00, v01}, w1 = {v10, v11};
        *(float2*)&C[(size_t)r0 * N + c0] = w0;
        *(float2*)&C[(size_t)(r0 + 8) * N + c0] = w1;
      }
    }
  }
}

// ---------------- rope on q,k in g_qkv ----------------
__global__ void k_rope(const float* __restrict__ rf) {
  int i = blockIdx.x * 256 + threadIdx.x;
  if (i >= cRows * cH * 32) return;
  int p = i & 31;
  int h = (i >> 5) & 15;
  int row = i >> 9;
  int n = row & 1023;
  float f = rf[n * 64 + 2 * p];
  float csv = cosf(f), snv = sinf(f);
  size_t base = (size_t)row * 3072 + h * 64 + 2 * p;
  #pragma unroll
  for (int s = 0; s < 2; s++) {
    float x0 = g_qkv[base + s * 1024];
    float x1 = g_qkv[base + s * 1024 + 1];
    g_qkv[base + s * 1024]     = x0 * csv - x1 * snv;
    g_qkv[base + s * 1024 + 1] = x1 * csv + x0 * snv;
  }
}

__global__ void k_savevr() {
  int i = blockIdx.x * 256 + threadIdx.x;
  if (i >= cRows * cD) return;
  int row = i >> 10, c = i & 1023;
  g_vr[i] = g_qkv[(size_t)row * 3072 + 2048 + c];
}

// ---------------- gates = sigmoid(xc @ gates_w) ----------------
__global__ void k_gates(const float* __restrict__ gw) {
  int i = blockIdx.x * 256 + threadIdx.x;
  if (i >= cRows * cH) return;
  int row = i >> 4, h = i & 15;
  const float* xr = g_xc + (size_t)row * cD;
  float acc = 0.f;
  #pragma unroll 4
  for (int k = 0; k < cD; k++) acc += xr[k] * gw[k * cH + h];
  g_gates[i] = 1.f / (1.f + expf(-acc));
}

// ---------------- fused causal attention (emits tf32-rounded o) ----------------
__global__ void k_attn(int mix) {
  __shared__ float Qs[32 * 65];
  __shared__ float KP[64 * 65];
  __shared__ float Vs[64 * 64];
  int qt = blockIdx.x, bh = blockIdx.y;
  int b = bh >> 4, h = bh & 15;
  int q0 = qt * 32;
  int tid = threadIdx.x;
  int tx = tid & 15, ty = tid >> 4;

  for (int idx = tid; idx < 32 * 64; idx += 256) {
    int r = idx >> 6, d = idx & 63;
    Qs[r * 65 + d] = g_qkv[(size_t)(b * cN + q0 + r) * 3072 + h * 64 + d];
  }

  float o[2][4] = {};
  float mrun[2] = {-1e30f, -1e30f};
  float lrun[2] = {0.f, 0.f};
  int ktmax = (q0 + 31) >> 6;

  for (int kt = 0; kt <= ktmax; kt++) {
    int k0 = kt * 64;
    __syncthreads();
    for (int idx = tid; idx < 64 * 64; idx += 256) {
      int r = idx >> 6, d = idx & 63;
      size_t base = (size_t)(b * cN + k0 + r) * 3072 + h * 64 + d;
      KP[r * 65 + d] = g_qkv[base + 1024];
      float vv = g_qkv[base + 2048];
      if (mix) vv = 0.5f * (vv + g_vr[(size_t)(b * cN + k0 + r) * 1024 + h * 64 + d]);
      Vs[r * 64 + d] = vv;
    }
    __syncthreads();

    float s[2][4] = {};
    #pragma unroll 8
    for (int d = 0; d < 64; d++) {
      float a0 = Qs[(ty * 2) * 65 + d];
      float a1 = Qs[(ty * 2 + 1) * 65 + d];
      #pragma unroll
      for (int j = 0; j < 4; j++) {
        float kv = KP[(tx * 4 + j) * 65 + d];
        s[0][j] += a0 * kv;
        s[1][j] += a1 * kv;
      }
    }

    float p[2][4];
    #pragma unroll
    for (int ri = 0; ri < 2; ri++) {
      int ig = q0 + ty * 2 + ri;
      float rmax = -1e30f;
      #pragma unroll
      for (int j = 0; j < 4; j++) {
        int jg = k0 + tx * 4 + j;
        float v = s[ri][j] * 0.125f;
        v = 50.f * tanhf(v * 0.02f);
        if (jg > ig) v = -1e30f;
        s[ri][j] = v;
        rmax = fmaxf(rmax, v);
      }
      #pragma unroll
      for (int off = 1; off < 16; off <<= 1)
        rmax = fmaxf(rmax, __shfl_xor_sync(0xffffffffu, rmax, off));
      float mnew  = fmaxf(mrun[ri], rmax);
      float alpha = __expf(mrun[ri] - mnew);
      float rsum = 0.f;
      #pragma unroll
      for (int j = 0; j < 4; j++) {
        float pv = __expf(s[ri][j] - mnew);
        p[ri][j] = pv;
        rsum += pv;
      }
      #pragma unroll
      for (int off = 1; off < 16; off <<= 1)
        rsum += __shfl_xor_sync(0xffffffffu, rsum, off);
      lrun[ri] = lrun[ri] * alpha + rsum;
      mrun[ri] = mnew;
      #pragma unroll
      for (int j = 0; j < 4; j++) o[ri][j] *= alpha;
    }

    __syncthreads();
    #pragma unroll
    for (int ri = 0; ri < 2; ri++)
      #pragma unroll
      for (int j = 0; j < 4; j++)
        KP[(ty * 2 + ri) * 65 + tx * 4 + j] = p[ri][j];
    __syncthreads();

    #pragma unroll 4
    for (int j = 0; j < 64; j++) {
      float p0 = KP[(ty * 2) * 65 + j];
      float p1 = KP[(ty * 2 + 1) * 65 + j];
      float4 v4 = *(const float4*)&Vs[j * 64 + tx * 4];
      o[0][0] += p0 * v4.x; o[0][1] += p0 * v4.y; o[0][2] += p0 * v4.z; o[0][3] += p0 * v4.w;
      o[1][0] += p1 * v4.x; o[1][1] += p1 * v4.y; o[1][2] += p1 * v4.z; o[1][3] += p1 * v4.w;
    }
  }

  #pragma unroll
  for (int ri = 0; ri < 2; ri++) {
    int nIdx = q0 + ty * 2 + ri;
    float gate = g_gates[(b * cN + nIdx) * cH + h];
    float inv = gate / lrun[ri];
    #pragma unroll
    for (int j = 0; j < 4; j++)
      g_o[(size_t)(b * cN + nIdx) * cD + h * 64 + tx * 4 + j] = f2tf_f(o[ri][j] * inv);
  }
}

// ---------------- glu: ffa = tf32(gelu_exact(gate) * a) ----------------
__global__ void k_glu() {
  int i = blockIdx.x * 256 + threadIdx.x;
  if (i >= cRows * cDff) return;
  int row = i / cDff, c = i - row * cDff;
  float a = g_tmp[(size_t)row * 2 * cDff + c];
  float g = g_tmp[(size_t)row * 2 * cDff + cDff + c];
  float ge = 0.5f * g * (1.f + erff(g * 0.7071067811865476f));
  g_ffa[(size_t)row * cDffP + c] = f2tf_f(ge * a);
}

// ---------------- xcat = tf32([x, skip]) ----------------
__global__ void k_concat(const float* __restrict__ skip) {
  int i = blockIdx.x * 256 + threadIdx.x;
  if (i >= cRows * 2 * cD) return;
  int row = i >> 11, c = i & 2047;
  float v = (c < 1024) ? g_x[(size_t)row * cD + c] : skip[(size_t)row * cD + c - 1024];
  g_xcat[i] = f2tf_f(v);
}

// ---------------- final norm ----------------
__global__ void k_final(const float* __restrict__ gamma, float* __restrict__ out) {
  int row = blockIdx.x;
  int tid = threadIdx.x;
  float4 v = ((const float4*)(g_x + (size_t)row * cD))[tid];
  float s2 = v.x*v.x + v.y*v.y + v.z*v.z + v.w*v.w;
  #pragma unroll
  for (int off = 16; off > 0; off >>= 1)
    s2 += __shfl_xor_sync(0xffffffffu, s2, off);
  __shared__ float ws2[8];
  __shared__ float sscale;
  if ((tid & 31) == 0) ws2[tid >> 5] = s2;
  __syncthreads();
  if (tid == 0) {
    float t2 = 0.f;
    for (int w = 0; w < 8; w++) t2 += ws2[w];
    sscale = 32.f / fmaxf(sqrtf(t2), 1e-12f);
  }
  __syncthreads();
  float sc = sscale;
  int d = tid * 4;
  float4 o;
  o.x = v.x * sc * (gamma[d + 0] + 1.f);
  o.y = v.y * sc * (gamma[d + 1] + 1.f);
  o.z = v.z * sc * (gamma[d + 2] + 1.f);
  o.w = v.w * sc * (gamma[d + 3] + 1.f);
  ((float4*)(out + (size_t)row * cD))[tid] = o;
}

// ---------------- host launcher ----------------
extern "C" void kernel_launch(void* const* d_in, const int* in_sizes, int n_in,
                              void* d_out, int out_size) {
  const float* in_x  = (const float*)d_in[0];
  const float* times = (const float*)d_in[1];
  const float* rf    = (const float*)d_in[2];
  const float* fw    = (const float*)d_in[3];
  const float* tw    = (const float*)d_in[4];
  const float* tb    = (const float*)d_in[5];
  const float* skw   = (const float*)d_in[6];
  const float* afw   = (const float*)d_in[7];
  const float* afb   = (const float*)d_in[8];
  const float* aaw   = (const float*)d_in[9];
  const float* aab   = (const float*)d_in[10];
  const float* qkvw  = (const float*)d_in[11];
  const float* gw    = (const float*)d_in[12];
  const float* ow    = (const float*)d_in[13];
  const float* ffw   = (const float*)d_in[14];
  const float* ffb   = (const float*)d_in[15];
  const float* faw   = (const float*)d_in[16];
  const float* fab   = (const float*)d_in[17];
  const float* w1    = (const float*)d_in[18];
  const float* b1    = (const float*)d_in[19];
  const float* w2    = (const float*)d_in[20];
  const float* b2    = (const float*)d_in[21];
  const float* gamma = (const float*)d_in[22];
  float* out = (float*)d_out;

  float *px, *pxc, *pqkv, *po, *ptmp, *pffa, *pxcat, *pskip, *paf, *pff, *paa, *pfa;
  float *pwq, *pwo, *pw1, *pw2, *pws;
  cudaGetSymbolAddress((void**)&px,    g_x);
  cudaGetSymbolAddress((void**)&pxc,   g_xc);
  cudaGetSymbolAddress((void**)&pqkv,  g_qkv);
  cudaGetSymbolAddress((void**)&po,    g_o);
  cudaGetSymbolAddress((void**)&ptmp,  g_tmp);
  cudaGetSymbolAddress((void**)&pffa,  g_ffa);
  cudaGetSymbolAddress((void**)&pxcat, g_xcat);
  cudaGetSymbolAddress((void**)&pskip, g_skip);
  cudaGetSymbolAddress((void**)&paf,   g_attn_film);
  cudaGetSymbolAddress((void**)&pff,   g_ff_film);
  cudaGetSymbolAddress((void**)&paa,   g_attn_adaz);
  cudaGetSymbolAddress((void**)&pfa,   g_ff_adaz);
  cudaGetSymbolAddress((void**)&pwq,   g_wq);
  cudaGetSymbolAddress((void**)&pwo,   g_wo);
  cudaGetSymbolAddress((void**)&pw1,   g_w1);
  cudaGetSymbolAddress((void**)&pw2,   g_w2);
  cudaGetSymbolAddress((void**)&pws,   g_ws);

  // pre-round GEMM weights to tf32
  {
    int nq = cL * cD * 3 * cD, no = cL * cD * cD, n1 = cL * cD * 2 * cDff,
        n2 = cL * cDff * cD, ns = 3 * 2 * cD * cD;
    k_round<<<(nq / 4 + 255) / 256, 256>>>(pwq, qkvw, nq);
    k_round<<<(no / 4 + 255) / 256, 256>>>(pwo, ow, no);
    k_round<<<(n1 / 4 + 255) / 256, 256>>>(pw1, w1, n1);
    k_round<<<(n2 / 4 + 255) / 256, 256>>>(pw2, w2, n2);
    k_round<<<(ns / 4 + 255) / 256, 256>>>(pws, skw, ns);
  }

  k_copy<<<(cRows * cD) / 256, 256>>>(px, in_x, cRows * cD);
  k_cond<<<dim3(cDc / 256, cB), 256>>>(times, fw, tw, tb);
  k_proj<<<dim3(24, cL), 256>>>(afw, afb, ffw, ffb, aaw, aab, faw, fab);

  for (int l = 0; l < cL; l++) {
    if (l < 3) {
      k_copy<<<(cRows * cD) / 256, 256>>>(pskip + (size_t)l * cRows * cD, px, cRows * cD);
    } else {
      k_concat<<<(cRows * 2 * cD) / 256, 256>>>(pskip + (size_t)(5 - l) * cRows * cD);
      k_gemm<<<dim3(8, 16), 256>>>(pxcat, pws + (size_t)(l - 3) * 2048 * 1024, nullptr, px,
                                   nullptr, nullptr, cRows, 1024, 2048, 2048);
    }
    // attention block
    k_lnfilm<<<cRows, 256>>>(paf + (size_t)l * cB * 2 * cD);
    k_gemm<<<dim3(24, 16), 256>>>(pxc, pwq + (size_t)l * 1024 * 3072, nullptr, pqkv,
                                  nullptr, nullptr, cRows, 3072, 1024, 1024);
    if (l == 0) k_savevr<<<(cRows * cD) / 256, 256>>>();
    k_rope<<<(cRows * cH * 32) / 256, 256>>>(rf);
    k_gates<<<(cRows * cH) / 256, 256>>>(gw + (size_t)l * 1024 * 16);
    k_attn<<<dim3(32, 32), 256>>>(l > 0 ? 1 : 0);
    // out proj fused with residual * adaz
    k_gemm<<<dim3(8, 16), 256>>>(po, pwo + (size_t)l * 1024 * 1024, nullptr, px,
                                 px, paa + (size_t)l * cB * cD, cRows, 1024, 1024, 1024);
    // feed-forward block
    k_lnfilm<<<cRows, 256>>>(pff + (size_t)l * cB * 2 * cD);
    k_gemm<<<dim3(43, 16), 256>>>(pxc, pw1 + (size_t)l * 1024 * (2 * cDff),
                                  b1 + (size_t)l * (2 * cDff), ptmp,
                                  nullptr, nullptr, cRows, 2 * cDff, 1024, 1024);
    k_glu<<<(cRows * cDff + 255) / 256, 256>>>();
    // ff2 fused with residual * adaz
    k_gemm<<<dim3(8, 16), 256>>>(pffa, pw2 + (size_t)l * cDff * 1024,
                                 b2 + (size_t)l * 1024, px,
                                 px, pfa + (size_t)l * cB * cD, cRows, 1024, cDff, cDffP);
  }
  k_final<<<cRows, 256>>>(gamma, out);
}

// round 6
// speedup vs baseline: 3.0821x; 1.1439x over previous
#include <cuda_runtime.h>
#include <math.h>

// ---------------- problem constants ----------------
constexpr int cB   = 2;
constexpr int cN   = 1024;
constexpr int cD   = 1024;
constexpr int cL   = 6;
constexpr int cH   = 16;
constexpr int cDff = 2730;
constexpr int cDffP = 2732;    // padded (multiple of 4 -> 16B-aligned rows)
constexpr int cDc  = 4096;     // cond dim = 4*DIM
constexpr int cRows = cB * cN; // 2048

// ---------------- device scratch (static, allocation-free, zero-initialized) ----------------
__device__ float g_cond[cB * cDc];
__device__ float g_attn_film[cL * cB * 2 * cD];
__device__ float g_ff_film[cL * cB * 2 * cD];
__device__ float g_attn_adaz[cL * cB * cD];
__device__ float g_ff_adaz[cL * cB * cD];
__device__ __align__(16) float g_x[cRows * cD];
__device__ __align__(16) float g_xc[cRows * cD];
__device__ __align__(16) float g_qkv[cRows * 3 * cD];
__device__ __align__(16) float g_vr[cRows * cD];
__device__ __align__(16) float g_o[cRows * cD];
__device__ __align__(16) float g_tmp[cRows * 2 * cDff];
__device__ __align__(16) float g_ffa[cRows * cDffP + 64];  // +tail pad for overread
__device__ __align__(16) float g_skip[3][cRows * cD];
__device__ __align__(16) float g_xcat[cRows * 2 * cD];
__device__ float g_gates[cRows * cH];

// pre-rounded (tf32) weights
__device__ __align__(16) float g_wq[cL * cD * 3 * cD];
__device__ __align__(16) float g_wo[cL * cD * cD];
__device__ __align__(16) float g_w1[cL * cD * 2 * cDff];
__device__ __align__(16) float g_w2[cL * cDff * cD];
__device__ __align__(16) float g_ws[3 * 2 * cD * cD];

__device__ __forceinline__ float f2tf_f(float x) {
  unsigned u;
  asm("cvt.rna.tf32.f32 %0, %1;" : "=r"(u) : "f"(x));
  return __uint_as_float(u);
}
__device__ __forceinline__ unsigned f2tf_u(float x) {
  unsigned u;
  asm("cvt.rna.tf32.f32 %0, %1;" : "=r"(u) : "f"(x));
  return u;
}

// ---------------- utility ----------------
__global__ void k_copy(float* __restrict__ dst, const float* __restrict__ src, int n) {
  int i = blockIdx.x * 256 + threadIdx.x;
  if (i < n) dst[i] = src[i];
}

__global__ void k_round(float* __restrict__ dst, const float* __restrict__ src, int n) {
  int i = (blockIdx.x * 256 + threadIdx.x) * 4;
  if (i < n) {
    float4 v = *(const float4*)(src + i);
    float4 o = {f2tf_f(v.x), f2tf_f(v.y), f2tf_f(v.z), f2tf_f(v.w)};
    *(float4*)(dst + i) = o;
  }
}

// ---------------- cond = silu(fourier @ tcond_w + b) ----------------
__global__ void k_cond(const float* __restrict__ times, const float* __restrict__ fw,
                       const float* __restrict__ tw, const float* __restrict__ tb) {
  __shared__ float fs[1025];
  int b = blockIdx.y;
  float t = times[b];
  for (int i = threadIdx.x; i < 1025; i += 256) {
    if (i == 0)        fs[0] = t;
    else if (i <= 512) fs[i] = sinf(6.283185307179586f * t * fw[i - 1]);
    else               fs[i] = cosf(6.283185307179586f * t * fw[i - 513]);
  }
  __syncthreads();
  int j = blockIdx.x * 256 + threadIdx.x;
  float acc = tb[j];
  for (int k = 0; k < 1025; k++) acc += fs[k] * tw[k * cDc + j];
  g_cond[b * cDc + j] = acc / (1.f + expf(-acc));
}

// ---------------- all cond projections; both batch rows share one weight read ----------------
__global__ void k_proj(const float* __restrict__ afw, const float* __restrict__ afb,
                       const float* __restrict__ ffw, const float* __restrict__ ffb,
                       const float* __restrict__ aaw, const float* __restrict__ aab,
                       const float* __restrict__ faw, const float* __restrict__ fab) {
  __shared__ float cs0[cDc], cs1[cDc];
  int l = blockIdx.y;
  for (int i = threadIdx.x; i < cDc; i += 256) {
    cs0[i] = g_cond[i];
    cs1[i] = g_cond[cDc + i];
  }
  __syncthreads();
  int o = blockIdx.x * 256 + threadIdx.x;
  const float* W; const float* bias; float* out; int cols; int c; bool sig = false;
  if (o < 2048)      { c = o;        cols = 2048; W = afw + (size_t)l*cDc*2048; bias = afb + l*2048; out = g_attn_film + (size_t)l*cB*2048; }
  else if (o < 4096) { c = o - 2048; cols = 2048; W = ffw + (size_t)l*cDc*2048; bias = ffb + l*2048; out = g_ff_film   + (size_t)l*cB*2048; }
  else if (o < 5120) { c = o - 4096; cols = 1024; W = aaw + (size_t)l*cDc*1024; bias = aab + l*1024; out = g_attn_adaz + (size_t)l*cB*1024; sig = true; }
  else               { c = o - 5120; cols = 1024; W = faw + (size_t)l*cDc*1024; bias = fab + l*1024; out = g_ff_adaz   + (size_t)l*cB*1024; sig = true; }
  float acc0 = bias[c], acc1 = bias[c];
  #pragma unroll 8
  for (int k = 0; k < cDc; k++) {
    float w = W[(size_t)k * cols + c];
    acc0 += cs0[k] * w;
    acc1 += cs1[k] * w;
  }
  if (sig) { acc0 = 1.f / (1.f + expf(-acc0)); acc1 = 1.f / (1.f + expf(-acc1)); }
  out[c] = acc0;
  out[cols + c] = acc1;
}

// ---------------- LN + FiLM (emits tf32-rounded xc) ----------------
__global__ void k_lnfilm(const float* __restrict__ film) {
  int row = blockIdx.x;
  int b = row >> 10;
  int tid = threadIdx.x;
  float4 v = ((const float4*)(g_x + (size_t)row * cD))[tid];
  float s  = v.x + v.y + v.z + v.w;
  float s2 = v.x*v.x + v.y*v.y + v.z*v.z + v.w*v.w;
  #pragma unroll
  for (int off = 16; off > 0; off >>= 1) {
    s  += __shfl_xor_sync(0xffffffffu, s,  off);
    s2 += __shfl_xor_sync(0xffffffffu, s2, off);
  }
  __shared__ float ws[8], ws2[8];
  __shared__ float smu, srstd;
  if ((tid & 31) == 0) { ws[tid >> 5] = s; ws2[tid >> 5] = s2; }
  __syncthreads();
  if (tid == 0) {
    float t1 = 0.f, t2 = 0.f;
    for (int w = 0; w < 8; w++) { t1 += ws[w]; t2 += ws2[w]; }
    float mu = t1 * (1.f / cD);
    float var = t2 * (1.f / cD) - mu * mu;
    smu = mu; srstd = rsqrtf(var + 1e-5f);
  }
  __syncthreads();
  float mu = smu, rs = srstd;
  const float* fg = film + b * 2 * cD;
  int d = tid * 4;
  float4 o;
  o.x = f2tf_f((v.x - mu) * rs * (fg[d+0] + 1.f) + fg[cD + d + 0]);
  o.y = f2tf_f((v.y - mu) * rs * (fg[d+1] + 1.f) + fg[cD + d + 1]);
  o.z = f2tf_f((v.z - mu) * rs * (fg[d+2] + 1.f) + fg[cD + d + 2]);
  o.w = f2tf_f((v.w - mu) * rs * (fg[d+3] + 1.f) + fg[cD + d + 3]);
  ((float4*)(g_xc + (size_t)row * cD))[tid] = o;
}

// ---------------- tf32 tensor-core GEMM, cp.async 3-stage pipeline ----------------
__device__ __forceinline__ void mma_tf32(float (&c)[4], const unsigned (&a)[4],
                                         const unsigned (&b)[2]) {
  asm volatile(
      "mma.sync.aligned.m16n8k8.row.col.f32.tf32.tf32.f32 "
      "{%0,%1,%2,%3}, {%4,%5,%6,%7}, {%8,%9}, {%0,%1,%2,%3};\n"
      : "+f"(c[0]), "+f"(c[1]), "+f"(c[2]), "+f"(c[3])
      : "r"(a[0]), "r"(a[1]), "r"(a[2]), "r"(a[3]), "r"(b[0]), "r"(b[1]));
}
__device__ __forceinline__ void cpa16(void* smem, const void* gmem, bool valid) {
  unsigned sa = (unsigned)__cvta_generic_to_shared(smem);
  int sz = valid ? 16 : 0;
  asm volatile("cp.async.cg.shared.global [%0], [%1], 16, %2;\n"
               :: "r"(sa), "l"(gmem), "r"(sz) : "memory");
}

constexpr int GA_STRIDE = 20;     // sA row stride (u32)
constexpr int GB_STRIDE = 136;    // sB row stride (u32)
constexpr int GA_STAGE = 128 * GA_STRIDE;   // 2560 u32
constexpr int GB_STAGE = 16 * GB_STRIDE;    // 2176 u32
constexpr int G_STAGE  = GA_STAGE + GB_STAGE;
constexpr int GEMM_SMEM_BYTES = 3 * G_STAGE * 4;   // 56832 B

__global__ __launch_bounds__(256, 2) void k_gemm(
    const float* __restrict__ A, const float* __restrict__ W,
    const float* __restrict__ bias, float* __restrict__ C,
    const float* __restrict__ resid, const float* __restrict__ adaz,
    int M, int N, int K, int lda) {
  extern __shared__ unsigned dsm[];
  int tid = threadIdx.x;
  int warp = tid >> 5, lane = tid & 31;
  int wm = warp >> 2, wn = warp & 3;
  int g = lane >> 2, t = lane & 3;
  int rb = blockIdx.y * 128, cb = blockIdx.x * 128;
  float acc[4][4][4] = {};
  int nk = (K + 15) / 16;

  auto load_stage = [&](int buf, int k0) {
    unsigned* sA = dsm + buf * GA_STAGE;
    unsigned* sB = dsm + 3 * GA_STAGE + buf * GB_STAGE;
    #pragma unroll
    for (int it = 0; it < 2; it++) {
      int idx = tid + it * 256;              // 0..511
      int m = idx >> 2, kg = idx & 3;
      int gk = k0 + kg * 4;
      cpa16(&sA[m * GA_STRIDE + kg * 4], A + (size_t)(rb + m) * lda + gk, true);
    }
    #pragma unroll
    for (int it = 0; it < 2; it++) {
      int idx = tid + it * 256;
      int kk = idx >> 5, n4 = idx & 31;
      int gk = k0 + kk, gn = cb + n4 * 4;
      bool ok = (gk < K) && (gn < N);
      cpa16(&sB[kk * GB_STRIDE + n4 * 4], W + (size_t)gk * N + gn, ok);
    }
    asm volatile("cp.async.commit_group;\n" ::: "memory");
  };

  load_stage(0, 0);
  if (nk > 1) load_stage(1, 16);
  for (int it = 0; it < nk; it++) {
    if (it + 2 <= nk) {
      asm volatile("cp.async.wait_group 1;\n" ::: "memory");
    } else {
      asm volatile("cp.async.wait_group 0;\n" ::: "memory");
    }
    __syncthreads();
    if (it + 2 < nk) load_stage((it + 2) % 3, (it + 2) * 16);
    int buf = it % 3;
    unsigned* sA = dsm + buf * GA_STAGE;
    unsigned* sB = dsm + 3 * GA_STAGE + buf * GB_STAGE;
    #pragma unroll
    for (int ks = 0; ks < 2; ks++) {
      int kb = ks * 8;
      unsigned a[4][4], b[4][2];
      #pragma unroll
      for (int i = 0; i < 4; i++) {
        int mr = wm * 64 + i * 16;
        a[i][0] = sA[(mr + g) * GA_STRIDE + kb + t];
        a[i][1] = sA[(mr + 8 + g) * GA_STRIDE + kb + t];
        a[i][2] = sA[(mr + g) * GA_STRIDE + kb + 4 + t];
        a[i][3] = sA[(mr + 8 + g) * GA_STRIDE + kb + 4 + t];
      }
      #pragma unroll
      for (int j = 0; j < 4; j++) {
        int nc = wn * 32 + j * 8;
        b[j][0] = sB[(kb + t) * GB_STRIDE + nc + g];
        b[j][1] = sB[(kb + 4 + t) * GB_STRIDE + nc + g];
      }
      #pragma unroll
      for (int i = 0; i < 4; i++)
        #pragma unroll
        for (int j = 0; j < 4; j++)
          mma_tf32(acc[i][j], a[i], b[j]);
    }
  }

  #pragma unroll
  for (int i = 0; i < 4; i++) {
    int r0 = rb + wm * 64 + i * 16 + g;
    int bidx = r0 >> 10;
    #pragma unroll
    for (int j = 0; j < 4; j++) {
      int c0 = cb + wn * 32 + j * 8 + 2 * t;
      if (c0 < N) {
        float b0 = bias ? bias[c0] : 0.f;
        float b1 = bias ? bias[c0 + 1] : 0.f;
        float v00 = acc[i][j][0] + b0, v01 = acc[i][j][1] + b1;
        float v10 = acc[i][j][2] + b0, v11 = acc[i][j][3] + b1;
        if (adaz) {
          const float* az = adaz + bidx * N;
          float a0 = az[c0], a1 = az[c0 + 1];
          v00 = resid[(size_t)r0 * N + c0]       + v00 * a0;
          v01 = resid[(size_t)r0 * N + c0 + 1]   + v01 * a1;
          v10 = resid[(size_t)(r0+8) * N + c0]   + v10 * a0;
          v11 = resid[(size_t)(r0+8) * N + c0+1] + v11 * a1;
        }
        float2 w0 = {v00, v01}, w1 = {v10, v11};
        *(float2*)&C[(size_t)r0 * N + c0] = w0;
        *(float2*)&C[(size_t)(r0 + 8) * N + c0] = w1;
      }
    }
  }
}

// ---------------- rope on q,k in g_qkv ----------------
__global__ void k_rope(const float* __restrict__ rf) {
  int i = blockIdx.x * 256 + threadIdx.x;
  if (i >= cRows * cH * 32) return;
  int p = i & 31;
  int h = (i >> 5) & 15;
  int row = i >> 9;
  int n = row & 1023;
  float f = rf[n * 64 + 2 * p];
  float csv = cosf(f), snv = sinf(f);
  size_t base = (size_t)row * 3072 + h * 64 + 2 * p;
  #pragma unroll
  for (int s = 0; s < 2; s++) {
    float x0 = g_qkv[base + s * 1024];
    float x1 = g_qkv[base + s * 1024 + 1];
    g_qkv[base + s * 1024]     = x0 * csv - x1 * snv;
    g_qkv[base + s * 1024 + 1] = x1 * csv + x0 * snv;
  }
}

__global__ void k_savevr() {
  int i = blockIdx.x * 256 + threadIdx.x;
  if (i >= cRows * cD) return;
  int row = i >> 10, c = i & 1023;
  g_vr[i] = g_qkv[(size_t)row * 3072 + 2048 + c];
}

// ---------------- gates = sigmoid(xc @ gates_w) ----------------
__global__ void k_gates(const float* __restrict__ gw) {
  int i = blockIdx.x * 256 + threadIdx.x;
  if (i >= cRows * cH) return;
  int row = i >> 4, h = i & 15;
  const float* xr = g_xc + (size_t)row * cD;
  float acc = 0.f;
  #pragma unroll 4
  for (int k = 0; k < cD; k++) acc += xr[k] * gw[k * cH + h];
  g_gates[i] = 1.f / (1.f + expf(-acc));
}

// ---------------- tensor-core flash attention ----------------
// softcap bounds logits to [-50,50] -> exp never over/underflows -> no online max.
// p = exp(50*tanh(s/50)), accurate tanh via exp.
__device__ __forceinline__ float softcap_exp(float sv) {
  sv = fminf(fmaxf(sv, -2000.f), 2000.f);
  float e = __expf(sv * 0.04f);                 // e^{2*(sv/50)}
  float th = __fdividef(e - 1.f, e + 1.f);      // tanh(sv/50)
  return __expf(50.f * th);
}

// grid: (16 qtiles of 64 rows, 32 bh); block 128 threads (4 warps, 16 q-rows each)
__global__ __launch_bounds__(128) void k_attn(int mix) {
  __shared__ unsigned KP[64][68];   // K tile (n=kpos, k=d), then P tile (q, kpos)
  __shared__ unsigned Vs[64][68];   // V tile (k=kpos, n=d); also stages Q at start
  int qt = (int)gridDim.x - 1 - (int)blockIdx.x;   // big tiles first
  int bh = blockIdx.y;
  int b = bh >> 4, h = bh & 15;
  int q0 = qt * 64;
  int tid = threadIdx.x, warp = tid >> 5, lane = tid & 31;
  int g = lane >> 2, t = lane & 3;
  int mr = warp * 16;

  // stage Q through Vs into register A-fragments
  for (int idx = tid; idx < 64 * 64; idx += 128) {
    int r = idx >> 6, d = idx & 63;
    Vs[r][d] = f2tf_u(g_qkv[(size_t)(b * cN + q0 + r) * 3072 + h * 64 + d]);
  }
  __syncthreads();
  unsigned qa[8][4];
  #pragma unroll
  for (int kb = 0; kb < 8; kb++) {
    qa[kb][0] = Vs[mr + g][kb * 8 + t];
    qa[kb][1] = Vs[mr + 8 + g][kb * 8 + t];
    qa[kb][2] = Vs[mr + g][kb * 8 + 4 + t];
    qa[kb][3] = Vs[mr + 8 + g][kb * 8 + 4 + t];
  }

  float o[8][4] = {};
  float l0 = 0.f, l1 = 0.f;
  int row0 = q0 + mr + g, row1 = row0 + 8;

  for (int kt = 0; kt <= qt; kt++) {
    int k0 = kt * 64;
    __syncthreads();   // protects Vs (Q staging / prev V) and KP (prev P)
    for (int idx = tid; idx < 64 * 64; idx += 128) {
      int r = idx >> 6, d = idx & 63;
      size_t base = (size_t)(b * cN + k0 + r) * 3072 + h * 64 + d;
      KP[r][d] = f2tf_u(g_qkv[base + 1024]);
      float vv = g_qkv[base + 2048];
      if (mix) vv = 0.5f * (vv + g_vr[(size_t)(b * cN + k0 + r) * 1024 + h * 64 + d]);
      Vs[r][d] = f2tf_u(vv);
    }
    __syncthreads();

    // S = Q @ K^T  (each warp: 16 x 64)
    float s[8][4] = {};
    #pragma unroll
    for (int kb = 0; kb < 8; kb++) {
      #pragma unroll
      for (int nf = 0; nf < 8; nf++) {
        unsigned bfr[2] = {KP[nf * 8 + g][kb * 8 + t], KP[nf * 8 + g][kb * 8 + 4 + t]};
        mma_tf32(s[nf], qa[kb], bfr);
      }
    }

    // softcap + causal mask + exp (no max subtraction needed)
    float p[8][4];
    #pragma unroll
    for (int nf = 0; nf < 8; nf++) {
      int c0 = k0 + nf * 8 + 2 * t, c1 = c0 + 1;
      float p0 = (c0 <= row0) ? softcap_exp(s[nf][0] * 0.125f) : 0.f;
      float p1 = (c1 <= row0) ? softcap_exp(s[nf][1] * 0.125f) : 0.f;
      float p2 = (c0 <= row1) ? softcap_exp(s[nf][2] * 0.125f) : 0.f;
      float p3 = (c1 <= row1) ? softcap_exp(s[nf][3] * 0.125f) : 0.f;
      p[nf][0] = p0; p[nf][1] = p1; p[nf][2] = p2; p[nf][3] = p3;
      l0 += p0 + p1;
      l1 += p2 + p3;
    }

    __syncthreads();   // everyone done reading KP as K
    #pragma unroll
    for (int nf = 0; nf < 8; nf++) {
      KP[mr + g][nf * 8 + 2 * t]     = f2tf_u(p[nf][0]);
      KP[mr + g][nf * 8 + 2 * t + 1] = f2tf_u(p[nf][1]);
      KP[mr + 8 + g][nf * 8 + 2 * t]     = f2tf_u(p[nf][2]);
      KP[mr + 8 + g][nf * 8 + 2 * t + 1] = f2tf_u(p[nf][3]);
    }
    __syncthreads();

    // o += P @ V
    #pragma unroll
    for (int kb = 0; kb < 8; kb++) {
      unsigned pa[4] = {KP[mr + g][kb * 8 + t], KP[mr + 8 + g][kb * 8 + t],
                        KP[mr + g][kb * 8 + 4 + t], KP[mr + 8 + g][kb * 8 + 4 + t]};
      #pragma unroll
      for (int nf = 0; nf < 8; nf++) {
        unsigned bfr[2] = {Vs[kb * 8 + t][nf * 8 + g], Vs[kb * 8 + 4 + t][nf * 8 + g]};
        mma_tf32(o[nf], pa, bfr);
      }
    }
  }

  // reduce l over the quad (lanes sharing g)
  l0 += __shfl_xor_sync(0xffffffffu, l0, 1);
  l0 += __shfl_xor_sync(0xffffffffu, l0, 2);
  l1 += __shfl_xor_sync(0xffffffffu, l1, 1);
  l1 += __shfl_xor_sync(0xffffffffu, l1, 2);

  float gate0 = g_gates[(b * cN + row0) * cH + h];
  float gate1 = g_gates[(b * cN + row1) * cH + h];
  float inv0 = gate0 / l0, inv1 = gate1 / l1;
  #pragma unroll
  for (int nf = 0; nf < 8; nf++) {
    int dcol = h * 64 + nf * 8 + 2 * t;
    g_o[(size_t)(b * cN + row0) * cD + dcol]     = f2tf_f(o[nf][0] * inv0);
    g_o[(size_t)(b * cN + row0) * cD + dcol + 1] = f2tf_f(o[nf][1] * inv0);
    g_o[(size_t)(b * cN + row1) * cD + dcol]     = f2tf_f(o[nf][2] * inv1);
    g_o[(size_t)(b * cN + row1) * cD + dcol + 1] = f2tf_f(o[nf][3] * inv1);
  }
}

// ---------------- glu: ffa = tf32(gelu_exact(gate) * a) ----------------
__global__ void k_glu() {
  int i = blockIdx.x * 256 + threadIdx.x;
  if (i >= cRows * cDff) return;
  int row = i / cDff, c = i - row * cDff;
  float a = g_tmp[(size_t)row * 2 * cDff + c];
  float g = g_tmp[(size_t)row * 2 * cDff + cDff + c];
  float ge = 0.5f * g * (1.f + erff(g * 0.7071067811865476f));
  g_ffa[(size_t)row * cDffP + c] = f2tf_f(ge * a);
}

// ---------------- xcat = tf32([x, skip]) ----------------
__global__ void k_concat(const float* __restrict__ skip) {
  int i = blockIdx.x * 256 + threadIdx.x;
  if (i >= cRows * 2 * cD) return;
  int row = i >> 11, c = i & 2047;
  float v = (c < 1024) ? g_x[(size_t)row * cD + c] : skip[(size_t)row * cD + c - 1024];
  g_xcat[i] = f2tf_f(v);
}

// ---------------- final norm ----------------
__global__ void k_final(const float* __restrict__ gamma, float* __restrict__ out) {
  int row = blockIdx.x;
  int tid = threadIdx.x;
  float4 v = ((const float4*)(g_x + (size_t)row * cD))[tid];
  float s2 = v.x*v.x + v.y*v.y + v.z*v.z + v.w*v.w;
  #pragma unroll
  for (int off = 16; off > 0; off >>= 1)
    s2 += __shfl_xor_sync(0xffffffffu, s2, off);
  __shared__ float ws2[8];
  __shared__ float sscale;
  if ((tid & 31) == 0) ws2[tid >> 5] = s2;
  __syncthreads();
  if (tid == 0) {
    float t2 = 0.f;
    for (int w = 0; w < 8; w++) t2 += ws2[w];
    sscale = 32.f / fmaxf(sqrtf(t2), 1e-12f);
  }
  __syncthreads();
  float sc = sscale;
  int d = tid * 4;
  float4 o;
  o.x = v.x * sc * (gamma[d + 0] + 1.f);
  o.y = v.y * sc * (gamma[d + 1] + 1.f);
  o.z = v.z * sc * (gamma[d + 2] + 1.f);
  o.w = v.w * sc * (gamma[d + 3] + 1.f);
  ((float4*)(out + (size_t)row * cD))[tid] = o;
}

// ---------------- host launcher ----------------
extern "C" void kernel_launch(void* const* d_in, const int* in_sizes, int n_in,
                              void* d_out, int out_size) {
  const float* in_x  = (const float*)d_in[0];
  const float* times = (const float*)d_in[1];
  const float* rf    = (const float*)d_in[2];
  const float* fw    = (const float*)d_in[3];
  const float* tw    = (const float*)d_in[4];
  const float* tb    = (const float*)d_in[5];
  const float* skw   = (const float*)d_in[6];
  const float* afw   = (const float*)d_in[7];
  const float* afb   = (const float*)d_in[8];
  const float* aaw   = (const float*)d_in[9];
  const float* aab   = (const float*)d_in[10];
  const float* qkvw  = (const float*)d_in[11];
  const float* gw    = (const float*)d_in[12];
  const float* ow    = (const float*)d_in[13];
  const float* ffw   = (const float*)d_in[14];
  const float* ffb   = (const float*)d_in[15];
  const float* faw   = (const float*)d_in[16];
  const float* fab   = (const float*)d_in[17];
  const float* w1    = (const float*)d_in[18];
  const float* b1    = (const float*)d_in[19];
  const float* w2    = (const float*)d_in[20];
  const float* b2    = (const float*)d_in[21];
  const float* gamma = (const float*)d_in[22];
  float* out = (float*)d_out;

  cudaFuncSetAttribute(k_gemm, cudaFuncAttributeMaxDynamicSharedMemorySize,
                       GEMM_SMEM_BYTES);

  float *px, *pxc, *pqkv, *po, *ptmp, *pffa, *pxcat, *pskip, *paf, *pff, *paa, *pfa;
  float *pwq, *pwo, *pw1, *pw2, *pws;
  cudaGetSymbolAddress((void**)&px,    g_x);
  cudaGetSymbolAddress((void**)&pxc,   g_xc);
  cudaGetSymbolAddress((void**)&pqkv,  g_qkv);
  cudaGetSymbolAddress((void**)&po,    g_o);
  cudaGetSymbolAddress((void**)&ptmp,  g_tmp);
  cudaGetSymbolAddress((void**)&pffa,  g_ffa);
  cudaGetSymbolAddress((void**)&pxcat, g_xcat);
  cudaGetSymbolAddress((void**)&pskip, g_skip);
  cudaGetSymbolAddress((void**)&paf,   g_attn_film);
  cudaGetSymbolAddress((void**)&pff,   g_ff_film);
  cudaGetSymbolAddress((void**)&paa,   g_attn_adaz);
  cudaGetSymbolAddress((void**)&pfa,   g_ff_adaz);
  cudaGetSymbolAddress((void**)&pwq,   g_wq);
  cudaGetSymbolAddress((void**)&pwo,   g_wo);
  cudaGetSymbolAddress((void**)&pw1,   g_w1);
  cudaGetSymbolAddress((void**)&pw2,   g_w2);
  cudaGetSymbolAddress((void**)&pws,   g_ws);

  // pre-round GEMM weights to tf32
  {
    int nq = cL * cD * 3 * cD, no = cL * cD * cD, n1 = cL * cD * 2 * cDff,
        n2 = cL * cDff * cD, ns = 3 * 2 * cD * cD;
    k_round<<<(nq / 4 + 255) / 256, 256>>>(pwq, qkvw, nq);
    k_round<<<(no / 4 + 255) / 256, 256>>>(pwo, ow, no);
    k_round<<<(n1 / 4 + 255) / 256, 256>>>(pw1, w1, n1);
    k_round<<<(n2 / 4 + 255) / 256, 256>>>(pw2, w2, n2);
    k_round<<<(ns / 4 + 255) / 256, 256>>>(pws, skw, ns);
  }

  k_copy<<<(cRows * cD) / 256, 256>>>(px, in_x, cRows * cD);
  k_cond<<<dim3(cDc / 256, cB), 256>>>(times, fw, tw, tb);
  k_proj<<<dim3(24, cL), 256>>>(afw, afb, ffw, ffb, aaw, aab, faw, fab);

  for (int l = 0; l < cL; l++) {
    if (l < 3) {
      k_copy<<<(cRows * cD) / 256, 256>>>(pskip + (size_t)l * cRows * cD, px, cRows * cD);
    } else {
      k_concat<<<(cRows * 2 * cD) / 256, 256>>>(pskip + (size_t)(5 - l) * cRows * cD);
      k_gemm<<<dim3(8, 16), 256, GEMM_SMEM_BYTES>>>(
          pxcat, pws + (size_t)(l - 3) * 2048 * 1024, nullptr, px,
          nullptr, nullptr, cRows, 1024, 2048, 2048);
    }
    // attention block
    k_lnfilm<<<cRows, 256>>>(paf + (size_t)l * cB * 2 * cD);
    k_gemm<<<dim3(24, 16), 256, GEMM_SMEM_BYTES>>>(
        pxc, pwq + (size_t)l * 1024 * 3072, nullptr, pqkv,
        nullptr, nullptr, cRows, 3072, 1024, 1024);
    if (l == 0) k_savevr<<<(cRows * cD) / 256, 256>>>();
    k_rope<<<(cRows * cH * 32) / 256, 256>>>(rf);
    k_gates<<<(cRows * cH) / 256, 256>>>(gw + (size_t)l * 1024 * 16);
    k_attn<<<dim3(16, 32), 128>>>(l > 0 ? 1 : 0);
    // out proj fused with residual * adaz
    k_gemm<<<dim3(8, 16), 256, GEMM_SMEM_BYTES>>>(
        po, pwo + (size_t)l * 1024 * 1024, nullptr, px,
        px, paa + (size_t)l * cB * cD, cRows, 1024, 1024, 1024);
    // feed-forward block
    k_lnfilm<<<cRows, 256>>>(pff + (size_t)l * cB * 2 * cD);
    k_gemm<<<dim3(43, 16), 256, GEMM_SMEM_BYTES>>>(
        pxc, pw1 + (size_t)l * 1024 * (2 * cDff),
        b1 + (size_t)l * (2 * cDff), ptmp,
        nullptr, nullptr, cRows, 2 * cDff, 1024, 1024);
    k_glu<<<(cRows * cDff + 255) / 256, 256>>>();
    // ff2 fused with residual * adaz
    k_gemm<<<dim3(8, 16), 256, GEMM_SMEM_BYTES>>>(
        pffa, pw2 + (size_t)l * cDff * 1024,
        b2 + (size_t)l * 1024, px,
        px, pfa + (size_t)l * cB * cD, cRows, 1024, cDff, cDffP);
  }
  k_final<<<cRows, 256>>>(gamma, out);
}

// round 7
// speedup vs baseline: 3.1383x; 1.0182x over previous
#include <cuda_runtime.h>
#include <math.h>

// ---------------- problem constants ----------------
constexpr int cB   = 2;
constexpr int cN   = 1024;
constexpr int cD   = 1024;
constexpr int cL   = 6;
constexpr int cH   = 16;
constexpr int cDff = 2730;
constexpr int cDffP = 2732;    // padded (multiple of 4 -> 16B-aligned rows)
constexpr int cDc  = 4096;
constexpr int cRows = cB * cN; // 2048

// ---------------- device scratch (static, allocation-free, zero-initialized) ----------------
__device__ float g_cond[cB * cDc];
__device__ float g_attn_film[cL * cB * 2 * cD];
__device__ float g_ff_film[cL * cB * 2 * cD];
__device__ float g_attn_adaz[cL * cB * cD];
__device__ float g_ff_adaz[cL * cB * cD];
__device__ __align__(16) float g_xc[cRows * cD];
__device__ __align__(16) float g_qkv[cRows * 3 * cD];
__device__ __align__(16) float g_vr[cRows * cD];
__device__ __align__(16) float g_o[cRows * cD];
__device__ __align__(16) float g_tmp[cRows * 2 * cDff];
__device__ __align__(16) float g_ffa[cRows * cDffP + 64];
__device__ __align__(16) float g_xb[3][cRows * cD];    // rotating x buffers
__device__ __align__(16) float g_xcat[cRows * 2 * cD];
__device__ float g_gates[cRows * cH];
__device__ float2 g_cs[cN * 32];                       // rope cos/sin table

// pre-rounded (tf32) weights
__device__ __align__(16) float g_wq[cL * cD * 3 * cD];
__device__ __align__(16) float g_wo[cL * cD * cD];
__device__ __align__(16) float g_w1[cL * cD * 2 * cDff];
__device__ __align__(16) float g_w2[cL * cDff * cD];
__device__ __align__(16) float g_ws[3 * 2 * cD * cD];

__device__ __forceinline__ float f2tf_f(float x) {
  unsigned u;
  asm("cvt.rna.tf32.f32 %0, %1;" : "=r"(u) : "f"(x));
  return __uint_as_float(u);
}
__device__ __forceinline__ unsigned f2tf_u(float x) {
  unsigned u;
  asm("cvt.rna.tf32.f32 %0, %1;" : "=r"(u) : "f"(x));
  return u;
}

// ---------------- utility ----------------
__global__ void k_round(float* __restrict__ dst, const float* __restrict__ src, int n) {
  int i = (blockIdx.x * 256 + threadIdx.x) * 4;
  if (i < n) {
    float4 v = *(const float4*)(src + i);
    float4 o = {f2tf_f(v.x), f2tf_f(v.y), f2tf_f(v.z), f2tf_f(v.w)};
    *(float4*)(dst + i) = o;
  }
}

__global__ void k_sincos(const float* __restrict__ rf) {
  int i = blockIdx.x * 256 + threadIdx.x;
  if (i >= cN * 32) return;
  int n = i >> 5, p = i & 31;
  float f = rf[n * 64 + 2 * p];
  float s, c;
  sincosf(f, &s, &c);
  g_cs[i] = make_float2(c, s);
}

// ---------------- cond = silu(fourier @ tcond_w + b) ----------------
__global__ void k_cond(const float* __restrict__ times, const float* __restrict__ fw,
                       const float* __restrict__ tw, const float* __restrict__ tb) {
  __shared__ float fs[1025];
  int b = blockIdx.y;
  float t = times[b];
  for (int i = threadIdx.x; i < 1025; i += 256) {
    if (i == 0)        fs[0] = t;
    else if (i <= 512) fs[i] = sinf(6.283185307179586f * t * fw[i - 1]);
    else               fs[i] = cosf(6.283185307179586f * t * fw[i - 513]);
  }
  __syncthreads();
  int j = blockIdx.x * 256 + threadIdx.x;
  float acc = tb[j];
  for (int k = 0; k < 1025; k++) acc += fs[k] * tw[k * cDc + j];
  g_cond[b * cDc + j] = acc / (1.f + expf(-acc));
}

// ---------------- all cond projections ----------------
__global__ void k_proj(const float* __restrict__ afw, const float* __restrict__ afb,
                       const float* __restrict__ ffw, const float* __restrict__ ffb,
                       const float* __restrict__ aaw, const float* __restrict__ aab,
                       const float* __restrict__ faw, const float* __restrict__ fab) {
  __shared__ float cs0[cDc], cs1[cDc];
  int l = blockIdx.y;
  for (int i = threadIdx.x; i < cDc; i += 256) {
    cs0[i] = g_cond[i];
    cs1[i] = g_cond[cDc + i];
  }
  __syncthreads();
  int o = blockIdx.x * 256 + threadIdx.x;
  const float* W; const float* bias; float* out; int cols; int c; bool sig = false;
  if (o < 2048)      { c = o;        cols = 2048; W = afw + (size_t)l*cDc*2048; bias = afb + l*2048; out = g_attn_film + (size_t)l*cB*2048; }
  else if (o < 4096) { c = o - 2048; cols = 2048; W = ffw + (size_t)l*cDc*2048; bias = ffb + l*2048; out = g_ff_film   + (size_t)l*cB*2048; }
  else if (o < 5120) { c = o - 4096; cols = 1024; W = aaw + (size_t)l*cDc*1024; bias = aab + l*1024; out = g_attn_adaz + (size_t)l*cB*1024; sig = true; }
  else               { c = o - 5120; cols = 1024; W = faw + (size_t)l*cDc*1024; bias = fab + l*1024; out = g_ff_adaz   + (size_t)l*cB*1024; sig = true; }
  float acc0 = bias[c], acc1 = bias[c];
  #pragma unroll 8
  for (int k = 0; k < cDc; k++) {
    float w = W[(size_t)k * cols + c];
    acc0 += cs0[k] * w;
    acc1 += cs1[k] * w;
  }
  if (sig) { acc0 = 1.f / (1.f + expf(-acc0)); acc1 = 1.f / (1.f + expf(-acc1)); }
  out[c] = acc0;
  out[cols + c] = acc1;
}

// ---------------- LN + FiLM (src param; emits tf32-rounded xc) ----------------
__global__ void k_lnfilm(const float* __restrict__ film, const float* __restrict__ src) {
  int row = blockIdx.x;
  int b = row >> 10;
  int tid = threadIdx.x;
  float4 v = ((const float4*)(src + (size_t)row * cD))[tid];
  float s  = v.x + v.y + v.z + v.w;
  float s2 = v.x*v.x + v.y*v.y + v.z*v.z + v.w*v.w;
  #pragma unroll
  for (int off = 16; off > 0; off >>= 1) {
    s  += __shfl_xor_sync(0xffffffffu, s,  off);
    s2 += __shfl_xor_sync(0xffffffffu, s2, off);
  }
  __shared__ float ws[8], ws2[8];
  __shared__ float smu, srstd;
  if ((tid & 31) == 0) { ws[tid >> 5] = s; ws2[tid >> 5] = s2; }
  __syncthreads();
  if (tid == 0) {
    float t1 = 0.f, t2 = 0.f;
    for (int w = 0; w < 8; w++) { t1 += ws[w]; t2 += ws2[w]; }
    float mu = t1 * (1.f / cD);
    float var = t2 * (1.f / cD) - mu * mu;
    smu = mu; srstd = rsqrtf(var + 1e-5f);
  }
  __syncthreads();
  float mu = smu, rs = srstd;
  const float* fg = film + b * 2 * cD;
  int d = tid * 4;
  float4 o;
  o.x = f2tf_f((v.x - mu) * rs * (fg[d+0] + 1.f) + fg[cD + d + 0]);
  o.y = f2tf_f((v.y - mu) * rs * (fg[d+1] + 1.f) + fg[cD + d + 1]);
  o.z = f2tf_f((v.z - mu) * rs * (fg[d+2] + 1.f) + fg[cD + d + 2]);
  o.w = f2tf_f((v.w - mu) * rs * (fg[d+3] + 1.f) + fg[cD + d + 3]);
  ((float4*)(g_xc + (size_t)row * cD))[tid] = o;
}

// ---------------- tf32 tensor-core GEMM, cp.async 3-stage, templated ----------------
// MODE 0: C = A@W (+bias)
// MODE 1: C = resid + (A@W + bias) * adaz
// MODE 2: qkv epilogue — rope on q/k cols, v-save (l0) / v-mix on v cols
__device__ __forceinline__ void mma_tf32(float (&c)[4], const unsigned (&a)[4],
                                         const unsigned (&b)[2]) {
  asm volatile(
      "mma.sync.aligned.m16n8k8.row.col.f32.tf32.tf32.f32 "
      "{%0,%1,%2,%3}, {%4,%5,%6,%7}, {%8,%9}, {%0,%1,%2,%3};\n"
      : "+f"(c[0]), "+f"(c[1]), "+f"(c[2]), "+f"(c[3])
      : "r"(a[0]), "r"(a[1]), "r"(a[2]), "r"(a[3]), "r"(b[0]), "r"(b[1]));
}
__device__ __forceinline__ void cpa16(void* smem, const void* gmem, bool valid) {
  unsigned sa = (unsigned)__cvta_generic_to_shared(smem);
  int sz = valid ? 16 : 0;
  asm volatile("cp.async.cg.shared.global [%0], [%1], 16, %2;\n"
               :: "r"(sa), "l"(gmem), "r"(sz) : "memory");
}

constexpr int GA_STRIDE = 20;
constexpr int GA_STAGE = 128 * GA_STRIDE;
constexpr int smem_bytes(int BN) {
  return 3 * (GA_STAGE + 16 * (BN == 128 ? 136 : 72)) * 4;
}

template <int BN, int MODE>
__global__ __launch_bounds__(256, 2) void k_gemm(
    const float* __restrict__ A, const float* __restrict__ W,
    const float* __restrict__ bias, float* __restrict__ C,
    const float* __restrict__ resid, const float* __restrict__ adaz,
    int M, int N, int K, int lda, int l0) {
  constexpr int GBS = (BN == 128) ? 136 : 72;
  constexpr int GB_STAGE = 16 * GBS;
  constexpr int MI = (BN == 128) ? 4 : 2;
  constexpr int BITER = (BN == 128) ? 2 : 1;
  extern __shared__ unsigned dsm[];
  int tid = threadIdx.x;
  int warp = tid >> 5, lane = tid & 31;
  int wm = (BN == 128) ? (warp >> 2) : (warp >> 1);
  int wn = (BN == 128) ? (warp & 3) : (warp & 1);
  int g = lane >> 2, t = lane & 3;
  int rb = blockIdx.y * 128, cb = blockIdx.x * BN;
  float acc[MI][4][4] = {};
  int nk = (K + 15) / 16;

  auto load_stage = [&](int buf, int k0) {
    unsigned* sA = dsm + buf * GA_STAGE;
    unsigned* sB = dsm + 3 * GA_STAGE + buf * GB_STAGE;
    #pragma unroll
    for (int it = 0; it < 2; it++) {
      int idx = tid + it * 256;
      int m = idx >> 2, kg = idx & 3;
      int gk = k0 + kg * 4;
      cpa16(&sA[m * GA_STRIDE + kg * 4], A + (size_t)(rb + m) * lda + gk, true);
    }
    #pragma unroll
    for (int it = 0; it < BITER; it++) {
      int idx = tid + it * 256;
      int kk = idx / (BN / 4), n4 = idx % (BN / 4);
      int gk = k0 + kk, gn = cb + n4 * 4;
      bool ok = (gk < K) && (gn < N);
      cpa16(&sB[kk * GBS + n4 * 4], W + (size_t)gk * N + gn, ok);
    }
    asm volatile("cp.async.commit_group;\n" ::: "memory");
  };

  load_stage(0, 0);
  if (nk > 1) load_stage(1, 16);
  for (int it = 0; it < nk; it++) {
    if (it + 2 <= nk) {
      asm volatile("cp.async.wait_group 1;\n" ::: "memory");
    } else {
      asm volatile("cp.async.wait_group 0;\n" ::: "memory");
    }
    __syncthreads();
    if (it + 2 < nk) load_stage((it + 2) % 3, (it + 2) * 16);
    int buf = it % 3;
    unsigned* sA = dsm + buf * GA_STAGE;
    unsigned* sB = dsm + 3 * GA_STAGE + buf * GB_STAGE;
    #pragma unroll
    for (int ks = 0; ks < 2; ks++) {
      int kb = ks * 8;
      unsigned a[MI][4], b[4][2];
      #pragma unroll
      for (int i = 0; i < MI; i++) {
        int mr = wm * (MI * 16) + i * 16;
        a[i][0] = sA[(mr + g) * GA_STRIDE + kb + t];
        a[i][1] = sA[(mr + 8 + g) * GA_STRIDE + kb + t];
        a[i][2] = sA[(mr + g) * GA_STRIDE + kb + 4 + t];
        a[i][3] = sA[(mr + 8 + g) * GA_STRIDE + kb + 4 + t];
      }
      #pragma unroll
      for (int j = 0; j < 4; j++) {
        int nc = wn * 32 + j * 8;
        b[j][0] = sB[(kb + t) * GBS + nc + g];
        b[j][1] = sB[(kb + 4 + t) * GBS + nc + g];
      }
      #pragma unroll
      for (int i = 0; i < MI; i++)
        #pragma unroll
        for (int j = 0; j < 4; j++)
          mma_tf32(acc[i][j], a[i], b[j]);
    }
  }

  #pragma unroll
  for (int i = 0; i < MI; i++) {
    int r0 = rb + wm * (MI * 16) + i * 16 + g;
    int bidx = r0 >> 10;
    #pragma unroll
    for (int j = 0; j < 4; j++) {
      int c0 = cb + wn * 32 + j * 8 + 2 * t;
      if (c0 >= N) continue;
      float v00 = acc[i][j][0], v01 = acc[i][j][1];
      float v10 = acc[i][j][2], v11 = acc[i][j][3];
      if constexpr (MODE == 0 || MODE == 1) {
        float b0 = bias ? bias[c0] : 0.f;
        float b1 = bias ? bias[c0 + 1] : 0.f;
        v00 += b0; v01 += b1; v10 += b0; v11 += b1;
        if constexpr (MODE == 1) {
          const float* az = adaz + bidx * N;
          float a0 = az[c0], a1 = az[c0 + 1];
          v00 = resid[(size_t)r0 * N + c0]       + v00 * a0;
          v01 = resid[(size_t)r0 * N + c0 + 1]   + v01 * a1;
          v10 = resid[(size_t)(r0+8) * N + c0]   + v10 * a0;
          v11 = resid[(size_t)(r0+8) * N + c0+1] + v11 * a1;
        }
      } else {  // MODE 2: qkv
        if (c0 < 2048) {
          int p = (c0 & 63) >> 1;
          float2 csa = g_cs[(r0 & 1023) * 32 + p];
          float2 csb = g_cs[((r0 + 8) & 1023) * 32 + p];
          float o00 = v00 * csa.x - v01 * csa.y;
          float o01 = v01 * csa.x + v00 * csa.y;
          float o10 = v10 * csb.x - v11 * csb.y;
          float o11 = v11 * csb.x + v10 * csb.y;
          v00 = o00; v01 = o01; v10 = o10; v11 = o11;
        } else {
          int cv = c0 - 2048;
          if (l0) {
            *(float2*)&g_vr[(size_t)r0 * 1024 + cv]       = make_float2(v00, v01);
            *(float2*)&g_vr[(size_t)(r0 + 8) * 1024 + cv] = make_float2(v10, v11);
          } else {
            float2 w0 = *(const float2*)&g_vr[(size_t)r0 * 1024 + cv];
            float2 w1 = *(const float2*)&g_vr[(size_t)(r0 + 8) * 1024 + cv];
            v00 = 0.5f * (v00 + w0.x); v01 = 0.5f * (v01 + w0.y);
            v10 = 0.5f * (v10 + w1.x); v11 = 0.5f * (v11 + w1.y);
          }
        }
      }
      *(float2*)&C[(size_t)r0 * N + c0]       = make_float2(v00, v01);
      *(float2*)&C[(size_t)(r0 + 8) * N + c0] = make_float2(v10, v11);
    }
  }
}

// ---------------- gates = sigmoid(xc @ gates_w) ----------------
__global__ void k_gates(const float* __restrict__ gw) {
  int i = blockIdx.x * 256 + threadIdx.x;
  if (i >= cRows * cH) return;
  int row = i >> 4, h = i & 15;
  const float* xr = g_xc + (size_t)row * cD;
  float acc = 0.f;
  #pragma unroll 4
  for (int k = 0; k < cD; k++) acc += xr[k] * gw[k * cH + h];
  g_gates[i] = 1.f / (1.f + expf(-acc));
}

// ---------------- tensor-core flash attention ----------------
// p = exp(50*tanh(s/50)); tanh via Pade(3,2) -> 2 MUFU (rcp + ex2).
__device__ __forceinline__ float softcap_exp(float s) {
  float z = s * 0.02f;
  float z2 = z * z;
  float num = s * (15.f + z2);            // 50*z*(15+z2)
  float den = 15.f + 6.f * z2;
  return __expf(__fdividef(num, den));
}

__global__ __launch_bounds__(128) void k_attn() {
  __shared__ unsigned KP[64][68];
  __shared__ unsigned Vs[64][68];
  int qt = (int)gridDim.x - 1 - (int)blockIdx.x;
  int bh = blockIdx.y;
  int b = bh >> 4, h = bh & 15;
  int q0 = qt * 64;
  int tid = threadIdx.x, warp = tid >> 5, lane = tid & 31;
  int g = lane >> 2, t = lane & 3;
  int mr = warp * 16;

  for (int idx = tid; idx < 64 * 64; idx += 128) {
    int r = idx >> 6, d = idx & 63;
    Vs[r][d] = f2tf_u(g_qkv[(size_t)(b * cN + q0 + r) * 3072 + h * 64 + d]);
  }
  __syncthreads();
  unsigned qa[8][4];
  #pragma unroll
  for (int kb = 0; kb < 8; kb++) {
    qa[kb][0] = Vs[mr + g][kb * 8 + t];
    qa[kb][1] = Vs[mr + 8 + g][kb * 8 + t];
    qa[kb][2] = Vs[mr + g][kb * 8 + 4 + t];
    qa[kb][3] = Vs[mr + 8 + g][kb * 8 + 4 + t];
  }

  float o[8][4] = {};
  float l0 = 0.f, l1 = 0.f;
  int row0 = q0 + mr + g, row1 = row0 + 8;

  for (int kt = 0; kt <= qt; kt++) {
    int k0 = kt * 64;
    __syncthreads();
    for (int idx = tid; idx < 64 * 64; idx += 128) {
      int r = idx >> 6, d = idx & 63;
      size_t base = (size_t)(b * cN + k0 + r) * 3072 + h * 64 + d;
      KP[r][d] = f2tf_u(g_qkv[base + 1024]);
      Vs[r][d] = f2tf_u(g_qkv[base + 2048]);   // v already mixed by qkv epilogue
    }
    __syncthreads();

    float s[8][4] = {};
    #pragma unroll
    for (int kb = 0; kb < 8; kb++) {
      #pragma unroll
      for (int nf = 0; nf < 8; nf++) {
        unsigned bfr[2] = {KP[nf * 8 + g][kb * 8 + t], KP[nf * 8 + g][kb * 8 + 4 + t]};
        mma_tf32(s[nf], qa[kb], bfr);
      }
    }

    float p[8][4];
    #pragma unroll
    for (int nf = 0; nf < 8; nf++) {
      int c0 = k0 + nf * 8 + 2 * t, c1 = c0 + 1;
      float p0 = (c0 <= row0) ? softcap_exp(s[nf][0] * 0.125f) : 0.f;
      float p1 = (c1 <= row0) ? softcap_exp(s[nf][1] * 0.125f) : 0.f;
      float p2 = (c0 <= row1) ? softcap_exp(s[nf][2] * 0.125f) : 0.f;
      float p3 = (c1 <= row1) ? softcap_exp(s[nf][3] * 0.125f) : 0.f;
      p[nf][0] = p0; p[nf][1] = p1; p[nf][2] = p2; p[nf][3] = p3;
      l0 += p0 + p1;
      l1 += p2 + p3;
    }

    __syncthreads();
    #pragma unroll
    for (int nf = 0; nf < 8; nf++) {
      KP[mr + g][nf * 8 + 2 * t]     = f2tf_u(p[nf][0]);
      KP[mr + g][nf * 8 + 2 * t + 1] = f2tf_u(p[nf][1]);
      KP[mr + 8 + g][nf * 8 + 2 * t]     = f2tf_u(p[nf][2]);
      KP[mr + 8 + g][nf * 8 + 2 * t + 1] = f2tf_u(p[nf][3]);
    }
    __syncthreads();

    #pragma unroll
    for (int kb = 0; kb < 8; kb++) {
      unsigned pa[4] = {KP[mr + g][kb * 8 + t], KP[mr + 8 + g][kb * 8 + t],
                        KP[mr + g][kb * 8 + 4 + t], KP[mr + 8 + g][kb * 8 + 4 + t]};
      #pragma unroll
      for (int nf = 0; nf < 8; nf++) {
        unsigned bfr[2] = {Vs[kb * 8 + t][nf * 8 + g], Vs[kb * 8 + 4 + t][nf * 8 + g]};
        mma_tf32(o[nf], pa, bfr);
      }
    }
  }

  l0 += __shfl_xor_sync(0xffffffffu, l0, 1);
  l0 += __shfl_xor_sync(0xffffffffu, l0, 2);
  l1 += __shfl_xor_sync(0xffffffffu, l1, 1);
  l1 += __shfl_xor_sync(0xffffffffu, l1, 2);

  float gate0 = g_gates[(b * cN + row0) * cH + h];
  float gate1 = g_gates[(b * cN + row1) * cH + h];
  float inv0 = gate0 / l0, inv1 = gate1 / l1;
  #pragma unroll
  for (int nf = 0; nf < 8; nf++) {
    int dcol = h * 64 + nf * 8 + 2 * t;
    g_o[(size_t)(b * cN + row0) * cD + dcol]     = f2tf_f(o[nf][0] * inv0);
    g_o[(size_t)(b * cN + row0) * cD + dcol + 1] = f2tf_f(o[nf][1] * inv0);
    g_o[(size_t)(b * cN + row1) * cD + dcol]     = f2tf_f(o[nf][2] * inv1);
    g_o[(size_t)(b * cN + row1) * cD + dcol + 1] = f2tf_f(o[nf][3] * inv1);
  }
}

// ---------------- glu: ffa = tf32(gelu_exact(gate) * a) ----------------
__global__ void k_glu() {
  int i = blockIdx.x * 256 + threadIdx.x;
  if (i >= cRows * cDff) return;
  int row = i / cDff, c = i - row * cDff;
  float a = g_tmp[(size_t)row * 2 * cDff + c];
  float g = g_tmp[(size_t)row * 2 * cDff + cDff + c];
  float ge = 0.5f * g * (1.f + erff(g * 0.7071067811865476f));
  g_ffa[(size_t)row * cDffP + c] = f2tf_f(ge * a);
}

// ---------------- xcat = tf32([x, skip]) ----------------
__global__ void k_concat(const float* __restrict__ x, const float* __restrict__ skip) {
  int i = blockIdx.x * 256 + threadIdx.x;
  if (i >= cRows * 2 * cD) return;
  int row = i >> 11, c = i & 2047;
  float v = (c < 1024) ? x[(size_t)row * cD + c] : skip[(size_t)row * cD + c - 1024];
  g_xcat[i] = f2tf_f(v);
}

// ---------------- final norm ----------------
__global__ void k_final(const float* __restrict__ gamma, const float* __restrict__ src,
                        float* __restrict__ out) {
  int row = blockIdx.x;
  int tid = threadIdx.x;
  float4 v = ((const float4*)(src + (size_t)row * cD))[tid];
  float s2 = v.x*v.x + v.y*v.y + v.z*v.z + v.w*v.w;
  #pragma unroll
  for (int off = 16; off > 0; off >>= 1)
    s2 += __shfl_xor_sync(0xffffffffu, s2, off);
  __shared__ float ws2[8];
  __shared__ float sscale;
  if ((tid & 31) == 0) ws2[tid >> 5] = s2;
  __syncthreads();
  if (tid == 0) {
    float t2 = 0.f;
    for (int w = 0; w < 8; w++) t2 += ws2[w];
    sscale = 32.f / fmaxf(sqrtf(t2), 1e-12f);
  }
  __syncthreads();
  float sc = sscale;
  int d = tid * 4;
  float4 o;
  o.x = v.x * sc * (gamma[d + 0] + 1.f);
  o.y = v.y * sc * (gamma[d + 1] + 1.f);
  o.z = v.z * sc * (gamma[d + 2] + 1.f);
  o.w = v.w * sc * (gamma[d + 3] + 1.f);
  ((float4*)(out + (size_t)row * cD))[tid] = o;
}

// ---------------- host launcher ----------------
extern "C" void kernel_launch(void* const* d_in, const int* in_sizes, int n_in,
                              void* d_out, int out_size) {
  const float* in_x  = (const float*)d_in[0];
  const float* times = (const float*)d_in[1];
  const float* rf    = (const float*)d_in[2];
  const float* fw    = (const float*)d_in[3];
  const float* tw    = (const float*)d_in[4];
  const float* tb    = (const float*)d_in[5];
  const float* skw   = (const float*)d_in[6];
  const float* afw   = (const float*)d_in[7];
  const float* afb   = (const float*)d_in[8];
  const float* aaw   = (const float*)d_in[9];
  const float* aab   = (const float*)d_in[10];
  const float* qkvw  = (const float*)d_in[11];
  const float* gw    = (const float*)d_in[12];
  const float* ow    = (const float*)d_in[13];
  const float* ffw   = (const float*)d_in[14];
  const float* ffb   = (const float*)d_in[15];
  const float* faw   = (const float*)d_in[16];
  const float* fab   = (const float*)d_in[17];
  const float* w1    = (const float*)d_in[18];
  const float* b1    = (const float*)d_in[19];
  const float* w2    = (const float*)d_in[20];
  const float* b2    = (const float*)d_in[21];
  const float* gamma = (const float*)d_in[22];
  float* out = (float*)d_out;

  cudaFuncSetAttribute(k_gemm<128,0>, cudaFuncAttributeMaxDynamicSharedMemorySize, smem_bytes(128));
  cudaFuncSetAttribute(k_gemm<128,2>, cudaFuncAttributeMaxDynamicSharedMemorySize, smem_bytes(128));
  cudaFuncSetAttribute(k_gemm<64,0>,  cudaFuncAttributeMaxDynamicSharedMemorySize, smem_bytes(64));
  cudaFuncSetAttribute(k_gemm<64,1>,  cudaFuncAttributeMaxDynamicSharedMemorySize, smem_bytes(64));

  float *pxc, *pqkv, *po, *ptmp, *pffa, *pxcat, *pxb, *paf, *pff, *paa, *pfa;
  float *pwq, *pwo, *pw1, *pw2, *pws;
  cudaGetSymbolAddress((void**)&pxc,   g_xc);
  cudaGetSymbolAddress((void**)&pqkv,  g_qkv);
  cudaGetSymbolAddress((void**)&po,    g_o);
  cudaGetSymbolAddress((void**)&ptmp,  g_tmp);
  cudaGetSymbolAddress((void**)&pffa,  g_ffa);
  cudaGetSymbolAddress((void**)&pxcat, g_xcat);
  cudaGetSymbolAddress((void**)&pxb,   g_xb);
  cudaGetSymbolAddress((void**)&paf,   g_attn_film);
  cudaGetSymbolAddress((void**)&pff,   g_ff_film);
  cudaGetSymbolAddress((void**)&paa,   g_attn_adaz);
  cudaGetSymbolAddress((void**)&pfa,   g_ff_adaz);
  cudaGetSymbolAddress((void**)&pwq,   g_wq);
  cudaGetSymbolAddress((void**)&pwo,   g_wo);
  cudaGetSymbolAddress((void**)&pw1,   g_w1);
  cudaGetSymbolAddress((void**)&pw2,   g_w2);
  cudaGetSymbolAddress((void**)&pws,   g_ws);

  const size_t XS = (size_t)cRows * cD;
  const float* XB[4] = {in_x, pxb, pxb + XS, pxb + 2 * XS};
  float* XBw[4] = {nullptr, pxb, pxb + XS, pxb + 2 * XS};
  int cur = 0;

  // early launches (qkv gemm lands at launch index 5 for ncu)
  int nq = cL * cD * 3 * cD;
  k_round<<<(nq / 4 + 255) / 256, 256>>>(pwq, qkvw, nq);
  k_cond<<<dim3(cDc / 256, cB), 256>>>(times, fw, tw, tb);
  k_proj<<<dim3(24, cL), 256>>>(afw, afb, ffw, ffb, aaw, aab, faw, fab);
  k_sincos<<<(cN * 32) / 256, 256>>>(rf);

  for (int l = 0; l < cL; l++) {
    if (l >= 3) {
      k_concat<<<(cRows * 2 * cD) / 256, 256>>>(XB[cur], XB[5 - l]);
      k_gemm<64,0><<<dim3(16, 16), 256, smem_bytes(64)>>>(
          pxcat, pws + (size_t)(l - 3) * 2048 * 1024, nullptr, XBw[3],
          nullptr, nullptr, cRows, 1024, 2048, 2048, 0);
      cur = 3;
    }
    // attention block
    k_lnfilm<<<cRows, 256>>>(paf + (size_t)l * cB * 2 * cD, XB[cur]);
    k_gemm<128,2><<<dim3(24, 16), 256, smem_bytes(128)>>>(
        pxc, pwq + (size_t)l * 1024 * 3072, nullptr, pqkv,
        nullptr, nullptr, cRows, 3072, 1024, 1024, l == 0 ? 1 : 0);
    if (l == 0) {
      int no = cL * cD * cD, n1 = cL * cD * 2 * cDff, n2 = cL * cDff * cD,
          ns = 3 * 2 * cD * cD;
      k_round<<<(no / 4 + 255) / 256, 256>>>(pwo, ow, no);
      k_round<<<(n1 / 4 + 255) / 256, 256>>>(pw1, w1, n1);
      k_round<<<(n2 / 4 + 255) / 256, 256>>>(pw2, w2, n2);
      k_round<<<(ns / 4 + 255) / 256, 256>>>(pws, skw, ns);
    }
    k_gates<<<(cRows * cH) / 256, 256>>>(gw + (size_t)l * 1024 * 16);
    k_attn<<<dim3(16, 32), 128>>>();
    int nxt = (l < 3) ? l + 1 : 3;
    k_gemm<64,1><<<dim3(16, 16), 256, smem_bytes(64)>>>(
        po, pwo + (size_t)l * 1024 * 1024, nullptr, XBw[nxt],
        XB[cur], paa + (size_t)l * cB * cD, cRows, 1024, 1024, 1024, 0);
    cur = nxt;
    // feed-forward block
    k_lnfilm<<<cRows, 256>>>(pff + (size_t)l * cB * 2 * cD, XB[cur]);
    k_gemm<128,0><<<dim3(43, 16), 256, smem_bytes(128)>>>(
        pxc, pw1 + (size_t)l * 1024 * (2 * cDff),
        b1 + (size_t)l * (2 * cDff), ptmp,
        nullptr, nullptr, cRows, 2 * cDff, 1024, 1024, 0);
    k_glu<<<(cRows * cDff + 255) / 256, 256>>>();
    k_gemm<64,1><<<dim3(16, 16), 256, smem_bytes(64)>>>(
        pffa, pw2 + (size_t)l * cDff * 1024,
        b2 + (size_t)l * 1024, XBw[cur],
        XB[cur], pfa + (size_t)l * cB * cD, cRows, 1024, cDff, cDffP, 0);
  }
  k_final<<<cRows, 256>>>(gamma, XB[3], out);
}

// round 9
// speedup vs baseline: 3.2875x; 1.0476x over previous
#include <cuda_runtime.h>
#include <math.h>

// ---------------- problem constants ----------------
constexpr int cB   = 2;
constexpr int cN   = 1024;
constexpr int cD   = 1024;
constexpr int cL   = 6;
constexpr int cH   = 16;
constexpr int cDff = 2730;
constexpr int cDffP = 2732;    // padded row stride
constexpr int cDc  = 4096;
constexpr int cRows = cB * cN; // 2048

// ---------------- device scratch ----------------
__device__ float g_cond[cB * cDc];
__device__ float g_attn_film[cL * cB * 2 * cD];
__device__ float g_ff_film[cL * cB * 2 * cD];
__device__ float g_attn_adaz[cL * cB * cD];
__device__ float g_ff_adaz[cL * cB * cD];
__device__ __align__(16) float g_xc[cRows * cD];
__device__ __align__(16) float g_qkv[cRows * 3 * cD];
__device__ __align__(16) float g_vr[cRows * cD];
__device__ __align__(16) float g_o[cRows * cD];
__device__ __align__(16) float g_ffa[cRows * cDffP + 64];
__device__ __align__(16) float g_xb[3][cRows * cD];
__device__ __align__(16) float g_xcat[cRows * 2 * cD];
__device__ float g_gates[cRows * cH];
__device__ float2 g_cs[cN * 32];

__device__ __forceinline__ float f2tf_f(float x) {
  unsigned u;
  asm("cvt.rna.tf32.f32 %0, %1;" : "=r"(u) : "f"(x));
  return __uint_as_float(u);
}
__device__ __forceinline__ unsigned f2tf_u(float x) {
  unsigned u;
  asm("cvt.rna.tf32.f32 %0, %1;" : "=r"(u) : "f"(x));
  return u;
}

__global__ void k_sincos(const float* __restrict__ rf) {
  int i = blockIdx.x * 256 + threadIdx.x;
  if (i >= cN * 32) return;
  int n = i >> 5, p = i & 31;
  float f = rf[n * 64 + 2 * p];
  float s, c;
  sincosf(f, &s, &c);
  g_cs[i] = make_float2(c, s);
}

// ---------------- cond = silu(fourier @ tcond_w + b) ----------------
__global__ void k_cond(const float* __restrict__ times, const float* __restrict__ fw,
                       const float* __restrict__ tw, const float* __restrict__ tb) {
  __shared__ float fs[1025];
  int b = blockIdx.y;
  float t = times[b];
  for (int i = threadIdx.x; i < 1025; i += 256) {
    if (i == 0)        fs[0] = t;
    else if (i <= 512) fs[i] = sinf(6.283185307179586f * t * fw[i - 1]);
    else               fs[i] = cosf(6.283185307179586f * t * fw[i - 513]);
  }
  __syncthreads();
  int j = blockIdx.x * 256 + threadIdx.x;
  float acc = tb[j];
  for (int k = 0; k < 1025; k++) acc += fs[k] * tw[k * cDc + j];
  g_cond[b * cDc + j] = acc / (1.f + expf(-acc));
}

// ---------------- all cond projections ----------------
__global__ void k_proj(const float* __restrict__ afw, const float* __restrict__ afb,
                       const float* __restrict__ ffw, const float* __restrict__ ffb,
                       const float* __restrict__ aaw, const float* __restrict__ aab,
                       const float* __restrict__ faw, const float* __restrict__ fab) {
  __shared__ float cs0[cDc], cs1[cDc];
  int l = blockIdx.y;
  for (int i = threadIdx.x; i < cDc; i += 256) {
    cs0[i] = g_cond[i];
    cs1[i] = g_cond[cDc + i];
  }
  __syncthreads();
  int o = blockIdx.x * 256 + threadIdx.x;
  const float* W; const float* bias; float* out; int cols; int c; bool sig = false;
  if (o < 2048)      { c = o;        cols = 2048; W = afw + (size_t)l*cDc*2048; bias = afb + l*2048; out = g_attn_film + (size_t)l*cB*2048; }
  else if (o < 4096) { c = o - 2048; cols = 2048; W = ffw + (size_t)l*cDc*2048; bias = ffb + l*2048; out = g_ff_film   + (size_t)l*cB*2048; }
  else if (o < 5120) { c = o - 4096; cols = 1024; W = aaw + (size_t)l*cDc*1024; bias = aab + l*1024; out = g_attn_adaz + (size_t)l*cB*1024; sig = true; }
  else               { c = o - 5120; cols = 1024; W = faw + (size_t)l*cDc*1024; bias = fab + l*1024; out = g_ff_adaz   + (size_t)l*cB*1024; sig = true; }
  float acc0 = bias[c], acc1 = bias[c];
  #pragma unroll 8
  for (int k = 0; k < cDc; k++) {
    float w = W[(size_t)k * cols + c];
    acc0 += cs0[k] * w;
    acc1 += cs1[k] * w;
  }
  if (sig) { acc0 = 1.f / (1.f + expf(-acc0)); acc1 = 1.f / (1.f + expf(-acc1)); }
  out[c] = acc0;
  out[cols + c] = acc1;
}

// ---------------- LN + FiLM ----------------
__global__ void k_lnfilm(const float* __restrict__ film, const float* __restrict__ src) {
  int row = blockIdx.x;
  int b = row >> 10;
  int tid = threadIdx.x;
  float4 v = ((const float4*)(src + (size_t)row * cD))[tid];
  float s  = v.x + v.y + v.z + v.w;
  float s2 = v.x*v.x + v.y*v.y + v.z*v.z + v.w*v.w;
  #pragma unroll
  for (int off = 16; off > 0; off >>= 1) {
    s  += __shfl_xor_sync(0xffffffffu, s,  off);
    s2 += __shfl_xor_sync(0xffffffffu, s2, off);
  }
  __shared__ float ws[8], ws2[8];
  __shared__ float smu, srstd;
  if ((tid & 31) == 0) { ws[tid >> 5] = s; ws2[tid >> 5] = s2; }
  __syncthreads();
  if (tid == 0) {
    float t1 = 0.f, t2 = 0.f;
    for (int w = 0; w < 8; w++) { t1 += ws[w]; t2 += ws2[w]; }
    float mu = t1 * (1.f / cD);
    float var = t2 * (1.f / cD) - mu * mu;
    smu = mu; srstd = rsqrtf(var + 1e-5f);
  }
  __syncthreads();
  float mu = smu, rs = srstd;
  const float* fg = film + b * 2 * cD;
  int d = tid * 4;
  float4 o;
  o.x = f2tf_f((v.x - mu) * rs * (fg[d+0] + 1.f) + fg[cD + d + 0]);
  o.y = f2tf_f((v.y - mu) * rs * (fg[d+1] + 1.f) + fg[cD + d + 1]);
  o.z = f2tf_f((v.z - mu) * rs * (fg[d+2] + 1.f) + fg[cD + d + 2]);
  o.w = f2tf_f((v.w - mu) * rs * (fg[d+3] + 1.f) + fg[cD + d + 3]);
  ((float4*)(g_xc + (size_t)row * cD))[tid] = o;
}

// ---------------- tf32 GEMM: cp.async 3-stage + ldmatrix A-frags ----------------
// MODE 0: C = A@W (+bias);  MODE 1: C = resid + (A@W+bias)*adaz
// MODE 2: qkv epilogue (rope/v-save/v-mix);  MODE 3: ff1+GLU fused
__device__ __forceinline__ void mma_tf32(float (&c)[4], const unsigned (&a)[4],
                                         const unsigned (&b)[2]) {
  asm volatile(
      "mma.sync.aligned.m16n8k8.row.col.f32.tf32.tf32.f32 "
      "{%0,%1,%2,%3}, {%4,%5,%6,%7}, {%8,%9}, {%0,%1,%2,%3};\n"
      : "+f"(c[0]), "+f"(c[1]), "+f"(c[2]), "+f"(c[3])
      : "r"(a[0]), "r"(a[1]), "r"(a[2]), "r"(a[3]), "r"(b[0]), "r"(b[1]));
}
__device__ __forceinline__ void ldsm_x4(unsigned (&r)[4], unsigned saddr) {
  asm volatile("ldmatrix.sync.aligned.m8n8.x4.shared.b16 {%0,%1,%2,%3}, [%4];"
               : "=r"(r[0]), "=r"(r[1]), "=r"(r[2]), "=r"(r[3]) : "r"(saddr));
}
__device__ __forceinline__ void cpa16(void* smem, const void* gmem, bool valid) {
  unsigned sa = (unsigned)__cvta_generic_to_shared(smem);
  int sz = valid ? 16 : 0;
  asm volatile("cp.async.cg.shared.global [%0], [%1], 16, %2;\n"
               :: "r"(sa), "l"(gmem), "r"(sz) : "memory");
}
__device__ __forceinline__ void cpa8(void* smem, const void* gmem, bool valid) {
  unsigned sa = (unsigned)__cvta_generic_to_shared(smem);
  int sz = valid ? 8 : 0;
  asm volatile("cp.async.ca.shared.global [%0], [%1], 8, %2;\n"
               :: "r"(sa), "l"(gmem), "r"(sz) : "memory");
}
__device__ __forceinline__ float gelu_e(float g) {
  return 0.5f * g * (1.f + erff(g * 0.7071067811865476f));
}

constexpr int GA_STRIDE = 20;
constexpr int smem_bytes(int BN, int MODE) {
  int bm = (MODE == 3) ? 64 : 128;
  int nb = (MODE == 3) ? 2 : 1;
  int gbs = (BN == 128) ? 136 : 72;
  return 3 * (bm * GA_STRIDE + nb * 16 * gbs) * 4;
}

template <int BN, int MODE>
__global__ __launch_bounds__(256, 2) void k_gemm(
    const float* __restrict__ A, const float* __restrict__ W,
    const float* __restrict__ bias, float* __restrict__ C,
    const float* __restrict__ resid, const float* __restrict__ adaz,
    int M, int N, int K, int lda, int l0) {
  constexpr int BM  = (MODE == 3) ? 64 : 128;
  constexpr int MI  = (MODE == 3) ? 2 : ((BN == 128) ? 4 : 2);
  constexpr int GBS = (BN == 128) ? 136 : 72;
  constexpr int GB_STAGE = 16 * GBS;
  constexpr int NB  = (MODE == 3) ? 2 : 1;
  constexpr int GA_ST = BM * GA_STRIDE;
  extern __shared__ unsigned dsm[];
  unsigned sa_base = (unsigned)__cvta_generic_to_shared(dsm);
  int tid = threadIdx.x;
  int warp = tid >> 5, lane = tid & 31;
  int wm, wn;
  if constexpr (MODE == 3 || BN == 128) { wm = warp >> 2; wn = warp & 3; }
  else { wm = warp >> 1; wn = warp & 1; }
  int g = lane >> 2, t = lane & 3;
  int lrow = lane & 15, lcol = (lane >> 4) << 2;   // ldmatrix lane addressing
  int rb = blockIdx.y * BM, cb = blockIdx.x * BN;
  float acc[NB][MI][4][4] = {};
  int nk = (K + 15) / 16;

  auto load_stage = [&](int buf, int k0) {
    unsigned* sA = dsm + buf * GA_ST;
    unsigned* sB = dsm + 3 * GA_ST + buf * (NB * GB_STAGE);
    #pragma unroll
    for (int it = 0; it < BM / 64; it++) {
      int idx = tid + it * 256;
      int m = idx >> 2, kg = idx & 3;
      cpa16(&sA[m * GA_STRIDE + kg * 4], A + (size_t)(rb + m) * lda + k0 + kg * 4, true);
    }
    #pragma unroll
    for (int it = 0; it < BN / 64; it++) {
      int idx = tid + it * 256;
      int kk = idx / (BN / 4), n4 = idx % (BN / 4);
      int gk = k0 + kk, gn = cb + n4 * 4;
      bool ok = (gk < K) && (gn < N);
      if constexpr (MODE == 3) {
        const float* sa_ = W + (size_t)gk * 5460 + gn;          // a-half
        cpa16(&sB[kk * GBS + n4 * 4], sa_, ok);
        const float* sg_ = W + (size_t)gk * 5460 + 2730 + gn;   // gate-half (8B aligned)
        cpa8(&sB[GB_STAGE + kk * GBS + n4 * 4], sg_, ok);
        cpa8(&sB[GB_STAGE + kk * GBS + n4 * 4 + 2], sg_ + 2, ok && (gn + 2 < N));
      } else {
        cpa16(&sB[kk * GBS + n4 * 4], W + (size_t)gk * N + gn, ok);
      }
    }
    asm volatile("cp.async.commit_group;\n" ::: "memory");
  };

  load_stage(0, 0);
  if (nk > 1) load_stage(1, 16);
  for (int it = 0; it < nk; it++) {
    if (it + 2 <= nk) {
      asm volatile("cp.async.wait_group 1;\n" ::: "memory");
    } else {
      asm volatile("cp.async.wait_group 0;\n" ::: "memory");
    }
    __syncthreads();
    if (it + 2 < nk) load_stage((it + 2) % 3, (it + 2) * 16);
    int buf = it % 3;
    unsigned* sB = dsm + 3 * GA_ST + buf * (NB * GB_STAGE);
    unsigned abase = sa_base + (unsigned)((buf * GA_ST + (wm * MI * 16 + lrow) * GA_STRIDE + lcol) * 4);
    #pragma unroll
    for (int ks = 0; ks < 2; ks++) {
      int kb = ks * 8;
      unsigned a[MI][4];
      #pragma unroll
      for (int i = 0; i < MI; i++)
        ldsm_x4(a[i], abase + (unsigned)((i * 16 * GA_STRIDE + kb) * 4));
      unsigned b[NB][4][2];
      #pragma unroll
      for (int nb = 0; nb < NB; nb++)
        #pragma unroll
        for (int j = 0; j < 4; j++) {
          int nc = wn * 32 + j * 8;
          b[nb][j][0] = sB[nb * GB_STAGE + (kb + t) * GBS + nc + g];
          b[nb][j][1] = sB[nb * GB_STAGE + (kb + 4 + t) * GBS + nc + g];
        }
      #pragma unroll
      for (int nb = 0; nb < NB; nb++)
        #pragma unroll
        for (int i = 0; i < MI; i++)
          #pragma unroll
          for (int j = 0; j < 4; j++)
            mma_tf32(acc[nb][i][j], a[i], b[nb][j]);
    }
  }

  #pragma unroll
  for (int i = 0; i < MI; i++) {
    int r0 = rb + wm * MI * 16 + i * 16 + g;
    int bidx = r0 >> 10;
    #pragma unroll
    for (int j = 0; j < 4; j++) {
      int c0 = cb + wn * 32 + j * 8 + 2 * t;
      if (c0 >= N) continue;
      float v00 = acc[0][i][j][0], v01 = acc[0][i][j][1];
      float v10 = acc[0][i][j][2], v11 = acc[0][i][j][3];
      if constexpr (MODE == 3) {
        float ba0 = bias[c0], ba1 = bias[c0 + 1];
        float bg0 = bias[2730 + c0], bg1 = bias[2730 + c0 + 1];
        float g00 = acc[1][i][j][0] + bg0, g01 = acc[1][i][j][1] + bg1;
        float g10 = acc[1][i][j][2] + bg0, g11 = acc[1][i][j][3] + bg1;
        float2 w0 = {f2tf_f(gelu_e(g00) * (v00 + ba0)), f2tf_f(gelu_e(g01) * (v01 + ba1))};
        float2 w1 = {f2tf_f(gelu_e(g10) * (v10 + ba0)), f2tf_f(gelu_e(g11) * (v11 + ba1))};
        *(float2*)&C[(size_t)r0 * cDffP + c0]       = w0;
        *(float2*)&C[(size_t)(r0 + 8) * cDffP + c0] = w1;
        continue;
      }
      if constexpr (MODE == 0 || MODE == 1) {
        float b0 = bias ? bias[c0] : 0.f;
        float b1 = bias ? bias[c0 + 1] : 0.f;
        v00 += b0; v01 += b1; v10 += b0; v11 += b1;
        if constexpr (MODE == 1) {
          const float* az = adaz + bidx * N;
          float a0 = az[c0], a1 = az[c0 + 1];
          v00 = resid[(size_t)r0 * N + c0]       + v00 * a0;
          v01 = resid[(size_t)r0 * N + c0 + 1]   + v01 * a1;
          v10 = resid[(size_t)(r0+8) * N + c0]   + v10 * a0;
          v11 = resid[(size_t)(r0+8) * N + c0+1] + v11 * a1;
        }
      } else if constexpr (MODE == 2) {
        if (c0 < 2048) {
          int p = (c0 & 63) >> 1;
          float2 csa = g_cs[(r0 & 1023) * 32 + p];
          float2 csb = g_cs[((r0 + 8) & 1023) * 32 + p];
          float o00 = v00 * csa.x - v01 * csa.y;
          float o01 = v01 * csa.x + v00 * csa.y;
          float o10 = v10 * csb.x - v11 * csb.y;
          float o11 = v11 * csb.x + v10 * csb.y;
          v00 = o00; v01 = o01; v10 = o10; v11 = o11;
        } else {
          int cv = c0 - 2048;
          if (l0) {
            *(float2*)&g_vr[(size_t)r0 * 1024 + cv]       = make_float2(v00, v01);
            *(float2*)&g_vr[(size_t)(r0 + 8) * 1024 + cv] = make_float2(v10, v11);
          } else {
            float2 w0 = *(const float2*)&g_vr[(size_t)r0 * 1024 + cv];
            float2 w1 = *(const float2*)&g_vr[(size_t)(r0 + 8) * 1024 + cv];
            v00 = 0.5f * (v00 + w0.x); v01 = 0.5f * (v01 + w0.y);
            v10 = 0.5f * (v10 + w1.x); v11 = 0.5f * (v11 + w1.y);
          }
        }
      }
      *(float2*)&C[(size_t)r0 * N + c0]       = make_float2(v00, v01);
      *(float2*)&C[(size_t)(r0 + 8) * N + c0] = make_float2(v10, v11);
    }
  }
}

// ---------------- gates = sigmoid(xc @ gates_w) ----------------
__global__ void k_gates(const float* __restrict__ gw) {
  int i = blockIdx.x * 256 + threadIdx.x;
  if (i >= cRows * cH) return;
  int row = i >> 4, h = i & 15;
  const float* xr = g_xc + (size_t)row * cD;
  float acc = 0.f;
  #pragma unroll 4
  for (int k = 0; k < cD; k++) acc += xr[k] * gw[k * cH + h];
  g_gates[i] = 1.f / (1.f + expf(-acc));
}

// ---------------- tensor-core flash attention ----------------
__device__ __forceinline__ float softcap_exp(float s) {
  float z = s * 0.02f;
  float z2 = z * z;
  float num = s * (15.f + z2);
  float den = 15.f + 6.f * z2;
  return __expf(__fdividef(num, den));
}

__global__ __launch_bounds__(128) void k_attn() {
  __shared__ unsigned KP[64][68];
  __shared__ unsigned Vs[64][68];
  int qt = (int)gridDim.x - 1 - (int)blockIdx.x;
  int bh = blockIdx.y;
  int b = bh >> 4, h = bh & 15;
  int q0 = qt * 64;
  int tid = threadIdx.x, warp = tid >> 5, lane = tid & 31;
  int g = lane >> 2, t = lane & 3;
  int mr = warp * 16;

  for (int idx = tid; idx < 64 * 16; idx += 128) {
    int r = idx >> 4, d4 = (idx & 15) * 4;
    float4 q4 = *(const float4*)&g_qkv[(size_t)(b * cN + q0 + r) * 3072 + h * 64 + d4];
    uint4 u = {f2tf_u(q4.x), f2tf_u(q4.y), f2tf_u(q4.z), f2tf_u(q4.w)};
    *(uint4*)&Vs[r][d4] = u;
  }
  __syncthreads();
  unsigned qa[8][4];
  #pragma unroll
  for (int kb = 0; kb < 8; kb++) {
    qa[kb][0] = Vs[mr + g][kb * 8 + t];
    qa[kb][1] = Vs[mr + 8 + g][kb * 8 + t];
    qa[kb][2] = Vs[mr + g][kb * 8 + 4 + t];
    qa[kb][3] = Vs[mr + 8 + g][kb * 8 + 4 + t];
  }

  float o[8][4] = {};
  float l0 = 0.f, l1 = 0.f;
  int row0 = q0 + mr + g, row1 = row0 + 8;

  for (int kt = 0; kt <= qt; kt++) {
    int k0 = kt * 64;
    __syncthreads();
    for (int idx = tid; idx < 64 * 16; idx += 128) {
      int r = idx >> 4, d4 = (idx & 15) * 4;
      size_t base = (size_t)(b * cN + k0 + r) * 3072 + h * 64 + d4;
      float4 kv = *(const float4*)&g_qkv[base + 1024];
      float4 vv = *(const float4*)&g_qkv[base + 2048];
      uint4 uk = {f2tf_u(kv.x), f2tf_u(kv.y), f2tf_u(kv.z), f2tf_u(kv.w)};
      uint4 uv = {f2tf_u(vv.x), f2tf_u(vv.y), f2tf_u(vv.z), f2tf_u(vv.w)};
      *(uint4*)&KP[r][d4] = uk;
      *(uint4*)&Vs[r][d4] = uv;
    }
    __syncthreads();

    float s[8][4] = {};
    #pragma unroll
    for (int kb = 0; kb < 8; kb++) {
      #pragma unroll
      for (int nf = 0; nf < 8; nf++) {
        unsigned bfr[2] = {KP[nf * 8 + g][kb * 8 + t], KP[nf * 8 + g][kb * 8 + 4 + t]};
        mma_tf32(s[nf], qa[kb], bfr);
      }
    }

    float p[8][4];
    #pragma unroll
    for (int nf = 0; nf < 8; nf++) {
      int c0 = k0 + nf * 8 + 2 * t, c1 = c0 + 1;
      float p0 = (c0 <= row0) ? softcap_exp(s[nf][0] * 0.125f) : 0.f;
      float p1 = (c1 <= row0) ? softcap_exp(s[nf][1] * 0.125f) : 0.f;
      float p2 = (c0 <= row1) ? softcap_exp(s[nf][2] * 0.125f) : 0.f;
      float p3 = (c1 <= row1) ? softcap_exp(s[nf][3] * 0.125f) : 0.f;
      p[nf][0] = p0; p[nf][1] = p1; p[nf][2] = p2; p[nf][3] = p3;
      l0 += p0 + p1;
      l1 += p2 + p3;
    }

    __syncthreads();
    #pragma unroll
    for (int nf = 0; nf < 8; nf++) {
      KP[mr + g][nf * 8 + 2 * t]     = f2tf_u(p[nf][0]);
      KP[mr + g][nf * 8 + 2 * t + 1] = f2tf_u(p[nf][1]);
      KP[mr + 8 + g][nf * 8 + 2 * t]     = f2tf_u(p[nf][2]);
      KP[mr + 8 + g][nf * 8 + 2 * t + 1] = f2tf_u(p[nf][3]);
    }
    __syncthreads();

    #pragma unroll
    for (int kb = 0; kb < 8; kb++) {
      unsigned pa[4] = {KP[mr + g][kb * 8 + t], KP[mr + 8 + g][kb * 8 + t],
                        KP[mr + g][kb * 8 + 4 + t], KP[mr + 8 + g][kb * 8 + 4 + t]};
      #pragma unroll
      for (int nf = 0; nf < 8; nf++) {
        unsigned bfr[2] = {Vs[kb * 8 + t][nf * 8 + g], Vs[kb * 8 + 4 + t][nf * 8 + g]};
        mma_tf32(o[nf], pa, bfr);
      }
    }
  }

  l0 += __shfl_xor_sync(0xffffffffu, l0, 1);
  l0 += __shfl_xor_sync(0xffffffffu, l0, 2);
  l1 += __shfl_xor_sync(0xffffffffu, l1, 1);
  l1 += __shfl_xor_sync(0xffffffffu, l1, 2);

  float gate0 = g_gates[(b * cN + row0) * cH + h];
  float gate1 = g_gates[(b * cN + row1) * cH + h];
  float inv0 = gate0 / l0, inv1 = gate1 / l1;
  #pragma unroll
  for (int nf = 0; nf < 8; nf++) {
    int dcol = h * 64 + nf * 8 + 2 * t;
    g_o[(size_t)(b * cN + row0) * cD + dcol]     = f2tf_f(o[nf][0] * inv0);
    g_o[(size_t)(b * cN + row0) * cD + dcol + 1] = f2tf_f(o[nf][1] * inv0);
    g_o[(size_t)(b * cN + row1) * cD + dcol]     = f2tf_f(o[nf][2] * inv1);
    g_o[(size_t)(b * cN + row1) * cD + dcol + 1] = f2tf_f(o[nf][3] * inv1);
  }
}

// ---------------- xcat = tf32([x, skip]) ----------------
__global__ void k_concat(const float* __restrict__ x, const float* __restrict__ skip) {
  int i = blockIdx.x * 256 + threadIdx.x;
  if (i >= cRows * 2 * cD) return;
  int row = i >> 11, c = i & 2047;
  float v = (c < 1024) ? x[(size_t)row * cD + c] : skip[(size_t)row * cD + c - 1024];
  g_xcat[i] = f2tf_f(v);
}

// ---------------- final norm ----------------
__global__ void k_final(const float* __restrict__ gamma, const float* __restrict__ src,
                        float* __restrict__ out) {
  int row = blockIdx.x;
  int tid = threadIdx.x;
  float4 v = ((const float4*)(src + (size_t)row * cD))[tid];
  float s2 = v.x*v.x + v.y*v.y + v.z*v.z + v.w*v.w;
  #pragma unroll
  for (int off = 16; off > 0; off >>= 1)
    s2 += __shfl_xor_sync(0xffffffffu, s2, off);
  __shared__ float ws2[8];
  __shared__ float sscale;
  if ((tid & 31) == 0) ws2[tid >> 5] = s2;
  __syncthreads();
  if (tid == 0) {
    float t2 = 0.f;
    for (int w = 0; w < 8; w++) t2 += ws2[w];
    sscale = 32.f / fmaxf(sqrtf(t2), 1e-12f);
  }
  __syncthreads();
  float sc = sscale;
  int d = tid * 4;
  float4 o;
  o.x = v.x * sc * (gamma[d + 0] + 1.f);
  o.y = v.y * sc * (gamma[d + 1] + 1.f);
  o.z = v.z * sc * (gamma[d + 2] + 1.f);
  o.w = v.w * sc * (gamma[d + 3] + 1.f);
  ((float4*)(out + (size_t)row * cD))[tid] = o;
}

// ---------------- host launcher ----------------
extern "C" void kernel_launch(void* const* d_in, const int* in_sizes, int n_in,
                              void* d_out, int out_size) {
  const float* in_x  = (const float*)d_in[0];
  const float* times = (const float*)d_in[1];
  const float* rf    = (const float*)d_in[2];
  const float* fw    = (const float*)d_in[3];
  const float* tw    = (const float*)d_in[4];
  const float* tb    = (const float*)d_in[5];
  const float* skw   = (const float*)d_in[6];
  const float* afw   = (const float*)d_in[7];
  const float* afb   = (const float*)d_in[8];
  const float* aaw   = (const float*)d_in[9];
  const float* aab   = (const float*)d_in[10];
  const float* qkvw  = (const float*)d_in[11];
  const float* gw    = (const float*)d_in[12];
  const float* ow    = (const float*)d_in[13];
  const float* ffw   = (const float*)d_in[14];
  const float* ffb   = (const float*)d_in[15];
  const float* faw   = (const float*)d_in[16];
  const float* fab   = (const float*)d_in[17];
  const float* w1    = (const float*)d_in[18];
  const float* b1    = (const float*)d_in[19];
  const float* w2    = (const float*)d_in[20];
  const float* b2    = (const float*)d_in[21];
  const float* gamma = (const float*)d_in[22];
  float* out = (float*)d_out;

  cudaFuncSetAttribute(k_gemm<64,0>,  cudaFuncAttributeMaxDynamicSharedMemorySize, smem_bytes(64,0));
  cudaFuncSetAttribute(k_gemm<64,1>,  cudaFuncAttributeMaxDynamicSharedMemorySize, smem_bytes(64,1));
  cudaFuncSetAttribute(k_gemm<128,2>, cudaFuncAttributeMaxDynamicSharedMemorySize, smem_bytes(128,2));
  cudaFuncSetAttribute(k_gemm<128,3>, cudaFuncAttributeMaxDynamicSharedMemorySize, smem_bytes(128,3));

  float *pxc, *pqkv, *po, *pffa, *pxcat, *pxb, *paf, *pff, *paa, *pfa;
  cudaGetSymbolAddress((void**)&pxc,   g_xc);
  cudaGetSymbolAddress((void**)&pqkv,  g_qkv);
  cudaGetSymbolAddress((void**)&po,    g_o);
  cudaGetSymbolAddress((void**)&pffa,  g_ffa);
  cudaGetSymbolAddress((void**)&pxcat, g_xcat);
  cudaGetSymbolAddress((void**)&pxb,   g_xb);
  cudaGetSymbolAddress((void**)&paf,   g_attn_film);
  cudaGetSymbolAddress((void**)&pff,   g_ff_film);
  cudaGetSymbolAddress((void**)&paa,   g_attn_adaz);
  cudaGetSymbolAddress((void**)&pfa,   g_ff_adaz);

  const size_t XS = (size_t)cRows * cD;
  const float* XB[4] = {in_x, pxb, pxb + XS, pxb + 2 * XS};
  float* XBw[4] = {nullptr, pxb, pxb + XS, pxb + 2 * XS};
  int cur = 0;

  k_cond<<<dim3(cDc / 256, cB), 256>>>(times, fw, tw, tb);
  k_proj<<<dim3(24, cL), 256>>>(afw, afb, ffw, ffb, aaw, aab, faw, fab);
  k_sincos<<<(cN * 32) / 256, 256>>>(rf);

  for (int l = 0; l < cL; l++) {
    if (l >= 3) {
      k_concat<<<(cRows * 2 * cD) / 256, 256>>>(XB[cur], XB[5 - l]);
      k_gemm<64,0><<<dim3(16, 16), 256, smem_bytes(64,0)>>>(
          pxcat, skw + (size_t)(l - 3) * 2048 * 1024, nullptr, XBw[3],
          nullptr, nullptr, cRows, 1024, 2048, 2048, 0);
      cur = 3;
    }
    // attention block
    k_lnfilm<<<cRows, 256>>>(paf + (size_t)l * cB * 2 * cD, XB[cur]);
    k_gemm<128,2><<<dim3(24, 16), 256, smem_bytes(128,2)>>>(
        pxc, qkvw + (size_t)l * 1024 * 3072, nullptr, pqkv,
        nullptr, nullptr, cRows, 3072, 1024, 1024, l == 0 ? 1 : 0);
    k_gates<<<(cRows * cH) / 256, 256>>>(gw + (size_t)l * 1024 * 16);
    k_attn<<<dim3(16, 32), 128>>>();
    int nxt = (l < 3) ? l + 1 : 3;
    k_gemm<64,1><<<dim3(16, 16), 256, smem_bytes(64,1)>>>(
        po, ow + (size_t)l * 1024 * 1024, nullptr, XBw[nxt],
        XB[cur], paa + (size_t)l * cB * cD, cRows, 1024, 1024, 1024, 0);
    cur = nxt;
    // feed-forward block (ff1 + GLU fused)
    k_lnfilm<<<cRows, 256>>>(pff + (size_t)l * cB * 2 * cD, XB[cur]);
    k_gemm<128,3><<<dim3((cDff + 127) / 128, cRows / 64), 256, smem_bytes(128,3)>>>(
        pxc, w1 + (size_t)l * 1024 * (2 * cDff), b1 + (size_t)l * (2 * cDff), pffa,
        nullptr, nullptr, cRows, cDff, 1024, 1024, 0);
    k_gemm<64,1><<<dim3(16, 16), 256, smem_bytes(64,1)>>>(
        pffa, w2 + (size_t)l * cDff * 1024, b2 + (size_t)l * 1024, XBw[cur],
        XB[cur], pfa + (size_t)l * cB * cD, cRows, 1024, cDff, cDffP, 0);
  }
  k_final<<<cRows, 256>>>(gamma, XB[3], out);
}

// round 10
// speedup vs baseline: 3.4184x; 1.0398x over previous
#include <cuda_runtime.h>
#include <math.h>

// ---------------- problem constants ----------------
constexpr int cB   = 2;
constexpr int cN   = 1024;
constexpr int cD   = 1024;
constexpr int cL   = 6;
constexpr int cH   = 16;
constexpr int cDff = 2730;
constexpr int cDffP = 2732;    // padded row stride
constexpr int cDc  = 4096;
constexpr int cRows = cB * cN; // 2048

// ---------------- device scratch ----------------
__device__ float g_cond[cB * cDc];
__device__ float g_attn_film[cL * cB * 2 * cD];
__device__ float g_ff_film[cL * cB * 2 * cD];
__device__ float g_attn_adaz[cL * cB * cD];
__device__ float g_ff_adaz[cL * cB * cD];
__device__ __align__(16) float g_xc[cRows * cD];
__device__ __align__(16) float g_qkv[cRows * 3 * cD];
__device__ __align__(16) float g_vr[cRows * cD];
__device__ __align__(16) float g_o[cRows * cD];
__device__ __align__(16) float g_ffa[cRows * cDffP + 64];
__device__ __align__(16) float g_xb[3][cRows * cD];
__device__ __align__(16) float g_xcat[cRows * 2 * cD];
__device__ float g_gates[cRows * cH];
__device__ float2 g_cs[cN * 32];
// attention split-K partials: [half][bh][qt-8][row][col] and l-sums
__device__ __align__(16) float g_po[2][32][8][64][64];
__device__ float g_pl[2][32][8][64];

// attention job table (LPT order, biggest first): qt, kt0, kt1, half(-1=full)
__constant__ signed char c_jq[24] = {15,15,14, 7,14,13,13,12, 6,12,11,11,10, 5,10, 9, 9, 8, 4, 8, 3, 2, 1, 0};
__constant__ signed char c_j0[24] = { 0, 8, 7, 0, 0, 0, 7, 6, 0, 0, 0, 6, 5, 0, 0, 0, 5, 4, 0, 0, 0, 0, 0, 0};
__constant__ signed char c_j1[24] = { 8,16,15, 8, 7, 7,14,13, 7, 6, 6,12,11, 6, 5, 5,10, 9, 5, 4, 4, 3, 2, 1};
__constant__ signed char c_jh[24] = { 0, 1, 1,-1, 0, 0, 1, 1,-1, 0, 0, 1, 1,-1, 0, 0, 1, 1,-1, 0,-1,-1,-1,-1};

__device__ __forceinline__ float f2tf_f(float x) {
  unsigned u;
  asm("cvt.rna.tf32.f32 %0, %1;" : "=r"(u) : "f"(x));
  return __uint_as_float(u);
}
__device__ __forceinline__ unsigned f2tf_u(float x) {
  unsigned u;
  asm("cvt.rna.tf32.f32 %0, %1;" : "=r"(u) : "f"(x));
  return u;
}

__global__ void k_sincos(const float* __restrict__ rf) {
  int i = blockIdx.x * 256 + threadIdx.x;
  if (i >= cN * 32) return;
  int n = i >> 5, p = i & 31;
  float f = rf[n * 64 + 2 * p];
  float s, c;
  sincosf(f, &s, &c);
  g_cs[i] = make_float2(c, s);
}

// ---------------- cond = silu(fourier @ tcond_w + b) ----------------
__global__ void k_cond(const float* __restrict__ times, const float* __restrict__ fw,
                       const float* __restrict__ tw, const float* __restrict__ tb) {
  __shared__ float fs[1025];
  int b = blockIdx.y;
  float t = times[b];
  for (int i = threadIdx.x; i < 1025; i += 256) {
    if (i == 0)        fs[0] = t;
    else if (i <= 512) fs[i] = sinf(6.283185307179586f * t * fw[i - 1]);
    else               fs[i] = cosf(6.283185307179586f * t * fw[i - 513]);
  }
  __syncthreads();
  int j = blockIdx.x * 256 + threadIdx.x;
  float acc = tb[j];
  for (int k = 0; k < 1025; k++) acc += fs[k] * tw[k * cDc + j];
  g_cond[b * cDc + j] = acc / (1.f + expf(-acc));
}

// ---------------- all cond projections ----------------
__global__ void k_proj(const float* __restrict__ afw, const float* __restrict__ afb,
                       const float* __restrict__ ffw, const float* __restrict__ ffb,
                       const float* __restrict__ aaw, const float* __restrict__ aab,
                       const float* __restrict__ faw, const float* __restrict__ fab) {
  __shared__ float cs0[cDc], cs1[cDc];
  int l = blockIdx.y;
  for (int i = threadIdx.x; i < cDc; i += 256) {
    cs0[i] = g_cond[i];
    cs1[i] = g_cond[cDc + i];
  }
  __syncthreads();
  int o = blockIdx.x * 256 + threadIdx.x;
  const float* W; const float* bias; float* out; int cols; int c; bool sig = false;
  if (o < 2048)      { c = o;        cols = 2048; W = afw + (size_t)l*cDc*2048; bias = afb + l*2048; out = g_attn_film + (size_t)l*cB*2048; }
  else if (o < 4096) { c = o - 2048; cols = 2048; W = ffw + (size_t)l*cDc*2048; bias = ffb + l*2048; out = g_ff_film   + (size_t)l*cB*2048; }
  else if (o < 5120) { c = o - 4096; cols = 1024; W = aaw + (size_t)l*cDc*1024; bias = aab + l*1024; out = g_attn_adaz + (size_t)l*cB*1024; sig = true; }
  else               { c = o - 5120; cols = 1024; W = faw + (size_t)l*cDc*1024; bias = fab + l*1024; out = g_ff_adaz   + (size_t)l*cB*1024; sig = true; }
  float acc0 = bias[c], acc1 = bias[c];
  #pragma unroll 8
  for (int k = 0; k < cDc; k++) {
    float w = W[(size_t)k * cols + c];
    acc0 += cs0[k] * w;
    acc1 += cs1[k] * w;
  }
  if (sig) { acc0 = 1.f / (1.f + expf(-acc0)); acc1 = 1.f / (1.f + expf(-acc1)); }
  out[c] = acc0;
  out[cols + c] = acc1;
}

// ---------------- LN + FiLM ----------------
__global__ void k_lnfilm(const float* __restrict__ film, const float* __restrict__ src) {
  int row = blockIdx.x;
  int b = row >> 10;
  int tid = threadIdx.x;
  float4 v = ((const float4*)(src + (size_t)row * cD))[tid];
  float s  = v.x + v.y + v.z + v.w;
  float s2 = v.x*v.x + v.y*v.y + v.z*v.z + v.w*v.w;
  #pragma unroll
  for (int off = 16; off > 0; off >>= 1) {
    s  += __shfl_xor_sync(0xffffffffu, s,  off);
    s2 += __shfl_xor_sync(0xffffffffu, s2, off);
  }
  __shared__ float ws[8], ws2[8];
  __shared__ float smu, srstd;
  if ((tid & 31) == 0) { ws[tid >> 5] = s; ws2[tid >> 5] = s2; }
  __syncthreads();
  if (tid == 0) {
    float t1 = 0.f, t2 = 0.f;
    for (int w = 0; w < 8; w++) { t1 += ws[w]; t2 += ws2[w]; }
    float mu = t1 * (1.f / cD);
    float var = t2 * (1.f / cD) - mu * mu;
    smu = mu; srstd = rsqrtf(var + 1e-5f);
  }
  __syncthreads();
  float mu = smu, rs = srstd;
  const float* fg = film + b * 2 * cD;
  int d = tid * 4;
  float4 o;
  o.x = f2tf_f((v.x - mu) * rs * (fg[d+0] + 1.f) + fg[cD + d + 0]);
  o.y = f2tf_f((v.y - mu) * rs * (fg[d+1] + 1.f) + fg[cD + d + 1]);
  o.z = f2tf_f((v.z - mu) * rs * (fg[d+2] + 1.f) + fg[cD + d + 2]);
  o.w = f2tf_f((v.w - mu) * rs * (fg[d+3] + 1.f) + fg[cD + d + 3]);
  ((float4*)(g_xc + (size_t)row * cD))[tid] = o;
}

// ---------------- tf32 GEMM: cp.async 3-stage + ldmatrix ----------------
// MODE 0: C = A@W (+bias);  MODE 1: C = resid + (A@W+bias)*adaz   [256 thr, BN=64]
// MODE 2: qkv epilogue;     MODE 3: ff1+GLU fused                 [128 thr, BN=128, 64x64 warp tile]
__device__ __forceinline__ void mma_tf32(float (&c)[4], const unsigned (&a)[4],
                                         const unsigned (&b)[2]) {
  asm volatile(
      "mma.sync.aligned.m16n8k8.row.col.f32.tf32.tf32.f32 "
      "{%0,%1,%2,%3}, {%4,%5,%6,%7}, {%8,%9}, {%0,%1,%2,%3};\n"
      : "+f"(c[0]), "+f"(c[1]), "+f"(c[2]), "+f"(c[3])
      : "r"(a[0]), "r"(a[1]), "r"(a[2]), "r"(a[3]), "r"(b[0]), "r"(b[1]));
}
__device__ __forceinline__ void ldsm_x4(unsigned (&r)[4], unsigned saddr) {
  asm volatile("ldmatrix.sync.aligned.m8n8.x4.shared.b16 {%0,%1,%2,%3}, [%4];"
               : "=r"(r[0]), "=r"(r[1]), "=r"(r[2]), "=r"(r[3]) : "r"(saddr));
}
__device__ __forceinline__ void cpa16(void* smem, const void* gmem, bool valid) {
  unsigned sa = (unsigned)__cvta_generic_to_shared(smem);
  int sz = valid ? 16 : 0;
  asm volatile("cp.async.cg.shared.global [%0], [%1], 16, %2;\n"
               :: "r"(sa), "l"(gmem), "r"(sz) : "memory");
}
__device__ __forceinline__ void cpa8(void* smem, const void* gmem, bool valid) {
  unsigned sa = (unsigned)__cvta_generic_to_shared(smem);
  int sz = valid ? 8 : 0;
  asm volatile("cp.async.ca.shared.global [%0], [%1], 8, %2;\n"
               :: "r"(sa), "l"(gmem), "r"(sz) : "memory");
}
__device__ __forceinline__ float gelu_e(float g) {
  return 0.5f * g * (1.f + erff(g * 0.7071067811865476f));
}

constexpr int GA_STRIDE = 20;
constexpr int smem_bytes(int BN, int MODE) {
  int bm = (MODE == 3) ? 64 : 128;
  int nb = (MODE == 3) ? 2 : 1;
  int gbs = (BN == 128) ? 136 : 72;
  return 3 * (bm * GA_STRIDE + nb * 16 * gbs) * 4;
}

template <int BN, int MODE>
__global__ __launch_bounds__(((MODE == 2 || MODE == 3) ? 128 : 256), 2) void k_gemm(
    const float* __restrict__ A, const float* __restrict__ W,
    const float* __restrict__ bias, float* __restrict__ C,
    const float* __restrict__ resid, const float* __restrict__ adaz,
    int M, int N, int K, int lda, int l0) {
  constexpr int TH  = (MODE == 2 || MODE == 3) ? 128 : 256;
  constexpr int BM  = (MODE == 3) ? 64 : 128;
  constexpr int NWM = (TH == 128) ? 2 : 4;
  constexpr int MI  = BM / NWM / 16;
  constexpr int NJ  = BN / 2 / 8;
  constexpr int GBS = (BN == 128) ? 136 : 72;
  constexpr int GB_STAGE = 16 * GBS;
  constexpr int NB  = (MODE == 3) ? 2 : 1;
  constexpr int GA_ST = BM * GA_STRIDE;
  extern __shared__ unsigned dsm[];
  unsigned sa_base = (unsigned)__cvta_generic_to_shared(dsm);
  int tid = threadIdx.x;
  int warp = tid >> 5, lane = tid & 31;
  int wm = warp >> 1, wn = warp & 1;
  int g = lane >> 2, t = lane & 3;
  int lrow = lane & 15, lcol = (lane >> 4) << 2;
  int rb = blockIdx.y * BM, cb = blockIdx.x * BN;
  float acc[NB][MI][NJ][4] = {};
  int nk = (K + 15) / 16;

  auto load_stage = [&](int buf, int k0) {
    unsigned* sA = dsm + buf * GA_ST;
    unsigned* sB = dsm + 3 * GA_ST + buf * (NB * GB_STAGE);
    #pragma unroll
    for (int it = 0; it < (BM * 4) / TH; it++) {
      int idx = tid + it * TH;
      int m = idx >> 2, kg = idx & 3;
      cpa16(&sA[m * GA_STRIDE + kg * 4], A + (size_t)(rb + m) * lda + k0 + kg * 4, true);
    }
    #pragma unroll
    for (int it = 0; it < (BN * 4) / TH; it++) {
      int idx = tid + it * TH;
      int kk = idx / (BN / 4), n4 = idx % (BN / 4);
      int gk = k0 + kk, gn = cb + n4 * 4;
      bool ok = (gk < K) && (gn < N);
      if constexpr (MODE == 3) {
        const float* sa_ = W + (size_t)gk * 5460 + gn;
        cpa16(&sB[kk * GBS + n4 * 4], sa_, ok);
        const float* sg_ = W + (size_t)gk * 5460 + 2730 + gn;
        cpa8(&sB[GB_STAGE + kk * GBS + n4 * 4], sg_, ok);
        cpa8(&sB[GB_STAGE + kk * GBS + n4 * 4 + 2], sg_ + 2, ok && (gn + 2 < N));
      } else {
        cpa16(&sB[kk * GBS + n4 * 4], W + (size_t)gk * N + gn, ok);
      }
    }
    asm volatile("cp.async.commit_group;\n" ::: "memory");
  };

  load_stage(0, 0);
  if (nk > 1) load_stage(1, 16);
  for (int it = 0; it < nk; it++) {
    if (it + 2 <= nk) {
      asm volatile("cp.async.wait_group 1;\n" ::: "memory");
    } else {
      asm volatile("cp.async.wait_group 0;\n" ::: "memory");
    }
    __syncthreads();
    if (it + 2 < nk) load_stage((it + 2) % 3, (it + 2) * 16);
    int buf = it % 3;
    unsigned* sB = dsm + 3 * GA_ST + buf * (NB * GB_STAGE);
    unsigned abase = sa_base + (unsigned)((buf * GA_ST + (wm * MI * 16 + lrow) * GA_STRIDE + lcol) * 4);
    #pragma unroll
    for (int ks = 0; ks < 2; ks++) {
      int kb = ks * 8;
      unsigned a[MI][4];
      #pragma unroll
      for (int i = 0; i < MI; i++)
        ldsm_x4(a[i], abase + (unsigned)((i * 16 * GA_STRIDE + kb) * 4));
      unsigned b[NB][NJ][2];
      #pragma unroll
      for (int nb = 0; nb < NB; nb++)
        #pragma unroll
        for (int j = 0; j < NJ; j++) {
          int nc = wn * (BN / 2) + j * 8;
          b[nb][j][0] = sB[nb * GB_STAGE + (kb + t) * GBS + nc + g];
          b[nb][j][1] = sB[nb * GB_STAGE + (kb + 4 + t) * GBS + nc + g];
        }
      #pragma unroll
      for (int nb = 0; nb < NB; nb++)
        #pragma unroll
        for (int i = 0; i < MI; i++)
          #pragma unroll
          for (int j = 0; j < NJ; j++)
            mma_tf32(acc[nb][i][j], a[i], b[nb][j]);
    }
  }

  #pragma unroll
  for (int i = 0; i < MI; i++) {
    int r0 = rb + wm * MI * 16 + i * 16 + g;
    int bidx = r0 >> 10;
    #pragma unroll
    for (int j = 0; j < NJ; j++) {
      int c0 = cb + wn * (BN / 2) + j * 8 + 2 * t;
      if (c0 >= N) continue;
      float v00 = acc[0][i][j][0], v01 = acc[0][i][j][1];
      float v10 = acc[0][i][j][2], v11 = acc[0][i][j][3];
      if constexpr (MODE == 3) {
        float ba0 = bias[c0], ba1 = bias[c0 + 1];
        float bg0 = bias[2730 + c0], bg1 = bias[2730 + c0 + 1];
        float g00 = acc[1][i][j][0] + bg0, g01 = acc[1][i][j][1] + bg1;
        float g10 = acc[1][i][j][2] + bg0, g11 = acc[1][i][j][3] + bg1;
        float2 w0 = {f2tf_f(gelu_e(g00) * (v00 + ba0)), f2tf_f(gelu_e(g01) * (v01 + ba1))};
        float2 w1 = {f2tf_f(gelu_e(g10) * (v10 + ba0)), f2tf_f(gelu_e(g11) * (v11 + ba1))};
        *(float2*)&C[(size_t)r0 * cDffP + c0]       = w0;
        *(float2*)&C[(size_t)(r0 + 8) * cDffP + c0] = w1;
        continue;
      }
      if constexpr (MODE == 0 || MODE == 1) {
        float b0 = bias ? bias[c0] : 0.f;
        float b1 = bias ? bias[c0 + 1] : 0.f;
        v00 += b0; v01 += b1; v10 += b0; v11 += b1;
        if constexpr (MODE == 1) {
          const float* az = adaz + bidx * N;
          float a0 = az[c0], a1 = az[c0 + 1];
          v00 = resid[(size_t)r0 * N + c0]       + v00 * a0;
          v01 = resid[(size_t)r0 * N + c0 + 1]   + v01 * a1;
          v10 = resid[(size_t)(r0+8) * N + c0]   + v10 * a0;
          v11 = resid[(size_t)(r0+8) * N + c0+1] + v11 * a1;
        }
      } else if constexpr (MODE == 2) {
        if (c0 < 2048) {
          int p = (c0 & 63) >> 1;
          float2 csa = g_cs[(r0 & 1023) * 32 + p];
          float2 csb = g_cs[((r0 + 8) & 1023) * 32 + p];
          float o00 = v00 * csa.x - v01 * csa.y;
          float o01 = v01 * csa.x + v00 * csa.y;
          float o10 = v10 * csb.x - v11 * csb.y;
          float o11 = v11 * csb.x + v10 * csb.y;
          v00 = o00; v01 = o01; v10 = o10; v11 = o11;
        } else {
          int cv = c0 - 2048;
          if (l0) {
            *(float2*)&g_vr[(size_t)r0 * 1024 + cv]       = make_float2(v00, v01);
            *(float2*)&g_vr[(size_t)(r0 + 8) * 1024 + cv] = make_float2(v10, v11);
          } else {
            float2 w0 = *(const float2*)&g_vr[(size_t)r0 * 1024 + cv];
            float2 w1 = *(const float2*)&g_vr[(size_t)(r0 + 8) * 1024 + cv];
            v00 = 0.5f * (v00 + w0.x); v01 = 0.5f * (v01 + w0.y);
            v10 = 0.5f * (v10 + w1.x); v11 = 0.5f * (v11 + w1.y);
          }
        }
      }
      *(float2*)&C[(size_t)r0 * N + c0]       = make_float2(v00, v01);
      *(float2*)&C[(size_t)(r0 + 8) * N + c0] = make_float2(v10, v11);
    }
  }
}

// ---------------- gates = sigmoid(xc @ gates_w) ----------------
__global__ void k_gates(const float* __restrict__ gw) {
  int i = blockIdx.x * 256 + threadIdx.x;
  if (i >= cRows * cH) return;
  int row = i >> 4, h = i & 15;
  const float* xr = g_xc + (size_t)row * cD;
  float acc = 0.f;
  #pragma unroll 4
  for (int k = 0; k < cD; k++) acc += xr[k] * gw[k * cH + h];
  g_gates[i] = 1.f / (1.f + expf(-acc));
}

// ---------------- tensor-core flash attention (split-K for big q-tiles) ----------------
__device__ __forceinline__ float softcap_exp(float s) {
  float z = s * 0.02f;
  float z2 = z * z;
  float num = s * (15.f + z2);
  float den = 15.f + 6.f * z2;
  return __expf(__fdividef(num, den));
}

// grid (24 jobs, 32 bh); 128 threads
__global__ __launch_bounds__(128) void k_attn() {
  __shared__ unsigned KP[64][68];
  __shared__ unsigned Vs[64][68];
  int job = blockIdx.x;
  int qt = c_jq[job], kt0 = c_j0[job], kt1 = c_j1[job], half = c_jh[job];
  int bh = blockIdx.y;
  int b = bh >> 4, h = bh & 15;
  int q0 = qt * 64;
  int tid = threadIdx.x, warp = tid >> 5, lane = tid & 31;
  int g = lane >> 2, t = lane & 3;
  int mr = warp * 16;

  for (int idx = tid; idx < 64 * 16; idx += 128) {
    int r = idx >> 4, d4 = (idx & 15) * 4;
    float4 q4 = *(const float4*)&g_qkv[(size_t)(b * cN + q0 + r) * 3072 + h * 64 + d4];
    uint4 u = {f2tf_u(q4.x), f2tf_u(q4.y), f2tf_u(q4.z), f2tf_u(q4.w)};
    *(uint4*)&Vs[r][d4] = u;
  }
  __syncthreads();
  unsigned qa[8][4];
  #pragma unroll
  for (int kb = 0; kb < 8; kb++) {
    qa[kb][0] = Vs[mr + g][kb * 8 + t];
    qa[kb][1] = Vs[mr + 8 + g][kb * 8 + t];
    qa[kb][2] = Vs[mr + g][kb * 8 + 4 + t];
    qa[kb][3] = Vs[mr + 8 + g][kb * 8 + 4 + t];
  }

  float o[8][4] = {};
  float l0 = 0.f, l1 = 0.f;
  int row0 = q0 + mr + g, row1 = row0 + 8;

  for (int kt = kt0; kt < kt1; kt++) {
    int k0 = kt * 64;
    __syncthreads();
    for (int idx = tid; idx < 64 * 16; idx += 128) {
      int r = idx >> 4, d4 = (idx & 15) * 4;
      size_t base = (size_t)(b * cN + k0 + r) * 3072 + h * 64 + d4;
      float4 kv = *(const float4*)&g_qkv[base + 1024];
      float4 vv = *(const float4*)&g_qkv[base + 2048];
      uint4 uk = {f2tf_u(kv.x), f2tf_u(kv.y), f2tf_u(kv.z), f2tf_u(kv.w)};
      uint4 uv = {f2tf_u(vv.x), f2tf_u(vv.y), f2tf_u(vv.z), f2tf_u(vv.w)};
      *(uint4*)&KP[r][d4] = uk;
      *(uint4*)&Vs[r][d4] = uv;
    }
    __syncthreads();

    float s[8][4] = {};
    #pragma unroll
    for (int kb = 0; kb < 8; kb++) {
      #pragma unroll
      for (int nf = 0; nf < 8; nf++) {
        unsigned bfr[2] = {KP[nf * 8 + g][kb * 8 + t], KP[nf * 8 + g][kb * 8 + 4 + t]};
        mma_tf32(s[nf], qa[kb], bfr);
      }
    }

    float p[8][4];
    #pragma unroll
    for (int nf = 0; nf < 8; nf++) {
      int c0 = k0 + nf * 8 + 2 * t, c1 = c0 + 1;
      float p0 = (c0 <= row0) ? softcap_exp(s[nf][0] * 0.125f) : 0.f;
      float p1 = (c1 <= row0) ? softcap_exp(s[nf][1] * 0.125f) : 0.f;
      float p2 = (c0 <= row1) ? softcap_exp(s[nf][2] * 0.125f) : 0.f;
      float p3 = (c1 <= row1) ? softcap_exp(s[nf][3] * 0.125f) : 0.f;
      p[nf][0] = p0; p[nf][1] = p1; p[nf][2] = p2; p[nf][3] = p3;
      l0 += p0 + p1;
      l1 += p2 + p3;
    }

    __syncthreads();
    #pragma unroll
    for (int nf = 0; nf < 8; nf++) {
      KP[mr + g][nf * 8 + 2 * t]     = f2tf_u(p[nf][0]);
      KP[mr + g][nf * 8 + 2 * t + 1] = f2tf_u(p[nf][1]);
      KP[mr + 8 + g][nf * 8 + 2 * t]     = f2tf_u(p[nf][2]);
      KP[mr + 8 + g][nf * 8 + 2 * t + 1] = f2tf_u(p[nf][3]);
    }
    __syncthreads();

    #pragma unroll
    for (int kb = 0; kb < 8; kb++) {
      unsigned pa[4] = {KP[mr + g][kb * 8 + t], KP[mr + 8 + g][kb * 8 + t],
                        KP[mr + g][kb * 8 + 4 + t], KP[mr + 8 + g][kb * 8 + 4 + t]};
      #pragma unroll
      for (int nf = 0; nf < 8; nf++) {
        unsigned bfr[2] = {Vs[kb * 8 + t][nf * 8 + g], Vs[kb * 8 + 4 + t][nf * 8 + g]};
        mma_tf32(o[nf], pa, bfr);
      }
    }
  }

  l0 += __shfl_xor_sync(0xffffffffu, l0, 1);
  l0 += __shfl_xor_sync(0xffffffffu, l0, 2);
  l1 += __shfl_xor_sync(0xffffffffu, l1, 1);
  l1 += __shfl_xor_sync(0xffffffffu, l1, 2);

  if (half < 0) {
    float gate0 = g_gates[(b * cN + row0) * cH + h];
    float gate1 = g_gates[(b * cN + row1) * cH + h];
    float inv0 = gate0 / l0, inv1 = gate1 / l1;
    #pragma unroll
    for (int nf = 0; nf < 8; nf++) {
      int dcol = h * 64 + nf * 8 + 2 * t;
      g_o[(size_t)(b * cN + row0) * cD + dcol]     = f2tf_f(o[nf][0] * inv0);
      g_o[(size_t)(b * cN + row0) * cD + dcol + 1] = f2tf_f(o[nf][1] * inv0);
      g_o[(size_t)(b * cN + row1) * cD + dcol]     = f2tf_f(o[nf][2] * inv1);
      g_o[(size_t)(b * cN + row1) * cD + dcol + 1] = f2tf_f(o[nf][3] * inv1);
    }
  } else {
    int qh = qt - 8;
    int lr0 = mr + g, lr1 = lr0 + 8;
    #pragma unroll
    for (int nf = 0; nf < 8; nf++) {
      int col = nf * 8 + 2 * t;
      *(float2*)&g_po[half][bh][qh][lr0][col] = make_float2(o[nf][0], o[nf][1]);
      *(float2*)&g_po[half][bh][qh][lr1][col] = make_float2(o[nf][2], o[nf][3]);
    }
    if (t == 0) {
      g_pl[half][bh][qh][lr0] = l0;
      g_pl[half][bh][qh][lr1] = l1;
    }
  }
}

// combine split-K attention partials: grid (8, 32), 256 threads
__global__ void k_comb() {
  int qh = blockIdx.x, bh = blockIdx.y;
  int b = bh >> 4, h = bh & 15;
  int tid = threadIdx.x;
  int lr = tid >> 2, c4 = (tid & 3) * 16;
  int grow = (8 + qh) * 64 + lr;
  float l = g_pl[0][bh][qh][lr] + g_pl[1][bh][qh][lr];
  float gate = g_gates[(b * cN + grow) * cH + h];
  float sc = gate / l;
  #pragma unroll
  for (int c = 0; c < 16; c += 4) {
    float4 a = *(const float4*)&g_po[0][bh][qh][lr][c4 + c];
    float4 d = *(const float4*)&g_po[1][bh][qh][lr][c4 + c];
    float4 o;
    o.x = f2tf_f((a.x + d.x) * sc);
    o.y = f2tf_f((a.y + d.y) * sc);
    o.z = f2tf_f((a.z + d.z) * sc);
    o.w = f2tf_f((a.w + d.w) * sc);
    *(float4*)&g_o[(size_t)(b * cN + grow) * cD + h * 64 + c4 + c] = o;
  }
}

// ---------------- xcat = tf32([x, skip]) ----------------
__global__ void k_concat(const float* __restrict__ x, const float* __restrict__ skip) {
  int i = blockIdx.x * 256 + threadIdx.x;
  if (i >= cRows * 2 * cD) return;
  int row = i >> 11, c = i & 2047;
  float v = (c < 1024) ? x[(size_t)row * cD + c] : skip[(size_t)row * cD + c - 1024];
  g_xcat[i] = f2tf_f(v);
}

// ---------------- final norm ----------------
__global__ void k_final(const float* __restrict__ gamma, const float* __restrict__ src,
                        float* __restrict__ out) {
  int row = blockIdx.x;
  int tid = threadIdx.x;
  float4 v = ((const float4*)(src + (size_t)row * cD))[tid];
  float s2 = v.x*v.x + v.y*v.y + v.z*v.z + v.w*v.w;
  #pragma unroll
  for (int off = 16; off > 0; off >>= 1)
    s2 += __shfl_xor_sync(0xffffffffu, s2, off);
  __shared__ float ws2[8];
  __shared__ float sscale;
  if ((tid & 31) == 0) ws2[tid >> 5] = s2;
  __syncthreads();
  if (tid == 0) {
    float t2 = 0.f;
    for (int w = 0; w < 8; w++) t2 += ws2[w];
    sscale = 32.f / fmaxf(sqrtf(t2), 1e-12f);
  }
  __syncthreads();
  float sc = sscale;
  int d = tid * 4;
  float4 o;
  o.x = v.x * sc * (gamma[d + 0] + 1.f);
  o.y = v.y * sc * (gamma[d + 1] + 1.f);
  o.z = v.z * sc * (gamma[d + 2] + 1.f);
  o.w = v.w * sc * (gamma[d + 3] + 1.f);
  ((float4*)(out + (size_t)row * cD))[tid] = o;
}

// ---------------- host launcher ----------------
extern "C" void kernel_launch(void* const* d_in, const int* in_sizes, int n_in,
                              void* d_out, int out_size) {
  const float* in_x  = (const float*)d_in[0];
  const float* times = (const float*)d_in[1];
  const float* rf    = (const float*)d_in[2];
  const float* fw    = (const float*)d_in[3];
  const float* tw    = (const float*)d_in[4];
  const float* tb    = (const float*)d_in[5];
  const float* skw   = (const float*)d_in[6];
  const float* afw   = (const float*)d_in[7];
  const float* afb   = (const float*)d_in[8];
  const float* aaw   = (const float*)d_in[9];
  const float* aab   = (const float*)d_in[10];
  const float* qkvw  = (const float*)d_in[11];
  const float* gw    = (const float*)d_in[12];
  const float* ow    = (const float*)d_in[13];
  const float* ffw   = (const float*)d_in[14];
  const float* ffb   = (const float*)d_in[15];
  const float* faw   = (const float*)d_in[16];
  const float* fab   = (const float*)d_in[17];
  const float* w1    = (const float*)d_in[18];
  const float* b1    = (const float*)d_in[19];
  const float* w2    = (const float*)d_in[20];
  const float* b2    = (const float*)d_in[21];
  const float* gamma = (const float*)d_in[22];
  float* out = (float*)d_out;

  cudaFuncSetAttribute(k_gemm<64,0>,  cudaFuncAttributeMaxDynamicSharedMemorySize, smem_bytes(64,0));
  cudaFuncSetAttribute(k_gemm<64,1>,  cudaFuncAttributeMaxDynamicSharedMemorySize, smem_bytes(64,1));
  cudaFuncSetAttribute(k_gemm<128,2>, cudaFuncAttributeMaxDynamicSharedMemorySize, smem_bytes(128,2));
  cudaFuncSetAttribute(k_gemm<128,3>, cudaFuncAttributeMaxDynamicSharedMemorySize, smem_bytes(128,3));

  float *pxc, *pqkv, *po, *pffa, *pxcat, *pxb, *paf, *pff, *paa, *pfa;
  cudaGetSymbolAddress((void**)&pxc,   g_xc);
  cudaGetSymbolAddress((void**)&pqkv,  g_qkv);
  cudaGetSymbolAddress((void**)&po,    g_o);
  cudaGetSymbolAddress((void**)&pffa,  g_ffa);
  cudaGetSymbolAddress((void**)&pxcat, g_xcat);
  cudaGetSymbolAddress((void**)&pxb,   g_xb);
  cudaGetSymbolAddress((void**)&paf,   g_attn_film);
  cudaGetSymbolAddress((void**)&pff,   g_ff_film);
  cudaGetSymbolAddress((void**)&paa,   g_attn_adaz);
  cudaGetSymbolAddress((void**)&pfa,   g_ff_adaz);

  const size_t XS = (size_t)cRows * cD;
  const float* XB[4] = {in_x, pxb, pxb + XS, pxb + 2 * XS};
  float* XBw[4] = {nullptr, pxb, pxb + XS, pxb + 2 * XS};
  int cur = 0;

  k_cond<<<dim3(cDc / 256, cB), 256>>>(times, fw, tw, tb);
  k_proj<<<dim3(24, cL), 256>>>(afw, afb, ffw, ffb, aaw, aab, faw, fab);
  k_sincos<<<(cN * 32) / 256, 256>>>(rf);

  for (int l = 0; l < cL; l++) {
    if (l >= 3) {
      k_concat<<<(cRows * 2 * cD) / 256, 256>>>(XB[cur], XB[5 - l]);
      k_gemm<64,0><<<dim3(16, 16), 256, smem_bytes(64,0)>>>(
          pxcat, skw + (size_t)(l - 3) * 2048 * 1024, nullptr, XBw[3],
          nullptr, nullptr, cRows, 1024, 2048, 2048, 0);
      cur = 3;
    }
    // attention block
    k_lnfilm<<<cRows, 256>>>(paf + (size_t)l * cB * 2 * cD, XB[cur]);
    k_gemm<128,2><<<dim3(24, 16), 128, smem_bytes(128,2)>>>(
        pxc, qkvw + (size_t)l * 1024 * 3072, nullptr, pqkv,
        nullptr, nullptr, cRows, 3072, 1024, 1024, l == 0 ? 1 : 0);
    k_gates<<<(cRows * cH) / 256, 256>>>(gw + (size_t)l * 1024 * 16);
    k_attn<<<dim3(24, 32), 128>>>();
    k_comb<<<dim3(8, 32), 256>>>();
    int nxt = (l < 3) ? l + 1 : 3;
    k_gemm<64,1><<<dim3(16, 16), 256, smem_bytes(64,1)>>>(
        po, ow + (size_t)l * 1024 * 1024, nullptr, XBw[nxt],
        XB[cur], paa + (size_t)l * cB * cD, cRows, 1024, 1024, 1024, 0);
    cur = nxt;
    // feed-forward block (ff1 + GLU fused)
    k_lnfilm<<<cRows, 256>>>(pff + (size_t)l * cB * 2 * cD, XB[cur]);
    k_gemm<128,3><<<dim3((cDff + 127) / 128, cRows / 64), 128, smem_bytes(128,3)>>>(
        pxc, w1 + (size_t)l * 1024 * (2 * cDff), b1 + (size_t)l * (2 * cDff), pffa,
        nullptr, nullptr, cRows, cDff, 1024, 1024, 0);
    k_gemm<64,1><<<dim3(16, 16), 256, smem_bytes(64,1)>>>(
        pffa, w2 + (size_t)l * cDff * 1024, b2 + (size_t)l * 1024, XBw[cur],
        XB[cur], pfa + (size_t)l * cB * cD, cRows, 1024, cDff, cDffP, 0);
  }
  k_final<<<cRows, 256>>>(gamma, XB[3], out);
}

// round 12
// speedup vs baseline: 3.8447x; 1.1247x over previous
#include <cuda_runtime.h>
#include <math.h>

// ---------------- problem constants ----------------
constexpr int cB   = 2;
constexpr int cN   = 1024;
constexpr int cD   = 1024;
constexpr int cL   = 6;
constexpr int cH   = 16;
constexpr int cDff = 2730;
constexpr int cDffP = 2732;    // padded row stride for ffa
constexpr int cDc  = 4096;
constexpr int cRows = cB * cN; // 2048
constexpr int cQS  = 3088;     // qkv row stride (3072 qkv + 16 gates)

// ---------------- device scratch ----------------
__device__ float g_cond[cB * cDc];
__device__ float g_attn_film[cL * cB * 2 * cD];
__device__ float g_ff_film[cL * cB * 2 * cD];
__device__ float g_attn_adaz[cL * cB * cD];
__device__ float g_ff_adaz[cL * cB * cD];
__device__ __align__(16) float g_xc[cRows * cD];
__device__ __align__(16) float g_qkv[cRows * cQS];
__device__ __align__(16) float g_vr[cRows * cD];
__device__ __align__(16) float g_o[cRows * cD];
__device__ __align__(16) float g_ffa[cRows * cDffP + 64];
__device__ __align__(16) float g_xb[3][cRows * cD];
__device__ __align__(16) float g_xcat[cRows * 2 * cD];
__device__ float g_gates[cRows * cH];
__device__ float2 g_cs[cN * 32];
__device__ __align__(16) float g_wqg[cL * cD * cQS];   // qkv || gates combined weight
// attention split-K partials
__device__ __align__(16) float g_po[2][32][8][64][64];
__device__ float g_pl[2][32][8][64];

// attention job table (LPT order): qt, kt0, kt1, half(-1=full)
__constant__ signed char c_jq[24] = {15,15,14, 7,14,13,13,12, 6,12,11,11,10, 5,10, 9, 9, 8, 4, 8, 3, 2, 1, 0};
__constant__ signed char c_j0[24] = { 0, 8, 7, 0, 0, 0, 7, 6, 0, 0, 0, 6, 5, 0, 0, 0, 5, 4, 0, 0, 0, 0, 0, 0};
__constant__ signed char c_j1[24] = { 8,16,15, 8, 7, 7,14,13, 7, 6, 6,12,11, 6, 5, 5,10, 9, 5, 4, 4, 3, 2, 1};
__constant__ signed char c_jh[24] = { 0, 1, 1,-1, 0, 0, 1, 1,-1, 0, 0, 1, 1,-1, 0, 0, 1, 1,-1, 0,-1,-1,-1,-1};

__device__ __forceinline__ float f2tf_f(float x) {
  unsigned u;
  asm("cvt.rna.tf32.f32 %0, %1;" : "=r"(u) : "f"(x));
  return __uint_as_float(u);
}
__device__ __forceinline__ unsigned f2tf_u(float x) {
  unsigned u;
  asm("cvt.rna.tf32.f32 %0, %1;" : "=r"(u) : "f"(x));
  return u;
}

__global__ void k_sincos(const float* __restrict__ rf) {
  int i = blockIdx.x * 256 + threadIdx.x;
  if (i >= cN * 32) return;
  int n = i >> 5, p = i & 31;
  float f = rf[n * 64 + 2 * p];
  float s, c;
  sincosf(f, &s, &c);
  g_cs[i] = make_float2(c, s);
}

// build combined qkv||gates weight: [L][D][3088]
__global__ void k_buildw(const float* __restrict__ qkvw, const float* __restrict__ gw) {
  int i = blockIdx.x * 256 + threadIdx.x;
  if (i >= cL * cD * cQS) return;
  int c = i % cQS;
  int rowk = i / cQS;          // l*cD + k
  g_wqg[i] = (c < 3072) ? qkvw[(size_t)rowk * 3072 + c] : gw[rowk * 16 + (c - 3072)];
}

// ---------------- cond = silu(fourier @ tcond_w + b) ----------------
__global__ void k_cond(const float* __restrict__ times, const float* __restrict__ fw,
                       const float* __restrict__ tw, const float* __restrict__ tb) {
  __shared__ float fs[1025];
  int b = blockIdx.y;
  float t = times[b];
  for (int i = threadIdx.x; i < 1025; i += 256) {
    if (i == 0)        fs[0] = t;
    else if (i <= 512) fs[i] = sinf(6.283185307179586f * t * fw[i - 1]);
    else               fs[i] = cosf(6.283185307179586f * t * fw[i - 513]);
  }
  __syncthreads();
  int j = blockIdx.x * 256 + threadIdx.x;
  float acc = tb[j];
  for (int k = 0; k < 1025; k++) acc += fs[k] * tw[k * cDc + j];
  g_cond[b * cDc + j] = acc / (1.f + expf(-acc));
}

// ---------------- all cond projections (4-way K split, 64 cols/CTA) ----------------
__global__ void k_proj(const float* __restrict__ afw, const float* __restrict__ afb,
                       const float* __restrict__ ffw, const float* __restrict__ ffb,
                       const float* __restrict__ aaw, const float* __restrict__ aab,
                       const float* __restrict__ faw, const float* __restrict__ fab) {
  __shared__ float cs0[cDc], cs1[cDc];
  __shared__ float red0[4][64], red1[4][64];
  int l = blockIdx.y;
  int tid = threadIdx.x;
  for (int i = tid; i < cDc; i += 256) {
    cs0[i] = g_cond[i];
    cs1[i] = g_cond[cDc + i];
  }
  __syncthreads();
  int warp = tid >> 5, lane = tid & 31;
  int q = warp >> 1;                       // k-quarter 0..3
  int cl = (warp & 1) * 32 + lane;         // 0..63
  int o = blockIdx.x * 64 + cl;            // 0..6143
  const float* W; int cols; int c;
  if (o < 2048)      { c = o;        cols = 2048; W = afw + (size_t)l*cDc*2048; }
  else if (o < 4096) { c = o - 2048; cols = 2048; W = ffw + (size_t)l*cDc*2048; }
  else if (o < 5120) { c = o - 4096; cols = 1024; W = aaw + (size_t)l*cDc*1024; }
  else               { c = o - 5120; cols = 1024; W = faw + (size_t)l*cDc*1024; }
  int k0 = q * 1024;
  float acc0 = 0.f, acc1 = 0.f;
  #pragma unroll 8
  for (int k = k0; k < k0 + 1024; k++) {
    float w = W[(size_t)k * cols + c];
    acc0 += cs0[k] * w;
    acc1 += cs1[k] * w;
  }
  red0[q][cl] = acc0;
  red1[q][cl] = acc1;
  __syncthreads();
  if (tid < 64) {
    int cl2 = tid;
    int o2 = blockIdx.x * 64 + cl2;
    const float* bias; float* out; int cols2; int c2; bool sig = false;
    if (o2 < 2048)      { c2 = o2;        cols2 = 2048; bias = afb + l*2048; out = g_attn_film + (size_t)l*cB*2048; }
    else if (o2 < 4096) { c2 = o2 - 2048; cols2 = 2048; bias = ffb + l*2048; out = g_ff_film   + (size_t)l*cB*2048; }
    else if (o2 < 5120) { c2 = o2 - 4096; cols2 = 1024; bias = aab + l*1024; out = g_attn_adaz + (size_t)l*cB*1024; sig = true; }
    else                { c2 = o2 - 5120; cols2 = 1024; bias = fab + l*1024; out = g_ff_adaz   + (size_t)l*cB*1024; sig = true; }
    float a0 = bias[c2] + red0[0][cl2] + red0[1][cl2] + red0[2][cl2] + red0[3][cl2];
    float a1 = bias[c2] + red1[0][cl2] + red1[1][cl2] + red1[2][cl2] + red1[3][cl2];
    if (sig) { a0 = 1.f / (1.f + expf(-a0)); a1 = 1.f / (1.f + expf(-a1)); }
    out[c2] = a0;
    out[cols2 + c2] = a1;
  }
}

// ---------------- LN + FiLM ----------------
__global__ void k_lnfilm(const float* __restrict__ film, const float* __restrict__ src) {
  int row = blockIdx.x;
  int b = row >> 10;
  int tid = threadIdx.x;
  float4 v = ((const float4*)(src + (size_t)row * cD))[tid];
  float s  = v.x + v.y + v.z + v.w;
  float s2 = v.x*v.x + v.y*v.y + v.z*v.z + v.w*v.w;
  #pragma unroll
  for (int off = 16; off > 0; off >>= 1) {
    s  += __shfl_xor_sync(0xffffffffu, s,  off);
    s2 += __shfl_xor_sync(0xffffffffu, s2, off);
  }
  __shared__ float ws[8], ws2[8];
  __shared__ float smu, srstd;
  if ((tid & 31) == 0) { ws[tid >> 5] = s; ws2[tid >> 5] = s2; }
  __syncthreads();
  if (tid == 0) {
    float t1 = 0.f, t2 = 0.f;
    for (int w = 0; w < 8; w++) { t1 += ws[w]; t2 += ws2[w]; }
    float mu = t1 * (1.f / cD);
    float var = t2 * (1.f / cD) - mu * mu;
    smu = mu; srstd = rsqrtf(var + 1e-5f);
  }
  __syncthreads();
  float mu = smu, rs = srstd;
  const float* fg = film + b * 2 * cD;
  int d = tid * 4;
  float4 o;
  o.x = f2tf_f((v.x - mu) * rs * (fg[d+0] + 1.f) + fg[cD + d + 0]);
  o.y = f2tf_f((v.y - mu) * rs * (fg[d+1] + 1.f) + fg[cD + d + 1]);
  o.z = f2tf_f((v.z - mu) * rs * (fg[d+2] + 1.f) + fg[cD + d + 2]);
  o.w = f2tf_f((v.w - mu) * rs * (fg[d+3] + 1.f) + fg[cD + d + 3]);
  ((float4*)(g_xc + (size_t)row * cD))[tid] = o;
}

// ---------------- tf32 GEMM: cp.async 3-stage + ldmatrix ----------------
// MODE 0: C = A@W (+bias);  MODE 1: C = resid + (A@W+bias)*adaz   [256 thr, BN=64]
// MODE 2: qkv+gates epilogue; MODE 3: ff1+GLU fused               [128 thr, BN=128]
__device__ __forceinline__ void mma_tf32(float (&c)[4], const unsigned (&a)[4],
                                         const unsigned (&b)[2]) {
  asm volatile(
      "mma.sync.aligned.m16n8k8.row.col.f32.tf32.tf32.f32 "
      "{%0,%1,%2,%3}, {%4,%5,%6,%7}, {%8,%9}, {%0,%1,%2,%3};\n"
      : "+f"(c[0]), "+f"(c[1]), "+f"(c[2]), "+f"(c[3])
      : "r"(a[0]), "r"(a[1]), "r"(a[2]), "r"(a[3]), "r"(b[0]), "r"(b[1]));
}
__device__ __forceinline__ void ldsm_x4(unsigned (&r)[4], unsigned saddr) {
  asm volatile("ldmatrix.sync.aligned.m8n8.x4.shared.b16 {%0,%1,%2,%3}, [%4];"
               : "=r"(r[0]), "=r"(r[1]), "=r"(r[2]), "=r"(r[3]) : "r"(saddr));
}
__device__ __forceinline__ void cpa16(void* smem, const void* gmem, bool valid) {
  unsigned sa = (unsigned)__cvta_generic_to_shared(smem);
  int sz = valid ? 16 : 0;
  asm volatile("cp.async.cg.shared.global [%0], [%1], 16, %2;\n"
               :: "r"(sa), "l"(gmem), "r"(sz) : "memory");
}
__device__ __forceinline__ void cpa8(void* smem, const void* gmem, bool valid) {
  unsigned sa = (unsigned)__cvta_generic_to_shared(smem);
  int sz = valid ? 8 : 0;
  asm volatile("cp.async.ca.shared.global [%0], [%1], 8, %2;\n"
               :: "r"(sa), "l"(gmem), "r"(sz) : "memory");
}
__device__ __forceinline__ float gelu_e(float g) {
  return 0.5f * g * (1.f + erff(g * 0.7071067811865476f));
}

constexpr int GA_STRIDE = 20;
constexpr int smem_bytes(int BN, int MODE) {
  int bm = (MODE == 3) ? 64 : 128;
  int nb = (MODE == 3) ? 2 : 1;
  int gbs = (BN == 128) ? 136 : 72;
  return 3 * (bm * GA_STRIDE + nb * 16 * gbs) * 4;
}

template <int BN, int MODE>
__global__ __launch_bounds__(((MODE == 2 || MODE == 3) ? 128 : 256), 2) void k_gemm(
    const float* __restrict__ A, const float* __restrict__ W,
    const float* __restrict__ bias, float* __restrict__ C,
    const float* __restrict__ resid, const float* __restrict__ adaz,
    int M, int N, int K, int lda, int l0) {
  constexpr int TH  = (MODE == 2 || MODE == 3) ? 128 : 256;
  constexpr int BM  = (MODE == 3) ? 64 : 128;
  constexpr int NWM = (TH == 128) ? 2 : 4;
  constexpr int MI  = BM / NWM / 16;
  constexpr int NJ  = BN / 2 / 8;
  constexpr int GBS = (BN == 128) ? 136 : 72;
  constexpr int GB_STAGE = 16 * GBS;
  constexpr int NB  = (MODE == 3) ? 2 : 1;
  constexpr int GA_ST = BM * GA_STRIDE;
  extern __shared__ unsigned dsm[];
  unsigned sa_base = (unsigned)__cvta_generic_to_shared(dsm);
  int tid = threadIdx.x;
  int warp = tid >> 5, lane = tid & 31;
  int wm = warp >> 1, wn = warp & 1;
  int g = lane >> 2, t = lane & 3;
  int lrow = lane & 15, lcol = (lane >> 4) << 2;
  int rb = blockIdx.y * BM, cb = blockIdx.x * BN;
  float acc[NB][MI][NJ][4] = {};
  int nk = (K + 15) / 16;

  auto load_stage = [&](int buf, int k0) {
    unsigned* sA = dsm + buf * GA_ST;
    unsigned* sB = dsm + 3 * GA_ST + buf * (NB * GB_STAGE);
    #pragma unroll
    for (int it = 0; it < (BM * 4) / TH; it++) {
      int idx = tid + it * TH;
      int m = idx >> 2, kg = idx & 3;
      cpa16(&sA[m * GA_STRIDE + kg * 4], A + (size_t)(rb + m) * lda + k0 + kg * 4, true);
    }
    #pragma unroll
    for (int it = 0; it < (BN * 4) / TH; it++) {
      int idx = tid + it * TH;
      int kk = idx / (BN / 4), n4 = idx % (BN / 4);
      int gk = k0 + kk, gn = cb + n4 * 4;
      bool ok = (gk < K) && (gn < N);
      if constexpr (MODE == 3) {
        const float* sa_ = W + (size_t)gk * 5460 + gn;
        cpa16(&sB[kk * GBS + n4 * 4], sa_, ok);
        const float* sg_ = W + (size_t)gk * 5460 + 2730 + gn;
        cpa8(&sB[GB_STAGE + kk * GBS + n4 * 4], sg_, ok);
        cpa8(&sB[GB_STAGE + kk * GBS + n4 * 4 + 2], sg_ + 2, ok && (gn + 2 < N));
      } else {
        cpa16(&sB[kk * GBS + n4 * 4], W + (size_t)gk * N + gn, ok);
      }
    }
    asm volatile("cp.async.commit_group;\n" ::: "memory");
  };

  load_stage(0, 0);
  if (nk > 1) load_stage(1, 16);
  for (int it = 0; it < nk; it++) {
    if (it + 2 <= nk) {
      asm volatile("cp.async.wait_group 1;\n" ::: "memory");
    } else {
      asm volatile("cp.async.wait_group 0;\n" ::: "memory");
    }
    __syncthreads();
    if (it + 2 < nk) load_stage((it + 2) % 3, (it + 2) * 16);
    int buf = it % 3;
    unsigned* sB = dsm + 3 * GA_ST + buf * (NB * GB_STAGE);
    unsigned abase = sa_base + (unsigned)((buf * GA_ST + (wm * MI * 16 + lrow) * GA_STRIDE + lcol) * 4);
    #pragma unroll
    for (int ks = 0; ks < 2; ks++) {
      int kb = ks * 8;
      unsigned a[MI][4];
      #pragma unroll
      for (int i = 0; i < MI; i++)
        ldsm_x4(a[i], abase + (unsigned)((i * 16 * GA_STRIDE + kb) * 4));
      unsigned b[NB][NJ][2];
      #pragma unroll
      for (int nb = 0; nb < NB; nb++)
        #pragma unroll
        for (int j = 0; j < NJ; j++) {
          int nc = wn * (BN / 2) + j * 8;
          b[nb][j][0] = sB[nb * GB_STAGE + (kb + t) * GBS + nc + g];
          b[nb][j][1] = sB[nb * GB_STAGE + (kb + 4 + t) * GBS + nc + g];
        }
      #pragma unroll
      for (int nb = 0; nb < NB; nb++)
        #pragma unroll
        for (int i = 0; i < MI; i++)
          #pragma unroll
          for (int j = 0; j < NJ; j++)
            mma_tf32(acc[nb][i][j], a[i], b[nb][j]);
    }
  }

  #pragma unroll
  for (int i = 0; i < MI; i++) {
    int r0 = rb + wm * MI * 16 + i * 16 + g;
    int bidx = r0 >> 10;
    #pragma unroll
    for (int j = 0; j < NJ; j++) {
      int c0 = cb + wn * (BN / 2) + j * 8 + 2 * t;
      if (c0 >= N) continue;
      float v00 = acc[0][i][j][0], v01 = acc[0][i][j][1];
      float v10 = acc[0][i][j][2], v11 = acc[0][i][j][3];
      if constexpr (MODE == 3) {
        float ba0 = bias[c0], ba1 = bias[c0 + 1];
        float bg0 = bias[2730 + c0], bg1 = bias[2730 + c0 + 1];
        float g00 = acc[1][i][j][0] + bg0, g01 = acc[1][i][j][1] + bg1;
        float g10 = acc[1][i][j][2] + bg0, g11 = acc[1][i][j][3] + bg1;
        float2 w0 = {f2tf_f(gelu_e(g00) * (v00 + ba0)), f2tf_f(gelu_e(g01) * (v01 + ba1))};
        float2 w1 = {f2tf_f(gelu_e(g10) * (v10 + ba0)), f2tf_f(gelu_e(g11) * (v11 + ba1))};
        *(float2*)&C[(size_t)r0 * cDffP + c0]       = w0;
        *(float2*)&C[(size_t)(r0 + 8) * cDffP + c0] = w1;
        continue;
      }
      if constexpr (MODE == 0 || MODE == 1) {
        float b0 = bias ? bias[c0] : 0.f;
        float b1 = bias ? bias[c0 + 1] : 0.f;
        v00 += b0; v01 += b1; v10 += b0; v11 += b1;
        if constexpr (MODE == 1) {
          const float* az = adaz + bidx * N;
          float a0 = az[c0], a1 = az[c0 + 1];
          v00 = resid[(size_t)r0 * N + c0]       + v00 * a0;
          v01 = resid[(size_t)r0 * N + c0 + 1]   + v01 * a1;
          v10 = resid[(size_t)(r0+8) * N + c0]   + v10 * a0;
          v11 = resid[(size_t)(r0+8) * N + c0+1] + v11 * a1;
        }
      } else if constexpr (MODE == 2) {
        if (c0 >= 3072) {   // gates columns
          int cg = c0 - 3072;
          float s00 = 1.f / (1.f + expf(-v00)), s01 = 1.f / (1.f + expf(-v01));
          float s10 = 1.f / (1.f + expf(-v10)), s11 = 1.f / (1.f + expf(-v11));
          *(float2*)&g_gates[r0 * cH + cg]       = make_float2(s00, s01);
          *(float2*)&g_gates[(r0 + 8) * cH + cg] = make_float2(s10, s11);
          continue;
        }
        if (c0 < 2048) {
          int p = (c0 & 63) >> 1;
          float2 csa = g_cs[(r0 & 1023) * 32 + p];
          float2 csb = g_cs[((r0 + 8) & 1023) * 32 + p];
          float o00 = v00 * csa.x - v01 * csa.y;
          float o01 = v01 * csa.x + v00 * csa.y;
          float o10 = v10 * csb.x - v11 * csb.y;
          float o11 = v11 * csb.x + v10 * csb.y;
          v00 = o00; v01 = o01; v10 = o10; v11 = o11;
        } else {
          int cv = c0 - 2048;
          if (l0) {
            *(float2*)&g_vr[(size_t)r0 * 1024 + cv]       = make_float2(v00, v01);
            *(float2*)&g_vr[(size_t)(r0 + 8) * 1024 + cv] = make_float2(v10, v11);
          } else {
            float2 w0 = *(const float2*)&g_vr[(size_t)r0 * 1024 + cv];
            float2 w1 = *(const float2*)&g_vr[(size_t)(r0 + 8) * 1024 + cv];
            v00 = 0.5f * (v00 + w0.x); v01 = 0.5f * (v01 + w0.y);
            v10 = 0.5f * (v10 + w1.x); v11 = 0.5f * (v11 + w1.y);
          }
        }
      }
      *(float2*)&C[(size_t)r0 * N + c0]       = make_float2(v00, v01);
      *(float2*)&C[(size_t)(r0 + 8) * N + c0] = make_float2(v10, v11);
    }
  }
}

// ---------------- tensor-core flash attention (split-K, 2 syncs/iter) ----------------
__device__ __forceinline__ float softcap_exp(float s) {
  float z = s * 0.02f;
  float z2 = z * z;
  float num = s * (15.f + z2);
  float den = 15.f + 6.f * z2;
  return __expf(__fdividef(num, den));
}

constexpr int ATT_SMEM = 3 * 64 * 68 * 4;   // KP, Vs, Ps

__global__ __launch_bounds__(128) void k_attn() {
  extern __shared__ unsigned dsm[];
  unsigned (*KP)[68] = (unsigned(*)[68])dsm;
  unsigned (*Vs)[68] = (unsigned(*)[68])(dsm + 64 * 68);
  unsigned (*Ps)[68] = (unsigned(*)[68])(dsm + 2 * 64 * 68);
  int job = blockIdx.x;
  int qt = c_jq[job], kt0 = c_j0[job], kt1 = c_j1[job], half = c_jh[job];
  int bh = blockIdx.y;
  int b = bh >> 4, h = bh & 15;
  int q0 = qt * 64;
  int tid = threadIdx.x, warp = tid >> 5, lane = tid & 31;
  int g = lane >> 2, t = lane & 3;
  int mr = warp * 16;

  // stage Q via Ps
  for (int idx = tid; idx < 64 * 16; idx += 128) {
    int r = idx >> 4, d4 = (idx & 15) * 4;
    float4 q4 = *(const float4*)&g_qkv[(size_t)(b * cN + q0 + r) * cQS + h * 64 + d4];
    uint4 u = {f2tf_u(q4.x), f2tf_u(q4.y), f2tf_u(q4.z), f2tf_u(q4.w)};
    *(uint4*)&Ps[r][d4] = u;
  }
  __syncthreads();
  unsigned qa[8][4];
  #pragma unroll
  for (int kb = 0; kb < 8; kb++) {
    qa[kb][0] = Ps[mr + g][kb * 8 + t];
    qa[kb][1] = Ps[mr + 8 + g][kb * 8 + t];
    qa[kb][2] = Ps[mr + g][kb * 8 + 4 + t];
    qa[kb][3] = Ps[mr + 8 + g][kb * 8 + 4 + t];
  }

  float o[8][4] = {};
  float l0 = 0.f, l1 = 0.f;
  int row0 = q0 + mr + g, row1 = row0 + 8;

  for (int kt = kt0; kt < kt1; kt++) {
    int k0 = kt * 64;
    __syncthreads();   // all warps done with KP/Vs (and Ps qa-reads on iter0)
    for (int idx = tid; idx < 64 * 16; idx += 128) {
      int r = idx >> 4, d4 = (idx & 15) * 4;
      size_t base = (size_t)(b * cN + k0 + r) * cQS + h * 64 + d4;
      float4 kv = *(const float4*)&g_qkv[base + 1024];
      float4 vv = *(const float4*)&g_qkv[base + 2048];
      uint4 uk = {f2tf_u(kv.x), f2tf_u(kv.y), f2tf_u(kv.z), f2tf_u(kv.w)};
      uint4 uv = {f2tf_u(vv.x), f2tf_u(vv.y), f2tf_u(vv.z), f2tf_u(vv.w)};
      *(uint4*)&KP[r][d4] = uk;
      *(uint4*)&Vs[r][d4] = uv;
    }
    __syncthreads();

    float s[8][4] = {};
    #pragma unroll
    for (int kb = 0; kb < 8; kb++) {
      #pragma unroll
      for (int nf = 0; nf < 8; nf++) {
        unsigned bfr[2] = {KP[nf * 8 + g][kb * 8 + t], KP[nf * 8 + g][kb * 8 + 4 + t]};
        mma_tf32(s[nf], qa[kb], bfr);
      }
    }

    // softcap + mask + exp; write P to own warp's rows of Ps (no block sync needed)
    #pragma unroll
    for (int nf = 0; nf < 8; nf++) {
      int c0 = k0 + nf * 8 + 2 * t, c1 = c0 + 1;
      float p0 = (c0 <= row0) ? softcap_exp(s[nf][0] * 0.125f) : 0.f;
      float p1 = (c1 <= row0) ? softcap_exp(s[nf][1] * 0.125f) : 0.f;
      float p2 = (c0 <= row1) ? softcap_exp(s[nf][2] * 0.125f) : 0.f;
      float p3 = (c1 <= row1) ? softcap_exp(s[nf][3] * 0.125f) : 0.f;
      l0 += p0 + p1;
      l1 += p2 + p3;
      *(float2*)&Ps[mr + g][nf * 8 + 2 * t]     = make_float2(__uint_as_float(f2tf_u(p0)), __uint_as_float(f2tf_u(p1)));
      *(float2*)&Ps[mr + 8 + g][nf * 8 + 2 * t] = make_float2(__uint_as_float(f2tf_u(p2)), __uint_as_float(f2tf_u(p3)));
    }
    __syncwarp();

    #pragma unroll
    for (int kb = 0; kb < 8; kb++) {
      unsigned pa[4] = {Ps[mr + g][kb * 8 + t], Ps[mr + 8 + g][kb * 8 + t],
                        Ps[mr + g][kb * 8 + 4 + t], Ps[mr + 8 + g][kb * 8 + 4 + t]};
      #pragma unroll
      for (int nf = 0; nf < 8; nf++) {
        unsigned bfr[2] = {Vs[kb * 8 + t][nf * 8 + g], Vs[kb * 8 + 4 + t][nf * 8 + g]};
        mma_tf32(o[nf], pa, bfr);
      }
    }
  }

  l0 += __shfl_xor_sync(0xffffffffu, l0, 1);
  l0 += __shfl_xor_sync(0xffffffffu, l0, 2);
  l1 += __shfl_xor_sync(0xffffffffu, l1, 1);
  l1 += __shfl_xor_sync(0xffffffffu, l1, 2);

  if (half < 0) {
    float gate0 = g_gates[(b * cN + row0) * cH + h];
    float gate1 = g_gates[(b * cN + row1) * cH + h];
    float inv0 = gate0 / l0, inv1 = gate1 / l1;
    #pragma unroll
    for (int nf = 0; nf < 8; nf++) {
      int dcol = h * 64 + nf * 8 + 2 * t;
      g_o[(size_t)(b * cN + row0) * cD + dcol]     = f2tf_f(o[nf][0] * inv0);
      g_o[(size_t)(b * cN + row0) * cD + dcol + 1] = f2tf_f(o[nf][1] * inv0);
      g_o[(size_t)(b * cN + row1) * cD + dcol]     = f2tf_f(o[nf][2] * inv1);
      g_o[(size_t)(b * cN + row1) * cD + dcol + 1] = f2tf_f(o[nf][3] * inv1);
    }
  } else {
    int qh = qt - 8;
    int lr0 = mr + g, lr1 = lr0 + 8;
    #pragma unroll
    for (int nf = 0; nf < 8; nf++) {
      int col = nf * 8 + 2 * t;
      *(float2*)&g_po[half][bh][qh][lr0][col] = make_float2(o[nf][0], o[nf][1]);
      *(float2*)&g_po[half][bh][qh][lr1][col] = make_float2(o[nf][2], o[nf][3]);
    }
    if (t == 0) {
      g_pl[half][bh][qh][lr0] = l0;
      g_pl[half][bh][qh][lr1] = l1;
    }
  }
}

// combine split-K attention partials: grid (8, 32), 256 threads
__global__ void k_comb() {
  int qh = blockIdx.x, bh = blockIdx.y;
  int b = bh >> 4, h = bh & 15;
  int tid = threadIdx.x;
  int lr = tid >> 2, c4 = (tid & 3) * 16;
  int grow = (8 + qh) * 64 + lr;
  float l = g_pl[0][bh][qh][lr] + g_pl[1][bh][qh][lr];
  float gate = g_gates[(b * cN + grow) * cH + h];
  float sc = gate / l;
  #pragma unroll
  for (int c = 0; c < 16; c += 4) {
    float4 a = *(const float4*)&g_po[0][bh][qh][lr][c4 + c];
    float4 d = *(const float4*)&g_po[1][bh][qh][lr][c4 + c];
    float4 o;
    o.x = f2tf_f((a.x + d.x) * sc);
    o.y = f2tf_f((a.y + d.y) * sc);
    o.z = f2tf_f((a.z + d.z) * sc);
    o.w = f2tf_f((a.w + d.w) * sc);
    *(float4*)&g_o[(size_t)(b * cN + grow) * cD + h * 64 + c4 + c] = o;
  }
}

// ---------------- xcat = tf32([x, skip]) ----------------
__global__ void k_concat(const float* __restrict__ x, const float* __restrict__ skip) {
  int i = blockIdx.x * 256 + threadIdx.x;
  if (i >= cRows * 2 * cD) return;
  int row = i >> 11, c = i & 2047;
  float v = (c < 1024) ? x[(size_t)row * cD + c] : skip[(size_t)row * cD + c - 1024];
  g_xcat[i] = f2tf_f(v);
}

// ---------------- final norm ----------------
__global__ void k_final(const float* __restrict__ gamma, const float* __restrict__ src,
                        float* __restrict__ out) {
  int row = blockIdx.x;
  int tid = threadIdx.x;
  float4 v = ((const float4*)(src + (size_t)row * cD))[tid];
  float s2 = v.x*v.x + v.y*v.y + v.z*v.z + v.w*v.w;
  #pragma unroll
  for (int off = 16; off > 0; off >>= 1)
    s2 += __shfl_xor_sync(0xffffffffu, s2, off);
  __shared__ float ws2[8];
  __shared__ float sscale;
  if ((tid & 31) == 0) ws2[tid >> 5] = s2;
  __syncthreads();
  if (tid == 0) {
    float t2 = 0.f;
    for (int w = 0; w < 8; w++) t2 += ws2[w];
    sscale = 32.f / fmaxf(sqrtf(t2), 1e-12f);
  }
  __syncthreads();
  float sc = sscale;
  int d = tid * 4;
  float4 o;
  o.x = v.x * sc * (gamma[d + 0] + 1.f);
  o.y = v.y * sc * (gamma[d + 1] + 1.f);
  o.z = v.z * sc * (gamma[d + 2] + 1.f);
  o.w = v.w * sc * (gamma[d + 3] + 1.f);
  ((float4*)(out + (size_t)row * cD))[tid] = o;
}

// ---------------- host launcher ----------------
extern "C" void kernel_launch(void* const* d_in, const int* in_sizes, int n_in,
                              void* d_out, int out_size) {
  const float* in_x  = (const float*)d_in[0];
  const float* times = (const float*)d_in[1];
  const float* rf    = (const float*)d_in[2];
  const float* fw    = (const float*)d_in[3];
  const float* tw    = (const float*)d_in[4];
  const float* tb    = (const float*)d_in[5];
  const float* skw   = (const float*)d_in[6];
  const float* afw   = (const float*)d_in[7];
  const float* afb   = (const float*)d_in[8];
  const float* aaw   = (const float*)d_in[9];
  const float* aab   = (const float*)d_in[10];
  const float* qkvw  = (const float*)d_in[11];
  const float* gw    = (const float*)d_in[12];
  const float* ow    = (const float*)d_in[13];
  const float* ffw   = (const float*)d_in[14];
  const float* ffb   = (const float*)d_in[15];
  const float* faw   = (const float*)d_in[16];
  const float* fab   = (const float*)d_in[17];
  const float* w1    = (const float*)d_in[18];
  const float* b1    = (const float*)d_in[19];
  const float* w2    = (const float*)d_in[20];
  const float* b2    = (const float*)d_in[21];
  const float* gamma = (const float*)d_in[22];
  float* out = (float*)d_out;

  cudaFuncSetAttribute(k_gemm<64,0>,  cudaFuncAttributeMaxDynamicSharedMemorySize, smem_bytes(64,0));
  cudaFuncSetAttribute(k_gemm<64,1>,  cudaFuncAttributeMaxDynamicSharedMemorySize, smem_bytes(64,1));
  cudaFuncSetAttribute(k_gemm<128,2>, cudaFuncAttributeMaxDynamicSharedMemorySize, smem_bytes(128,2));
  cudaFuncSetAttribute(k_gemm<128,3>, cudaFuncAttributeMaxDynamicSharedMemorySize, smem_bytes(128,3));
  cudaFuncSetAttribute(k_attn, cudaFuncAttributeMaxDynamicSharedMemorySize, ATT_SMEM);

  float *pxc, *pqkv, *po, *pffa, *pxcat, *pxb, *paf, *pff, *paa, *pfa, *pwqg;
  cudaGetSymbolAddress((void**)&pxc,   g_xc);
  cudaGetSymbolAddress((void**)&pqkv,  g_qkv);
  cudaGetSymbolAddress((void**)&po,    g_o);
  cudaGetSymbolAddress((void**)&pffa,  g_ffa);
  cudaGetSymbolAddress((void**)&pxcat, g_xcat);
  cudaGetSymbolAddress((void**)&pxb,   g_xb);
  cudaGetSymbolAddress((void**)&paf,   g_attn_film);
  cudaGetSymbolAddress((void**)&pff,   g_ff_film);
  cudaGetSymbolAddress((void**)&paa,   g_attn_adaz);
  cudaGetSymbolAddress((void**)&pfa,   g_ff_adaz);
  cudaGetSymbolAddress((void**)&pwqg,  g_wqg);

  const size_t XS = (size_t)cRows * cD;
  const float* XB[4] = {in_x, pxb, pxb + XS, pxb + 2 * XS};
  float* XBw[4] = {nullptr, pxb, pxb + XS, pxb + 2 * XS};
  int cur = 0;

  k_buildw<<<(cL * cD * cQS + 255) / 256, 256>>>(qkvw, gw);
  k_cond<<<dim3(cDc / 256, cB), 256>>>(times, fw, tw, tb);
  k_proj<<<dim3(96, cL), 256>>>(afw, afb, ffw, ffb, aaw, aab, faw, fab);
  k_sincos<<<(cN * 32) / 256, 256>>>(rf);

  for (int l = 0; l < cL; l++) {
    if (l >= 3) {
      k_concat<<<(cRows * 2 * cD) / 256, 256>>>(XB[cur], XB[5 - l]);
      k_gemm<64,0><<<dim3(16, 16), 256, smem_bytes(64,0)>>>(
          pxcat, skw + (size_t)(l - 3) * 2048 * 1024, nullptr, XBw[3],
          nullptr, nullptr, cRows, 1024, 2048, 2048, 0);
      cur = 3;
    }
    // attention block (qkv + rope + v-mix + gates fused in one GEMM)
    k_lnfilm<<<cRows, 256>>>(paf + (size_t)l * cB * 2 * cD, XB[cur]);
    k_gemm<128,2><<<dim3((cQS + 127) / 128, 16), 128, smem_bytes(128,2)>>>(
        pxc, pwqg + (size_t)l * cD * cQS, nullptr, pqkv,
        nullptr, nullptr, cRows, cQS, 1024, 1024, l == 0 ? 1 : 0);
    k_attn<<<dim3(24, 32), 128, ATT_SMEM>>>();
    k_comb<<<dim3(8, 32), 256>>>();
    int nxt = (l < 3) ? l + 1 : 3;
    k_gemm<64,1><<<dim3(16, 16), 256, smem_bytes(64,1)>>>(
        po, ow + (size_t)l * 1024 * 1024, nullptr, XBw[nxt],
        XB[cur], paa + (size_t)l * cB * cD, cRows, 1024, 1024, 1024, 0);
    cur = nxt;
    // feed-forward block (ff1 + GLU fused)
    k_lnfilm<<<cRows, 256>>>(pff + (size_t)l * cB * 2 * cD, XB[cur]);
    k_gemm<128,3><<<dim3((cDff + 127) / 128, cRows / 64), 128, smem_bytes(128,3)>>>(
        pxc, w1 + (size_t)l * 1024 * (2 * cDff), b1 + (size_t)l * (2 * cDff), pffa,
        nullptr, nullptr, cRows, cDff, 1024, 1024, 0);
    k_gemm<64,1><<<dim3(16, 16), 256, smem_bytes(64,1)>>>(
        pffa, w2 + (size_t)l * cDff * 1024, b2 + (size_t)l * 1024, XBw[cur],
        XB[cur], pfa + (size_t)l * cB * cD, cRows, 1024, cDff, cDffP, 0);
  }
  k_final<<<cRows, 256>>>(gamma, XB[3], out);
}

// round 13
// speedup vs baseline: 3.8969x; 1.0136x over previous
#include <cuda_runtime.h>
#include <math.h>

// ---------------- problem constants ----------------
constexpr int cB   = 2;
constexpr int cN   = 1024;
constexpr int cD   = 1024;
constexpr int cL   = 6;
constexpr int cH   = 16;
constexpr int cDff = 2730;
constexpr int cDffP = 2732;    // padded row stride for ffa
constexpr int cDc  = 4096;
constexpr int cRows = cB * cN; // 2048
constexpr int cQS  = 3088;     // qkv row stride (3072 qkv + 16 gates)

// ---------------- device scratch ----------------
__device__ float g_cond[cB * cDc];
__device__ __align__(16) float g_attn_film[cL * cB * 2 * cD];
__device__ __align__(16) float g_ff_film[cL * cB * 2 * cD];
__device__ __align__(16) float g_attn_adaz[cL * cB * cD];
__device__ __align__(16) float g_ff_adaz[cL * cB * cD];
__device__ __align__(16) float g_xc[cRows * cD];
__device__ __align__(16) float g_qkv[cRows * cQS];
__device__ __align__(16) float g_vr[cRows * cD];
__device__ __align__(16) float g_o[cRows * cD];
__device__ __align__(16) float g_ffa[cRows * cDffP + 64];
__device__ __align__(16) float g_xb[3][cRows * cD];
__device__ __align__(16) float g_gates[cRows * cH];
__device__ float2 g_cs[cN * 32];
__device__ __align__(16) float g_wqg[cL * cD * cQS];   // qkv || gates combined weight
// attention split-K partials
__device__ __align__(16) float g_po[2][32][8][64][64];
__device__ float g_pl[2][32][8][64];

// attention job table (LPT order): qt, kt0, kt1, half(-1=full)
__constant__ signed char c_jq[24] = {15,15,14, 7,14,13,13,12, 6,12,11,11,10, 5,10, 9, 9, 8, 4, 8, 3, 2, 1, 0};
__constant__ signed char c_j0[24] = { 0, 8, 7, 0, 0, 0, 7, 6, 0, 0, 0, 6, 5, 0, 0, 0, 5, 4, 0, 0, 0, 0, 0, 0};
__constant__ signed char c_j1[24] = { 8,16,15, 8, 7, 7,14,13, 7, 6, 6,12,11, 6, 5, 5,10, 9, 5, 4, 4, 3, 2, 1};
__constant__ signed char c_jh[24] = { 0, 1, 1,-1, 0, 0, 1, 1,-1, 0, 0, 1, 1,-1, 0, 0, 1, 1,-1, 0,-1,-1,-1,-1};

__device__ __forceinline__ float f2tf_f(float x) {
  unsigned u;
  asm("cvt.rna.tf32.f32 %0, %1;" : "=r"(u) : "f"(x));
  return __uint_as_float(u);
}
__device__ __forceinline__ unsigned f2tf_u(float x) {
  unsigned u;
  asm("cvt.rna.tf32.f32 %0, %1;" : "=r"(u) : "f"(x));
  return u;
}

__global__ void k_sincos(const float* __restrict__ rf) {
  int i = blockIdx.x * 256 + threadIdx.x;
  if (i >= cN * 32) return;
  int n = i >> 5, p = i & 31;
  float f = rf[n * 64 + 2 * p];
  float s, c;
  sincosf(f, &s, &c);
  g_cs[i] = make_float2(c, s);
}

// build combined qkv||gates weight: [L][D][3088]
__global__ void k_buildw(const float* __restrict__ qkvw, const float* __restrict__ gw) {
  int i = blockIdx.x * 256 + threadIdx.x;
  if (i >= cL * cD * cQS) return;
  int c = i % cQS;
  int rowk = i / cQS;          // l*cD + k
  g_wqg[i] = (c < 3072) ? qkvw[(size_t)rowk * 3072 + c] : gw[rowk * 16 + (c - 3072)];
}

// ---------------- cond = silu(fourier @ tcond_w + b) ----------------
__global__ void k_cond(const float* __restrict__ times, const float* __restrict__ fw,
                       const float* __restrict__ tw, const float* __restrict__ tb) {
  __shared__ float fs[1025];
  int b = blockIdx.y;
  float t = times[b];
  for (int i = threadIdx.x; i < 1025; i += 256) {
    if (i == 0)        fs[0] = t;
    else if (i <= 512) fs[i] = sinf(6.283185307179586f * t * fw[i - 1]);
    else               fs[i] = cosf(6.283185307179586f * t * fw[i - 513]);
  }
  __syncthreads();
  int j = blockIdx.x * 256 + threadIdx.x;
  float acc = tb[j];
  for (int k = 0; k < 1025; k++) acc += fs[k] * tw[k * cDc + j];
  g_cond[b * cDc + j] = acc / (1.f + expf(-acc));
}

// ---------------- all cond projections (4-way K split, 64 cols/CTA) ----------------
__global__ void k_proj(const float* __restrict__ afw, const float* __restrict__ afb,
                       const float* __restrict__ ffw, const float* __restrict__ ffb,
                       const float* __restrict__ aaw, const float* __restrict__ aab,
                       const float* __restrict__ faw, const float* __restrict__ fab) {
  __shared__ float cs0[cDc], cs1[cDc];
  __shared__ float red0[4][64], red1[4][64];
  int l = blockIdx.y;
  int tid = threadIdx.x;
  for (int i = tid; i < cDc; i += 256) {
    cs0[i] = g_cond[i];
    cs1[i] = g_cond[cDc + i];
  }
  __syncthreads();
  int warp = tid >> 5, lane = tid & 31;
  int q = warp >> 1;                       // k-quarter 0..3
  int cl = (warp & 1) * 32 + lane;         // 0..63
  int o = blockIdx.x * 64 + cl;            // 0..6143
  const float* W; int cols; int c;
  if (o < 2048)      { c = o;        cols = 2048; W = afw + (size_t)l*cDc*2048; }
  else if (o < 4096) { c = o - 2048; cols = 2048; W = ffw + (size_t)l*cDc*2048; }
  else if (o < 5120) { c = o - 4096; cols = 1024; W = aaw + (size_t)l*cDc*1024; }
  else               { c = o - 5120; cols = 1024; W = faw + (size_t)l*cDc*1024; }
  int k0 = q * 1024;
  float acc0 = 0.f, acc1 = 0.f;
  #pragma unroll 8
  for (int k = k0; k < k0 + 1024; k++) {
    float w = W[(size_t)k * cols + c];
    acc0 += cs0[k] * w;
    acc1 += cs1[k] * w;
  }
  red0[q][cl] = acc0;
  red1[q][cl] = acc1;
  __syncthreads();
  if (tid < 64) {
    int cl2 = tid;
    int o2 = blockIdx.x * 64 + cl2;
    const float* bias; float* out; int cols2; int c2; bool sig = false;
    if (o2 < 2048)      { c2 = o2;        cols2 = 2048; bias = afb + l*2048; out = g_attn_film + (size_t)l*cB*2048; }
    else if (o2 < 4096) { c2 = o2 - 2048; cols2 = 2048; bias = ffb + l*2048; out = g_ff_film   + (size_t)l*cB*2048; }
    else if (o2 < 5120) { c2 = o2 - 4096; cols2 = 1024; bias = aab + l*1024; out = g_attn_adaz + (size_t)l*cB*1024; sig = true; }
    else                { c2 = o2 - 5120; cols2 = 1024; bias = fab + l*1024; out = g_ff_adaz   + (size_t)l*cB*1024; sig = true; }
    float a0 = bias[c2] + red0[0][cl2] + red0[1][cl2] + red0[2][cl2] + red0[3][cl2];
    float a1 = bias[c2] + red1[0][cl2] + red1[1][cl2] + red1[2][cl2] + red1[3][cl2];
    if (sig) { a0 = 1.f / (1.f + expf(-a0)); a1 = 1.f / (1.f + expf(-a1)); }
    out[c2] = a0;
    out[cols2 + c2] = a1;
  }
}

// ---------------- LN + FiLM: warp-per-row, no block barriers ----------------
__global__ __launch_bounds__(256) void k_lnfilm(const float* __restrict__ film,
                                                const float* __restrict__ src) {
  int warp = threadIdx.x >> 5, lane = threadIdx.x & 31;
  int row = blockIdx.x * 8 + warp;
  int b = row >> 10;
  const float4* srow = (const float4*)(src + (size_t)row * cD);
  float4 v[8];
  float s = 0.f, s2 = 0.f;
  #pragma unroll
  for (int i = 0; i < 8; i++) {
    v[i] = srow[lane + i * 32];
    s  += v[i].x + v[i].y + v[i].z + v[i].w;
    s2 += v[i].x*v[i].x + v[i].y*v[i].y + v[i].z*v[i].z + v[i].w*v[i].w;
  }
  #pragma unroll
  for (int off = 16; off > 0; off >>= 1) {
    s  += __shfl_xor_sync(0xffffffffu, s,  off);
    s2 += __shfl_xor_sync(0xffffffffu, s2, off);
  }
  float mu = s * (1.f / cD);
  float rs = rsqrtf(s2 * (1.f / cD) - mu * mu + 1e-5f);
  const float4* fgg = (const float4*)(film + b * 2 * cD);
  const float4* fgb = (const float4*)(film + b * 2 * cD + cD);
  float4* dst = (float4*)(g_xc + (size_t)row * cD);
  #pragma unroll
  for (int i = 0; i < 8; i++) {
    float4 gg = fgg[lane + i * 32];
    float4 bb = fgb[lane + i * 32];
    float4 o;
    o.x = f2tf_f((v[i].x - mu) * rs * (gg.x + 1.f) + bb.x);
    o.y = f2tf_f((v[i].y - mu) * rs * (gg.y + 1.f) + bb.y);
    o.z = f2tf_f((v[i].z - mu) * rs * (gg.z + 1.f) + bb.z);
    o.w = f2tf_f((v[i].w - mu) * rs * (gg.w + 1.f) + bb.w);
    dst[lane + i * 32] = o;
  }
}

// ---------------- tf32 GEMM: cp.async 3-stage + ldmatrix ----------------
// MODE 0: C = A@W (+bias);      MODE 1: C = resid + (A@W+bias)*adaz  [256 thr]
// MODE 2: qkv+gates epilogue;   MODE 3: ff1+GLU fused                [128 thr]
// MODE 4: skip GEMM, A = [x | skip] two-source concat                [256 thr]
__device__ __forceinline__ void mma_tf32(float (&c)[4], const unsigned (&a)[4],
                                         const unsigned (&b)[2]) {
  asm volatile(
      "mma.sync.aligned.m16n8k8.row.col.f32.tf32.tf32.f32 "
      "{%0,%1,%2,%3}, {%4,%5,%6,%7}, {%8,%9}, {%0,%1,%2,%3};\n"
      : "+f"(c[0]), "+f"(c[1]), "+f"(c[2]), "+f"(c[3])
      : "r"(a[0]), "r"(a[1]), "r"(a[2]), "r"(a[3]), "r"(b[0]), "r"(b[1]));
}
__device__ __forceinline__ void ldsm_x4(unsigned (&r)[4], unsigned saddr) {
  asm volatile("ldmatrix.sync.aligned.m8n8.x4.shared.b16 {%0,%1,%2,%3}, [%4];"
               : "=r"(r[0]), "=r"(r[1]), "=r"(r[2]), "=r"(r[3]) : "r"(saddr));
}
__device__ __forceinline__ void cpa16(void* smem, const void* gmem, bool valid) {
  unsigned sa = (unsigned)__cvta_generic_to_shared(smem);
  int sz = valid ? 16 : 0;
  asm volatile("cp.async.cg.shared.global [%0], [%1], 16, %2;\n"
               :: "r"(sa), "l"(gmem), "r"(sz) : "memory");
}
__device__ __forceinline__ void cpa8(void* smem, const void* gmem, bool valid) {
  unsigned sa = (unsigned)__cvta_generic_to_shared(smem);
  int sz = valid ? 8 : 0;
  asm volatile("cp.async.ca.shared.global [%0], [%1], 8, %2;\n"
               :: "r"(sa), "l"(gmem), "r"(sz) : "memory");
}
__device__ __forceinline__ float gelu_e(float g) {
  return 0.5f * g * (1.f + erff(g * 0.7071067811865476f));
}

constexpr int GA_STRIDE = 20;
constexpr int smem_bytes(int BN, int MODE) {
  int bm = (MODE == 3) ? 64 : 128;
  int nb = (MODE == 3) ? 2 : 1;
  int gbs = (BN == 128) ? 136 : 72;
  return 3 * (bm * GA_STRIDE + nb * 16 * gbs) * 4;
}

template <int BN, int MODE>
__global__ __launch_bounds__(((MODE == 2 || MODE == 3) ? 128 : 256), 2) void k_gemm(
    const float* __restrict__ A, const float* __restrict__ W,
    const float* __restrict__ bias, float* __restrict__ C,
    const float* __restrict__ resid, const float* __restrict__ adaz,
    int M, int N, int K, int lda, int l0) {
  constexpr int TH  = (MODE == 2 || MODE == 3) ? 128 : 256;
  constexpr int BM  = (MODE == 3) ? 64 : 128;
  constexpr int NWN = TH / 64;                    // warps along N
  constexpr int MI  = BM / 2 / 16;                // 2 warp-rows always
  constexpr int NJ  = BN / NWN / 8;
  constexpr int GBS = (BN == 128) ? 136 : 72;
  constexpr int GB_STAGE = 16 * GBS;
  constexpr int NB  = (MODE == 3) ? 2 : 1;
  constexpr int GA_ST = BM * GA_STRIDE;
  extern __shared__ unsigned dsm[];
  unsigned sa_base = (unsigned)__cvta_generic_to_shared(dsm);
  int tid = threadIdx.x;
  int warp = tid >> 5, lane = tid & 31;
  int wm = warp / NWN, wn = warp % NWN;
  int g = lane >> 2, t = lane & 3;
  int lrow = lane & 15, lcol = (lane >> 4) << 2;
  int rb = blockIdx.y * BM, cb = blockIdx.x * BN;
  float acc[NB][MI][NJ][4] = {};
  int nk = (K + 15) / 16;

  auto load_stage = [&](int buf, int k0) {
    unsigned* sA = dsm + buf * GA_ST;
    unsigned* sB = dsm + 3 * GA_ST + buf * (NB * GB_STAGE);
    #pragma unroll
    for (int it = 0; it < (BM * 4) / TH; it++) {
      int idx = tid + it * TH;
      int m = idx >> 2, kg = idx & 3;
      int gk = k0 + kg * 4;
      const float* srcp;
      if constexpr (MODE == 4) {
        srcp = (gk < 1024) ? A + (size_t)(rb + m) * 1024 + gk
                           : resid + (size_t)(rb + m) * 1024 + (gk - 1024);
      } else {
        srcp = A + (size_t)(rb + m) * lda + gk;
      }
      cpa16(&sA[m * GA_STRIDE + kg * 4], srcp, true);
    }
    #pragma unroll
    for (int it = 0; it < (BN * 4) / TH; it++) {
      int idx = tid + it * TH;
      int kk = idx / (BN / 4), n4 = idx % (BN / 4);
      int gk = k0 + kk, gn = cb + n4 * 4;
      bool ok = (gk < K) && (gn < N);
      if constexpr (MODE == 3) {
        const float* sa_ = W + (size_t)gk * 5460 + gn;
        cpa16(&sB[kk * GBS + n4 * 4], sa_, ok);
        const float* sg_ = W + (size_t)gk * 5460 + 2730 + gn;
        cpa8(&sB[GB_STAGE + kk * GBS + n4 * 4], sg_, ok);
        cpa8(&sB[GB_STAGE + kk * GBS + n4 * 4 + 2], sg_ + 2, ok && (gn + 2 < N));
      } else {
        cpa16(&sB[kk * GBS + n4 * 4], W + (size_t)gk * N + gn, ok);
      }
    }
    asm volatile("cp.async.commit_group;\n" ::: "memory");
  };

  load_stage(0, 0);
  if (nk > 1) load_stage(1, 16);
  for (int it = 0; it < nk; it++) {
    if (it + 2 <= nk) {
      asm volatile("cp.async.wait_group 1;\n" ::: "memory");
    } else {
      asm volatile("cp.async.wait_group 0;\n" ::: "memory");
    }
    __syncthreads();
    if (it + 2 < nk) load_stage((it + 2) % 3, (it + 2) * 16);
    int buf = it % 3;
    unsigned* sB = dsm + 3 * GA_ST + buf * (NB * GB_STAGE);
    unsigned abase = sa_base + (unsigned)((buf * GA_ST + (wm * MI * 16 + lrow) * GA_STRIDE + lcol) * 4);
    #pragma unroll
    for (int ks = 0; ks < 2; ks++) {
      int kb = ks * 8;
      unsigned a[MI][4];
      #pragma unroll
      for (int i = 0; i < MI; i++)
        ldsm_x4(a[i], abase + (unsigned)((i * 16 * GA_STRIDE + kb) * 4));
      unsigned b[NB][NJ][2];
      #pragma unroll
      for (int nb = 0; nb < NB; nb++)
        #pragma unroll
        for (int j = 0; j < NJ; j++) {
          int nc = wn * (BN / NWN) + j * 8;
          b[nb][j][0] = sB[nb * GB_STAGE + (kb + t) * GBS + nc + g];
          b[nb][j][1] = sB[nb * GB_STAGE + (kb + 4 + t) * GBS + nc + g];
        }
      #pragma unroll
      for (int nb = 0; nb < NB; nb++)
        #pragma unroll
        for (int i = 0; i < MI; i++)
          #pragma unroll
          for (int j = 0; j < NJ; j++)
            mma_tf32(acc[nb][i][j], a[i], b[nb][j]);
    }
  }

  #pragma unroll
  for (int i = 0; i < MI; i++) {
    int r0 = rb + wm * MI * 16 + i * 16 + g;
    int bidx = r0 >> 10;
    #pragma unroll
    for (int j = 0; j < NJ; j++) {
      int c0 = cb + wn * (BN / NWN) + j * 8 + 2 * t;
      if (c0 >= N) continue;
      float v00 = acc[0][i][j][0], v01 = acc[0][i][j][1];
      float v10 = acc[0][i][j][2], v11 = acc[0][i][j][3];
      if constexpr (MODE == 3) {
        float ba0 = bias[c0], ba1 = bias[c0 + 1];
        float bg0 = bias[2730 + c0], bg1 = bias[2730 + c0 + 1];
        float g00 = acc[1][i][j][0] + bg0, g01 = acc[1][i][j][1] + bg1;
        float g10 = acc[1][i][j][2] + bg0, g11 = acc[1][i][j][3] + bg1;
        float2 w0 = {f2tf_f(gelu_e(g00) * (v00 + ba0)), f2tf_f(gelu_e(g01) * (v01 + ba1))};
        float2 w1 = {f2tf_f(gelu_e(g10) * (v10 + ba0)), f2tf_f(gelu_e(g11) * (v11 + ba1))};
        *(float2*)&C[(size_t)r0 * cDffP + c0]       = w0;
        *(float2*)&C[(size_t)(r0 + 8) * cDffP + c0] = w1;
        continue;
      }
      if constexpr (MODE == 0 || MODE == 1 || MODE == 4) {
        if constexpr (MODE != 4) {
          float b0 = bias ? bias[c0] : 0.f;
          float b1 = bias ? bias[c0 + 1] : 0.f;
          v00 += b0; v01 += b1; v10 += b0; v11 += b1;
        }
        if constexpr (MODE == 1) {
          const float* az = adaz + bidx * N;
          float a0 = az[c0], a1 = az[c0 + 1];
          v00 = resid[(size_t)r0 * N + c0]       + v00 * a0;
          v01 = resid[(size_t)r0 * N + c0 + 1]   + v01 * a1;
          v10 = resid[(size_t)(r0+8) * N + c0]   + v10 * a0;
          v11 = resid[(size_t)(r0+8) * N + c0+1] + v11 * a1;
        }
      } else if constexpr (MODE == 2) {
        if (c0 >= 3072) {   // gates columns
          int cg = c0 - 3072;
          float s00 = 1.f / (1.f + expf(-v00)), s01 = 1.f / (1.f + expf(-v01));
          float s10 = 1.f / (1.f + expf(-v10)), s11 = 1.f / (1.f + expf(-v11));
          *(float2*)&g_gates[r0 * cH + cg]       = make_float2(s00, s01);
          *(float2*)&g_gates[(r0 + 8) * cH + cg] = make_float2(s10, s11);
          continue;
        }
        if (c0 < 2048) {
          int p = (c0 & 63) >> 1;
          float2 csa = g_cs[(r0 & 1023) * 32 + p];
          float2 csb = g_cs[((r0 + 8) & 1023) * 32 + p];
          float o00 = v00 * csa.x - v01 * csa.y;
          float o01 = v01 * csa.x + v00 * csa.y;
          float o10 = v10 * csb.x - v11 * csb.y;
          float o11 = v11 * csb.x + v10 * csb.y;
          v00 = o00; v01 = o01; v10 = o10; v11 = o11;
        } else {
          int cv = c0 - 2048;
          if (l0) {
            *(float2*)&g_vr[(size_t)r0 * 1024 + cv]       = make_float2(v00, v01);
            *(float2*)&g_vr[(size_t)(r0 + 8) * 1024 + cv] = make_float2(v10, v11);
          } else {
            float2 w0 = *(const float2*)&g_vr[(size_t)r0 * 1024 + cv];
            float2 w1 = *(const float2*)&g_vr[(size_t)(r0 + 8) * 1024 + cv];
            v00 = 0.5f * (v00 + w0.x); v01 = 0.5f * (v01 + w0.y);
            v10 = 0.5f * (v10 + w1.x); v11 = 0.5f * (v11 + w1.y);
          }
        }
      }
      *(float2*)&C[(size_t)r0 * N + c0]       = make_float2(v00, v01);
      *(float2*)&C[(size_t)(r0 + 8) * N + c0] = make_float2(v10, v11);
    }
  }
}

// ---------------- tensor-core flash attention (split-K, 2 syncs/iter) ----------------
__device__ __forceinline__ float softcap_exp(float s) {
  float z = s * 0.02f;
  float z2 = z * z;
  float num = s * (15.f + z2);
  float den = 15.f + 6.f * z2;
  return __expf(__fdividef(num, den));
}

constexpr int ATT_SMEM = 3 * 64 * 68 * 4;   // KP, Vs, Ps

__global__ __launch_bounds__(128) void k_attn() {
  extern __shared__ unsigned dsm[];
  unsigned (*KP)[68] = (unsigned(*)[68])dsm;
  unsigned (*Vs)[68] = (unsigned(*)[68])(dsm + 64 * 68);
  unsigned (*Ps)[68] = (unsigned(*)[68])(dsm + 2 * 64 * 68);
  int job = blockIdx.x;
  int qt = c_jq[job], kt0 = c_j0[job], kt1 = c_j1[job], half = c_jh[job];
  int bh = blockIdx.y;
  int b = bh >> 4, h = bh & 15;
  int q0 = qt * 64;
  int tid = threadIdx.x, warp = tid >> 5, lane = tid & 31;
  int g = lane >> 2, t = lane & 3;
  int mr = warp * 16;

  // stage Q via Ps
  for (int idx = tid; idx < 64 * 16; idx += 128) {
    int r = idx >> 4, d4 = (idx & 15) * 4;
    float4 q4 = *(const float4*)&g_qkv[(size_t)(b * cN + q0 + r) * cQS + h * 64 + d4];
    uint4 u = {f2tf_u(q4.x), f2tf_u(q4.y), f2tf_u(q4.z), f2tf_u(q4.w)};
    *(uint4*)&Ps[r][d4] = u;
  }
  __syncthreads();
  unsigned qa[8][4];
  #pragma unroll
  for (int kb = 0; kb < 8; kb++) {
    qa[kb][0] = Ps[mr + g][kb * 8 + t];
    qa[kb][1] = Ps[mr + 8 + g][kb * 8 + t];
    qa[kb][2] = Ps[mr + g][kb * 8 + 4 + t];
    qa[kb][3] = Ps[mr + 8 + g][kb * 8 + 4 + t];
  }

  float o[8][4] = {};
  float l0 = 0.f, l1 = 0.f;
  int row0 = q0 + mr + g, row1 = row0 + 8;

  for (int kt = kt0; kt < kt1; kt++) {
    int k0 = kt * 64;
    __syncthreads();
    for (int idx = tid; idx < 64 * 16; idx += 128) {
      int r = idx >> 4, d4 = (idx & 15) * 4;
      size_t base = (size_t)(b * cN + k0 + r) * cQS + h * 64 + d4;
      float4 kv = *(const float4*)&g_qkv[base + 1024];
      float4 vv = *(const float4*)&g_qkv[base + 2048];
      uint4 uk = {f2tf_u(kv.x), f2tf_u(kv.y), f2tf_u(kv.z), f2tf_u(kv.w)};
      uint4 uv = {f2tf_u(vv.x), f2tf_u(vv.y), f2tf_u(vv.z), f2tf_u(vv.w)};
      *(uint4*)&KP[r][d4] = uk;
      *(uint4*)&Vs[r][d4] = uv;
    }
    __syncthreads();

    float s[8][4] = {};
    #pragma unroll
    for (int kb = 0; kb < 8; kb++) {
      #pragma unroll
      for (int nf = 0; nf < 8; nf++) {
        unsigned bfr[2] = {KP[nf * 8 + g][kb * 8 + t], KP[nf * 8 + g][kb * 8 + 4 + t]};
        mma_tf32(s[nf], qa[kb], bfr);
      }
    }

    #pragma unroll
    for (int nf = 0; nf < 8; nf++) {
      int c0 = k0 + nf * 8 + 2 * t, c1 = c0 + 1;
      float p0 = (c0 <= row0) ? softcap_exp(s[nf][0] * 0.125f) : 0.f;
      float p1 = (c1 <= row0) ? softcap_exp(s[nf][1] * 0.125f) : 0.f;
      float p2 = (c0 <= row1) ? softcap_exp(s[nf][2] * 0.125f) : 0.f;
      float p3 = (c1 <= row1) ? softcap_exp(s[nf][3] * 0.125f) : 0.f;
      l0 += p0 + p1;
      l1 += p2 + p3;
      *(float2*)&Ps[mr + g][nf * 8 + 2 * t]     = make_float2(__uint_as_float(f2tf_u(p0)), __uint_as_float(f2tf_u(p1)));
      *(float2*)&Ps[mr + 8 + g][nf * 8 + 2 * t] = make_float2(__uint_as_float(f2tf_u(p2)), __uint_as_float(f2tf_u(p3)));
    }
    __syncwarp();

    #pragma unroll
    for (int kb = 0; kb < 8; kb++) {
      unsigned pa[4] = {Ps[mr + g][kb * 8 + t], Ps[mr + 8 + g][kb * 8 + t],
                        Ps[mr + g][kb * 8 + 4 + t], Ps[mr + 8 + g][kb * 8 + 4 + t]};
      #pragma unroll
      for (int nf = 0; nf < 8; nf++) {
        unsigned bfr[2] = {Vs[kb * 8 + t][nf * 8 + g], Vs[kb * 8 + 4 + t][nf * 8 + g]};
        mma_tf32(o[nf], pa, bfr);
      }
    }
  }

  l0 += __shfl_xor_sync(0xffffffffu, l0, 1);
  l0 += __shfl_xor_sync(0xffffffffu, l0, 2);
  l1 += __shfl_xor_sync(0xffffffffu, l1, 1);
  l1 += __shfl_xor_sync(0xffffffffu, l1, 2);

  if (half < 0) {
    float gate0 = g_gates[(b * cN + row0) * cH + h];
    float gate1 = g_gates[(b * cN + row1) * cH + h];
    float inv0 = gate0 / l0, inv1 = gate1 / l1;
    #pragma unroll
    for (int nf = 0; nf < 8; nf++) {
      int dcol = h * 64 + nf * 8 + 2 * t;
      g_o[(size_t)(b * cN + row0) * cD + dcol]     = f2tf_f(o[nf][0] * inv0);
      g_o[(size_t)(b * cN + row0) * cD + dcol + 1] = f2tf_f(o[nf][1] * inv0);
      g_o[(size_t)(b * cN + row1) * cD + dcol]     = f2tf_f(o[nf][2] * inv1);
      g_o[(size_t)(b * cN + row1) * cD + dcol + 1] = f2tf_f(o[nf][3] * inv1);
    }
  } else {
    int qh = qt - 8;
    int lr0 = mr + g, lr1 = lr0 + 8;
    #pragma unroll
    for (int nf = 0; nf < 8; nf++) {
      int col = nf * 8 + 2 * t;
      *(float2*)&g_po[half][bh][qh][lr0][col] = make_float2(o[nf][0], o[nf][1]);
      *(float2*)&g_po[half][bh][qh][lr1][col] = make_float2(o[nf][2], o[nf][3]);
    }
    if (t == 0) {
      g_pl[half][bh][qh][lr0] = l0;
      g_pl[half][bh][qh][lr1] = l1;
    }
  }
}

// combine split-K attention partials: grid (8, 32), 256 threads
__global__ void k_comb() {
  int qh = blockIdx.x, bh = blockIdx.y;
  int b = bh >> 4, h = bh & 15;
  int tid = threadIdx.x;
  int lr = tid >> 2, c4 = (tid & 3) * 16;
  int grow = (8 + qh) * 64 + lr;
  float l = g_pl[0][bh][qh][lr] + g_pl[1][bh][qh][lr];
  float gate = g_gates[(b * cN + grow) * cH + h];
  float sc = gate / l;
  #pragma unroll
  for (int c = 0; c < 16; c += 4) {
    float4 a = *(const float4*)&g_po[0][bh][qh][lr][c4 + c];
    float4 d = *(const float4*)&g_po[1][bh][qh][lr][c4 + c];
    float4 o;
    o.x = f2tf_f((a.x + d.x) * sc);
    o.y = f2tf_f((a.y + d.y) * sc);
    o.z = f2tf_f((a.z + d.z) * sc);
    o.w = f2tf_f((a.w + d.w) * sc);
    *(float4*)&g_o[(size_t)(b * cN + grow) * cD + h * 64 + c4 + c] = o;
  }
}

// ---------------- final norm ----------------
__global__ void k_final(const float* __restrict__ gamma, const float* __restrict__ src,
                        float* __restrict__ out) {
  int row = blockIdx.x;
  int tid = threadIdx.x;
  float4 v = ((const float4*)(src + (size_t)row * cD))[tid];
  float s2 = v.x*v.x + v.y*v.y + v.z*v.z + v.w*v.w;
  #pragma unroll
  for (int off = 16; off > 0; off >>= 1)
    s2 += __shfl_xor_sync(0xffffffffu, s2, off);
  __shared__ float ws2[8];
  __shared__ float sscale;
  if ((tid & 31) == 0) ws2[tid >> 5] = s2;
  __syncthreads();
  if (tid == 0) {
    float t2 = 0.f;
    for (int w = 0; w < 8; w++) t2 += ws2[w];
    sscale = 32.f / fmaxf(sqrtf(t2), 1e-12f);
  }
  __syncthreads();
  float sc = sscale;
  int d = tid * 4;
  float4 o;
  o.x = v.x * sc * (gamma[d + 0] + 1.f);
  o.y = v.y * sc * (gamma[d + 1] + 1.f);
  o.z = v.z * sc * (gamma[d + 2] + 1.f);
  o.w = v.w * sc * (gamma[d + 3] + 1.f);
  ((float4*)(out + (size_t)row * cD))[tid] = o;
}

// ---------------- host launcher ----------------
extern "C" void kernel_launch(void* const* d_in, const int* in_sizes, int n_in,
                              void* d_out, int out_size) {
  const float* in_x  = (const float*)d_in[0];
  const float* times = (const float*)d_in[1];
  const float* rf    = (const float*)d_in[2];
  const float* fw    = (const float*)d_in[3];
  const float* tw    = (const float*)d_in[4];
  const float* tb    = (const float*)d_in[5];
  const float* skw   = (const float*)d_in[6];
  const float* afw   = (const float*)d_in[7];
  const float* afb   = (const float*)d_in[8];
  const float* aaw   = (const float*)d_in[9];
  const float* aab   = (const float*)d_in[10];
  const float* qkvw  = (const float*)d_in[11];
  const float* gw    = (const float*)d_in[12];
  const float* ow    = (const float*)d_in[13];
  const float* ffw   = (const float*)d_in[14];
  const float* ffb   = (const float*)d_in[15];
  const float* faw   = (const float*)d_in[16];
  const float* fab   = (const float*)d_in[17];
  const float* w1    = (const float*)d_in[18];
  const float* b1    = (const float*)d_in[19];
  const float* w2    = (const float*)d_in[20];
  const float* b2    = (const float*)d_in[21];
  const float* gamma = (const float*)d_in[22];
  float* out = (float*)d_out;

  cudaFuncSetAttribute(k_gemm<64,1>,  cudaFuncAttributeMaxDynamicSharedMemorySize, smem_bytes(64,1));
  cudaFuncSetAttribute(k_gemm<64,4>,  cudaFuncAttributeMaxDynamicSharedMemorySize, smem_bytes(64,4));
  cudaFuncSetAttribute(k_gemm<128,2>, cudaFuncAttributeMaxDynamicSharedMemorySize, smem_bytes(128,2));
  cudaFuncSetAttribute(k_gemm<128,3>, cudaFuncAttributeMaxDynamicSharedMemorySize, smem_bytes(128,3));
  cudaFuncSetAttribute(k_attn, cudaFuncAttributeMaxDynamicSharedMemorySize, ATT_SMEM);

  float *pxc, *pqkv, *po, *pffa, *pxb, *paf, *pff, *paa, *pfa, *pwqg;
  cudaGetSymbolAddress((void**)&pxc,   g_xc);
  cudaGetSymbolAddress((void**)&pqkv,  g_qkv);
  cudaGetSymbolAddress((void**)&po,    g_o);
  cudaGetSymbolAddress((void**)&pffa,  g_ffa);
  cudaGetSymbolAddress((void**)&pxb,   g_xb);
  cudaGetSymbolAddress((void**)&paf,   g_attn_film);
  cudaGetSymbolAddress((void**)&pff,   g_ff_film);
  cudaGetSymbolAddress((void**)&paa,   g_attn_adaz);
  cudaGetSymbolAddress((void**)&pfa,   g_ff_adaz);
  cudaGetSymbolAddress((void**)&pwqg,  g_wqg);

  const size_t XS = (size_t)cRows * cD;
  const float* XB[4] = {in_x, pxb, pxb + XS, pxb + 2 * XS};
  float* XBw[4] = {nullptr, pxb, pxb + XS, pxb + 2 * XS};
  int cur = 0;

  k_buildw<<<(cL * cD * cQS + 255) / 256, 256>>>(qkvw, gw);
  k_cond<<<dim3(cDc / 256, cB), 256>>>(times, fw, tw, tb);
  k_proj<<<dim3(96, cL), 256>>>(afw, afb, ffw, ffb, aaw, aab, faw, fab);
  k_sincos<<<(cN * 32) / 256, 256>>>(rf);

  for (int l = 0; l < cL; l++) {
    if (l >= 3) {
      // skip GEMM with fused concat: A = [x | skip]
      k_gemm<64,4><<<dim3(16, 16), 256, smem_bytes(64,4)>>>(
          XB[cur], skw + (size_t)(l - 3) * 2048 * 1024, nullptr, XBw[3],
          XB[5 - l], nullptr, cRows, 1024, 2048, 1024, 0);
      cur = 3;
    }
    // attention block (qkv + rope + v-mix + gates fused in one GEMM)
    k_lnfilm<<<cRows / 8, 256>>>(paf + (size_t)l * cB * 2 * cD, XB[cur]);
    k_gemm<128,2><<<dim3((cQS + 127) / 128, 16), 128, smem_bytes(128,2)>>>(
        pxc, pwqg + (size_t)l * cD * cQS, nullptr, pqkv,
        nullptr, nullptr, cRows, cQS, 1024, 1024, l == 0 ? 1 : 0);
    k_attn<<<dim3(24, 32), 128, ATT_SMEM>>>();
    k_comb<<<dim3(8, 32), 256>>>();
    int nxt = (l < 3) ? l + 1 : 3;
    k_gemm<64,1><<<dim3(16, 16), 256, smem_bytes(64,1)>>>(
        po, ow + (size_t)l * 1024 * 1024, nullptr, XBw[nxt],
        XB[cur], paa + (size_t)l * cB * cD, cRows, 1024, 1024, 1024, 0);
    cur = nxt;
    // feed-forward block (ff1 + GLU fused)
    k_lnfilm<<<cRows / 8, 256>>>(pff + (size_t)l * cB * 2 * cD, XB[cur]);
    k_gemm<128,3><<<dim3((cDff + 127) / 128, cRows / 64), 128, smem_bytes(128,3)>>>(
        pxc, w1 + (size_t)l * 1024 * (2 * cDff), b1 + (size_t)l * (2 * cDff), pffa,
        nullptr, nullptr, cRows, cDff, 1024, 1024, 0);
    k_gemm<64,1><<<dim3(16, 16), 256, smem_bytes(64,1)>>>(
        pffa, w2 + (size_t)l * cDff * 1024, b2 + (size_t)l * 1024, XBw[cur],
        XB[cur], pfa + (size_t)l * cB * cD, cRows, 1024, cDff, cDffP, 0);
  }
  k_final<<<cRows, 256>>>(gamma, XB[3], out);
}